// round 6
// baseline (speedup 1.0000x reference)
#include <cuda_runtime.h>
#include <cuda_bf16.h>
#include <math.h>
#include <stdint.h>

// Problem constants
#define BB 2
#define SS 2048
#define DD 2048
#define HH 16
#define HD 128
#define BS (BB * SS)        // 4096 tokens
#define NPAIR (HD / 2)      // 64 rope pairs per head
#define KBIG (3 * DD)       // 6144: bf16x3 split-K
#define ITERS (KBIG / 64)   // 96 K-chunks of 64
#define STG 4               // cp.async pipeline stages

// ---------------------------------------------------------------------------
// Scratch (device globals -- no allocation allowed in kernel_launch)
// ---------------------------------------------------------------------------
__device__ float g_q[BS * DD];
__device__ float g_k[BS * DD];
__device__ float g_v[BS * DD];
__device__ float g_ao[BS * DD];
__device__ float g_cos[SS * NPAIR];
__device__ float g_sin[SS * NPAIR];
__device__ __nv_bfloat16 g_abig[(size_t)BS * KBIG];  // [hi | lo | hi]
__device__ __nv_bfloat16 g_wbig[(size_t)DD * KBIG];  // [hi | hi | lo]

// ---------------------------------------------------------------------------
// Helpers
// ---------------------------------------------------------------------------
__device__ __forceinline__ uint32_t smem_u32(const void* p) {
    uint32_t a;
    asm("{ .reg .u64 t; cvta.to.shared.u64 t, %1; cvt.u32.u64 %0, t; }"
        : "=r"(a) : "l"(p));
    return a;
}
#define CP_ASYNC16(smem, gptr) \
    asm volatile("cp.async.cg.shared.global [%0], [%1], 16;" \
                 :: "r"((uint32_t)(smem)), "l"((const void*)(gptr)) : "memory")
#define CP_COMMIT() asm volatile("cp.async.commit_group;" ::: "memory")

// ---------------------------------------------------------------------------
// RoPE table (double precision generation)
// ---------------------------------------------------------------------------
__global__ void rope_table_kernel() {
    int idx = blockIdx.x * blockDim.x + threadIdx.x;
    if (idx >= SS * NPAIR) return;
    int s = idx / NPAIR;
    int i = idx - s * NPAIR;
    double freq = (double)s * exp(((double)(-2 * i) / (double)HD) * log(10000.0));
    g_cos[idx] = (float)cos(freq);
    g_sin[idx] = (float)sin(freq);
}

// RoPE in place on g_q and g_k
__global__ void rope_apply_kernel() {
    int idx = blockIdx.x * blockDim.x + threadIdx.x;
    if (idx >= BS * (DD / 2)) return;
    int t = idx >> 10;
    int p = idx & 1023;
    int i = p & (NPAIR - 1);
    int s = t & (SS - 1);
    float c  = g_cos[(s << 6) + i];
    float sn = g_sin[(s << 6) + i];
    size_t base = ((size_t)t << 11) + ((size_t)p << 1);
    float2 q2 = *reinterpret_cast<float2*>(&g_q[base]);
    float2 k2 = *reinterpret_cast<float2*>(&g_k[base]);
    float2 qo = make_float2(q2.x * c - q2.y * sn, q2.x * sn + q2.y * c);
    float2 ko = make_float2(k2.x * c - k2.y * sn, k2.x * sn + k2.y * c);
    *reinterpret_cast<float2*>(&g_q[base]) = qo;
    *reinterpret_cast<float2*>(&g_k[base]) = ko;
}

// ---------------------------------------------------------------------------
// bf16x3 split: src fp32 [rows, 2048] -> dst bf16 [rows, 6144]
// mode 0 (activation): [hi | lo | hi];  mode 1 (weight): [hi | hi | lo]
// ---------------------------------------------------------------------------
__global__ void split3_kernel(const float* __restrict__ src,
                              __nv_bfloat16* __restrict__ dst,
                              int n, int mode) {
    int idx = blockIdx.x * blockDim.x + threadIdx.x;
    if (idx >= n) return;
    int r = idx >> 11;
    int c = idx & 2047;
    float v = src[idx];
    __nv_bfloat16 hi = __float2bfloat16(v);
    __nv_bfloat16 lo = __float2bfloat16(v - __bfloat162float(hi));
    size_t base = (size_t)r * KBIG + c;
    if (mode == 0) {
        dst[base] = hi; dst[base + DD] = lo; dst[base + 2 * DD] = hi;
    } else {
        dst[base] = hi; dst[base + DD] = hi; dst[base + 2 * DD] = lo;
    }
}

// ---------------------------------------------------------------------------
// HMMA GEMM: C[4096,2048] = A[4096,6144] * B[2048,6144]^T  (bf16 in, fp32 out)
// 128x128 CTA tile, BK=64, 4-stage cp.async pipeline, SW128-swizzled smem,
// mma.sync.m16n8k16 bf16 with fp32 register accumulators.
// ---------------------------------------------------------------------------
#define TILE_STAGE_BYTES 32768          // A(16KB) + B(16KB) per stage
#define GEMM_SMEM_BYTES (STG * TILE_STAGE_BYTES)  // 131072

__device__ __forceinline__ void issue_stage(
    uint32_t sb, int s, int tid,
    const __nv_bfloat16* __restrict__ Ag,
    const __nv_bfloat16* __restrict__ Bg)
{
    if (s < ITERS) {
        const int k0 = s * 64;
        const int slot = s & (STG - 1);
        uint32_t abase = sb + slot * TILE_STAGE_BYTES;
        uint32_t bbase = abase + 16384;
#pragma unroll
        for (int i = 0; i < 4; i++) {
            int id = tid + 256 * i;          // 0..1023 chunks of 16B
            int row = id >> 3;               // 0..127
            int c = id & 7;                  // 16B chunk within 128B row
            uint32_t off = (uint32_t)(row * 128 + ((c ^ (row & 7)) << 4));
            CP_ASYNC16(abase + off, Ag + (size_t)row * KBIG + k0 + c * 8);
            CP_ASYNC16(bbase + off, Bg + (size_t)row * KBIG + k0 + c * 8);
        }
    }
    CP_COMMIT();
}

__global__ __launch_bounds__(256, 1)
void gemm_hmma(const __nv_bfloat16* __restrict__ A,
               const __nv_bfloat16* __restrict__ Bw,
               float* __restrict__ C)
{
    extern __shared__ char smraw[];
    uint32_t sb = smem_u32(smraw);
    const int tid  = threadIdx.x;
    const int lane = tid & 31;
    const int warp = tid >> 5;
    const int wm = warp & 1;        // m half (64 rows)
    const int wn = warp >> 1;       // n quarter (32 cols)
    const int m0 = blockIdx.y * 128;
    const int n0 = blockIdx.x * 128;
    const __nv_bfloat16* Ag = A  + (size_t)m0 * KBIG;
    const __nv_bfloat16* Bg = Bw + (size_t)n0 * KBIG;

    float acc[4][4][4];
#pragma unroll
    for (int a = 0; a < 4; a++)
#pragma unroll
        for (int b = 0; b < 4; b++)
#pragma unroll
            for (int c = 0; c < 4; c++) acc[a][b][c] = 0.f;

    issue_stage(sb, 0, tid, Ag, Bg);
    issue_stage(sb, 1, tid, Ag, Bg);
    issue_stage(sb, 2, tid, Ag, Bg);

    for (int s = 0; s < ITERS; s++) {
        asm volatile("cp.async.wait_group 2;" ::: "memory");
        __syncthreads();
        const int slot = s & (STG - 1);
        uint32_t abase = sb + slot * TILE_STAGE_BYTES;
        uint32_t bbase = abase + 16384;

#pragma unroll
        for (int ks = 0; ks < 4; ks++) {
            uint32_t af[4][4];
            uint32_t bf[4][2];
#pragma unroll
            for (int mt = 0; mt < 4; mt++) {
                int row = wm * 64 + mt * 16 + (lane & 15);
                int ch  = ks * 2 + (lane >> 4);
                uint32_t ad = abase + (uint32_t)(row * 128 +
                                  ((ch ^ (row & 7)) << 4));
                asm volatile(
                    "ldmatrix.sync.aligned.m8n8.x4.shared.b16 {%0,%1,%2,%3}, [%4];"
                    : "=r"(af[mt][0]), "=r"(af[mt][1]),
                      "=r"(af[mt][2]), "=r"(af[mt][3])
                    : "r"(ad));
            }
#pragma unroll
            for (int np = 0; np < 2; np++) {
                int row = wn * 32 + np * 16 + ((lane >> 4) << 3) + (lane & 7);
                int ch  = ks * 2 + ((lane >> 3) & 1);
                uint32_t bd = bbase + (uint32_t)(row * 128 +
                                  ((ch ^ (row & 7)) << 4));
                asm volatile(
                    "ldmatrix.sync.aligned.m8n8.x4.shared.b16 {%0,%1,%2,%3}, [%4];"
                    : "=r"(bf[2 * np][0]), "=r"(bf[2 * np][1]),
                      "=r"(bf[2 * np + 1][0]), "=r"(bf[2 * np + 1][1])
                    : "r"(bd));
            }
#pragma unroll
            for (int mt = 0; mt < 4; mt++)
#pragma unroll
                for (int nt = 0; nt < 4; nt++)
                    asm volatile(
                        "mma.sync.aligned.m16n8k16.row.col.f32.bf16.bf16.f32 "
                        "{%0,%1,%2,%3}, {%4,%5,%6,%7}, {%8,%9}, {%0,%1,%2,%3};"
                        : "+f"(acc[mt][nt][0]), "+f"(acc[mt][nt][1]),
                          "+f"(acc[mt][nt][2]), "+f"(acc[mt][nt][3])
                        : "r"(af[mt][0]), "r"(af[mt][1]),
                          "r"(af[mt][2]), "r"(af[mt][3]),
                          "r"(bf[nt][0]), "r"(bf[nt][1]));
        }
        // Safe: slot(s+3) == slot(s-1); all warps finished compute(s-1)
        // before this iteration's __syncthreads.
        issue_stage(sb, s + 3, tid, Ag, Bg);
    }

    // Epilogue: fragment layout d0,d1 -> (row, col..col+1), d2,d3 -> row+8
#pragma unroll
    for (int mt = 0; mt < 4; mt++) {
#pragma unroll
        for (int nt = 0; nt < 4; nt++) {
            int row = m0 + wm * 64 + mt * 16 + (lane >> 2);
            int col = n0 + wn * 32 + nt * 8 + (lane & 3) * 2;
            float2 v0 = make_float2(acc[mt][nt][0], acc[mt][nt][1]);
            float2 v1 = make_float2(acc[mt][nt][2], acc[mt][nt][3]);
            *reinterpret_cast<float2*>(&C[(size_t)row * DD + col]) = v0;
            *reinterpret_cast<float2*>(&C[(size_t)(row + 8) * DD + col]) = v1;
        }
    }
}

// ---------------------------------------------------------------------------
// Flash attention (fp32, unchanged from R1): one block per (q-tile 64, b*h)
// ---------------------------------------------------------------------------
#define FLASH_SMEM_FLOATS (2 * 128 * 65 + 64 * 65 + 3 * 64)
#define FLASH_SMEM_BYTES  (FLASH_SMEM_FLOATS * 4)

__global__ __launch_bounds__(256, 2) void flash_kernel() {
    extern __shared__ float smf[];
    float* Qt  = smf;
    float* KV  = smf + 128 * 65;
    float* Pt  = smf + 2 * 128 * 65;
    float* m_s  = Pt + 64 * 65;
    float* l_s  = m_s + 64;
    float* al_s = l_s + 64;

    const int tid = threadIdx.x;
    const int q0  = blockIdx.x * 64;
    const int bh  = blockIdx.y;
    const int b   = bh >> 4;
    const int h   = bh & 15;
    const size_t base_bh = (size_t)b * SS * DD + (size_t)h * HD;

#pragma unroll
    for (int rep = 0; rep < 32; rep++) {
        int lin = rep * 256 + tid;
        int r = lin >> 7;
        int d = lin & 127;
        Qt[d * 65 + r] = g_q[base_bh + (size_t)(q0 + r) * DD + d];
    }

    if (tid < 64) { m_s[tid] = -INFINITY; l_s[tid] = 0.f; }

    float oacc[8][4];
#pragma unroll
    for (int a = 0; a < 8; a++)
#pragma unroll
        for (int c = 0; c < 4; c++) oacc[a][c] = 0.f;

    const int ty = tid >> 4, tx = tid & 15;
    const int ry = tid >> 5, cx = tid & 31;

    for (int kv0 = 0; kv0 < SS; kv0 += 64) {
        __syncthreads();

#pragma unroll
        for (int rep = 0; rep < 32; rep++) {
            int lin = rep * 256 + tid;
            int j = lin >> 7;
            int d = lin & 127;
            KV[d * 65 + j] = g_k[base_bh + (size_t)(kv0 + j) * DD + d];
        }
        __syncthreads();

        float sacc[4][4];
#pragma unroll
        for (int a = 0; a < 4; a++)
#pragma unroll
            for (int c = 0; c < 4; c++) sacc[a][c] = 0.f;

#pragma unroll 4
        for (int d = 0; d < 128; d++) {
            float ar[4], br[4];
#pragma unroll
            for (int a = 0; a < 4; a++) ar[a] = Qt[d * 65 + 4 * ty + a];
#pragma unroll
            for (int c = 0; c < 4; c++) br[c] = KV[d * 65 + 4 * tx + c];
#pragma unroll
            for (int a = 0; a < 4; a++)
#pragma unroll
                for (int c = 0; c < 4; c++)
                    sacc[a][c] += ar[a] * br[c];
        }
#pragma unroll
        for (int c = 0; c < 4; c++)
#pragma unroll
            for (int a = 0; a < 4; a++)
                Pt[(4 * tx + c) * 65 + 4 * ty + a] =
                    sacc[a][c] * 0.08838834764831845f;
        __syncthreads();

#pragma unroll
        for (int rep = 0; rep < 8; rep++) {
            int lin4 = rep * 256 + tid;
            int j  = lin4 >> 5;
            int d4 = (lin4 & 31) << 2;
            *reinterpret_cast<float4*>(&KV[j * 128 + d4]) =
                *reinterpret_cast<const float4*>(
                    &g_v[base_bh + (size_t)(kv0 + j) * DD + d4]);
        }

        if (tid < 64) {
            const int r = tid;
            float mi = m_s[r];
            float mx = mi;
#pragma unroll 8
            for (int c = 0; c < 64; c++)
                mx = fmaxf(mx, Pt[c * 65 + r]);
            float alpha = __expf(mi - mx);
            float sum = 0.f;
#pragma unroll 8
            for (int c = 0; c < 64; c++) {
                float p = __expf(Pt[c * 65 + r] - mx);
                Pt[c * 65 + r] = p;
                sum += p;
            }
            m_s[r]  = mx;
            l_s[r]  = l_s[r] * alpha + sum;
            al_s[r] = alpha;
        }
        __syncthreads();

        float al[8];
#pragma unroll
        for (int a = 0; a < 8; a++) al[a] = al_s[ry * 8 + a];
#pragma unroll
        for (int a = 0; a < 8; a++)
#pragma unroll
            for (int c = 0; c < 4; c++) oacc[a][c] *= al[a];

#pragma unroll 2
        for (int j = 0; j < 64; j++) {
            float4 vv = *reinterpret_cast<float4*>(&KV[j * 128 + 4 * cx]);
#pragma unroll
            for (int a = 0; a < 8; a++) {
                float p = Pt[j * 65 + ry * 8 + a];
                oacc[a][0] += p * vv.x;
                oacc[a][1] += p * vv.y;
                oacc[a][2] += p * vv.z;
                oacc[a][3] += p * vv.w;
            }
        }
    }

#pragma unroll
    for (int a = 0; a < 8; a++) {
        float inv = 1.0f / l_s[ry * 8 + a];
        float4 o = make_float4(oacc[a][0] * inv, oacc[a][1] * inv,
                               oacc[a][2] * inv, oacc[a][3] * inv);
        *reinterpret_cast<float4*>(
            &g_ao[base_bh + (size_t)(q0 + ry * 8 + a) * DD + 4 * cx]) = o;
    }
}

// ---------------------------------------------------------------------------
// Launch
// ---------------------------------------------------------------------------
extern "C" void kernel_launch(void* const* d_in, const int* in_sizes, int n_in,
                              void* d_out, int out_size) {
    (void)in_sizes; (void)n_in; (void)out_size;
    const float* x  = (const float*)d_in[0];
    const float* wq = (const float*)d_in[1];
    const float* wk = (const float*)d_in[2];
    const float* wv = (const float*)d_in[3];
    const float* wo = (const float*)d_in[4];
    float* out = (float*)d_out;

    float *q, *k, *v, *ao;
    __nv_bfloat16 *abig, *wbig;
    cudaGetSymbolAddress((void**)&q,    g_q);
    cudaGetSymbolAddress((void**)&k,    g_k);
    cudaGetSymbolAddress((void**)&v,    g_v);
    cudaGetSymbolAddress((void**)&ao,   g_ao);
    cudaGetSymbolAddress((void**)&abig, g_abig);
    cudaGetSymbolAddress((void**)&wbig, g_wbig);

    cudaFuncSetAttribute(gemm_hmma,
                         cudaFuncAttributeMaxDynamicSharedMemorySize,
                         GEMM_SMEM_BYTES);
    cudaFuncSetAttribute(flash_kernel,
                         cudaFuncAttributeMaxDynamicSharedMemorySize,
                         FLASH_SMEM_BYTES);

    const int n_act = BS * DD;
    const int n_w   = DD * DD;
    dim3 ggrid(DD / 128, BS / 128);  // (16, 32)

    rope_table_kernel<<<(SS * NPAIR + 255) / 256, 256>>>();

    split3_kernel<<<(n_act + 255) / 256, 256>>>(x, abig, n_act, 0);

    split3_kernel<<<(n_w + 255) / 256, 256>>>(wq, wbig, n_w, 1);
    gemm_hmma<<<ggrid, 256, GEMM_SMEM_BYTES>>>(abig, wbig, q);
    split3_kernel<<<(n_w + 255) / 256, 256>>>(wk, wbig, n_w, 1);
    gemm_hmma<<<ggrid, 256, GEMM_SMEM_BYTES>>>(abig, wbig, k);
    split3_kernel<<<(n_w + 255) / 256, 256>>>(wv, wbig, n_w, 1);
    gemm_hmma<<<ggrid, 256, GEMM_SMEM_BYTES>>>(abig, wbig, v);

    rope_apply_kernel<<<(BS * (DD / 2) + 255) / 256, 256>>>();

    dim3 fgrid(SS / 64, BB * HH);
    flash_kernel<<<fgrid, 256, FLASH_SMEM_BYTES>>>();

    split3_kernel<<<(n_act + 255) / 256, 256>>>(ao, abig, n_act, 0);
    split3_kernel<<<(n_w + 255) / 256, 256>>>(wo, wbig, n_w, 1);
    gemm_hmma<<<ggrid, 256, GEMM_SMEM_BYTES>>>(abig, wbig, out);
}

// round 7
// speedup vs baseline: 1.5529x; 1.5529x over previous
#include <cuda_runtime.h>
#include <cuda_bf16.h>
#include <math.h>
#include <stdint.h>

// Problem constants
#define BB 2
#define SS 2048
#define DD 2048
#define HH 16
#define HD 128
#define BS (BB * SS)        // 4096 tokens
#define NPAIR (HD / 2)      // 64 rope pairs per head
#define KBIG (3 * DD)       // 6144: bf16x3 split-K
#define ITERS (KBIG / 64)   // 96 K-chunks of 64
#define STG 4               // cp.async pipeline stages
#define LOG2E 1.4426950408889634f
#define QK_SCALE 0.08838834764831845f

// ---------------------------------------------------------------------------
// Scratch (device globals -- no allocation allowed in kernel_launch)
// ---------------------------------------------------------------------------
__device__ float g_q[BS * DD];
__device__ float g_k[BS * DD];
__device__ float g_v[BS * DD];
__device__ float g_ao[BS * DD];
__device__ float g_cos[SS * NPAIR];
__device__ float g_sin[SS * NPAIR];
__device__ __nv_bfloat16 g_abig[(size_t)BS * KBIG];  // [hi | lo | hi]
__device__ __nv_bfloat16 g_wbig[(size_t)DD * KBIG];  // [hi | hi | lo]
// Attention split buffers, [bh][s][d] (q/k) and [bh][d][s] (v transposed)
__device__ __nv_bfloat16 g_qshi[(size_t)BS * DD];
__device__ __nv_bfloat16 g_qslo[(size_t)BS * DD];
__device__ __nv_bfloat16 g_kshi[(size_t)BS * DD];
__device__ __nv_bfloat16 g_kslo[(size_t)BS * DD];
__device__ __nv_bfloat16 g_vthi[(size_t)BS * DD];
__device__ __nv_bfloat16 g_vtlo[(size_t)BS * DD];

// ---------------------------------------------------------------------------
// Helpers
// ---------------------------------------------------------------------------
__device__ __forceinline__ uint32_t smem_u32(const void* p) {
    uint32_t a;
    asm("{ .reg .u64 t; cvta.to.shared.u64 t, %1; cvt.u32.u64 %0, t; }"
        : "=r"(a) : "l"(p));
    return a;
}
#define CP_ASYNC16(smem, gptr) \
    asm volatile("cp.async.cg.shared.global [%0], [%1], 16;" \
                 :: "r"((uint32_t)(smem)), "l"((const void*)(gptr)) : "memory")
#define CP_COMMIT() asm volatile("cp.async.commit_group;" ::: "memory")

#define LDSM_X4(r0, r1, r2, r3, addr) \
    asm volatile("ldmatrix.sync.aligned.m8n8.x4.shared.b16 {%0,%1,%2,%3}, [%4];" \
                 : "=r"(r0), "=r"(r1), "=r"(r2), "=r"(r3) : "r"(addr))

#define MMA16816(d, a, b0, b1) \
    asm volatile("mma.sync.aligned.m16n8k16.row.col.f32.bf16.bf16.f32 " \
                 "{%0,%1,%2,%3}, {%4,%5,%6,%7}, {%8,%9}, {%0,%1,%2,%3};" \
                 : "+f"((d)[0]), "+f"((d)[1]), "+f"((d)[2]), "+f"((d)[3]) \
                 : "r"((a)[0]), "r"((a)[1]), "r"((a)[2]), "r"((a)[3]),   \
                   "r"(b0), "r"(b1))

// Fast exp2 on FMA pipe: t <= 0, clamp at -126; |rel err| ~ 3e-6
__device__ __forceinline__ float exp2_fast(float t) {
    t = fmaxf(t, -126.0f);
    float r = t + 12582912.0f;                 // round-to-nearest int
    int e = __float_as_int(r) - 0x4B400000;
    float f = t - (r - 12582912.0f);           // f in [-0.5, 0.5]
    float p = 0.0013333558f;
    p = fmaf(p, f, 0.0096181291f);
    p = fmaf(p, f, 0.0555041087f);
    p = fmaf(p, f, 0.2402265070f);
    p = fmaf(p, f, 0.6931471806f);
    p = fmaf(p, f, 1.0f);
    return __int_as_float((e + 127) << 23) * p;
}

// ---------------------------------------------------------------------------
// RoPE table (double precision generation)
// ---------------------------------------------------------------------------
__global__ void rope_table_kernel() {
    int idx = blockIdx.x * blockDim.x + threadIdx.x;
    if (idx >= SS * NPAIR) return;
    int s = idx / NPAIR;
    int i = idx - s * NPAIR;
    double freq = (double)s * exp(((double)(-2 * i) / (double)HD) * log(10000.0));
    g_cos[idx] = (float)cos(freq);
    g_sin[idx] = (float)sin(freq);
}

// RoPE in place on g_q and g_k
__global__ void rope_apply_kernel() {
    int idx = blockIdx.x * blockDim.x + threadIdx.x;
    if (idx >= BS * (DD / 2)) return;
    int t = idx >> 10;
    int p = idx & 1023;
    int i = p & (NPAIR - 1);
    int s = t & (SS - 1);
    float c  = g_cos[(s << 6) + i];
    float sn = g_sin[(s << 6) + i];
    size_t base = ((size_t)t << 11) + ((size_t)p << 1);
    float2 q2 = *reinterpret_cast<float2*>(&g_q[base]);
    float2 k2 = *reinterpret_cast<float2*>(&g_k[base]);
    float2 qo = make_float2(q2.x * c - q2.y * sn, q2.x * sn + q2.y * c);
    float2 ko = make_float2(k2.x * c - k2.y * sn, k2.x * sn + k2.y * c);
    *reinterpret_cast<float2*>(&g_q[base]) = qo;
    *reinterpret_cast<float2*>(&g_k[base]) = ko;
}

// ---------------------------------------------------------------------------
// bf16x3 split for projection GEMMs
// ---------------------------------------------------------------------------
__global__ void split3_kernel(const float* __restrict__ src,
                              __nv_bfloat16* __restrict__ dst,
                              int n, int mode) {
    int idx = blockIdx.x * blockDim.x + threadIdx.x;
    if (idx >= n) return;
    int r = idx >> 11;
    int c = idx & 2047;
    float v = src[idx];
    __nv_bfloat16 hi = __float2bfloat16(v);
    __nv_bfloat16 lo = __float2bfloat16(v - __bfloat162float(hi));
    size_t base = (size_t)r * KBIG + c;
    if (mode == 0) {
        dst[base] = hi; dst[base + DD] = lo; dst[base + 2 * DD] = hi;
    } else {
        dst[base] = hi; dst[base + DD] = hi; dst[base + 2 * DD] = lo;
    }
}

// ---------------------------------------------------------------------------
// Q/K split to [bh][s][d] bf16 hi/lo.  Q scaled by 1/sqrt(hd).
// ---------------------------------------------------------------------------
__global__ void qk_split_kernel() {
    int idx = blockIdx.x * blockDim.x + threadIdx.x;
    if (idx >= BS * DD) return;
    int d = idx & 127;
    int h = (idx >> 7) & 15;
    int s = (idx >> 11) & 2047;
    int b = idx >> 22;
    size_t dst = ((size_t)(b * HH + h) * SS + s) * HD + d;
    float qv = g_q[idx] * QK_SCALE;
    __nv_bfloat16 qh = __float2bfloat16(qv);
    g_qshi[dst] = qh;
    g_qslo[dst] = __float2bfloat16(qv - __bfloat162float(qh));
    float kv = g_k[idx];
    __nv_bfloat16 kh = __float2bfloat16(kv);
    g_kshi[dst] = kh;
    g_kslo[dst] = __float2bfloat16(kv - __bfloat162float(kh));
}

// ---------------------------------------------------------------------------
// V transpose+split: g_v[b][s][h][d] -> g_vthi/lo [bh][d][s]
// ---------------------------------------------------------------------------
__global__ __launch_bounds__(256) void v_split_t_kernel() {
    __shared__ float st[64][129];
    const int s0 = blockIdx.x * 64;
    const int bh = blockIdx.y;
    const int b = bh >> 4, h = bh & 15;
    const float* src = g_v + (size_t)b * SS * DD + (size_t)s0 * DD + h * HD;
    const int tid = threadIdx.x;
#pragma unroll
    for (int i = 0; i < 32; i++) {
        int id = tid + 256 * i;
        int sl = id >> 7, d = id & 127;
        st[sl][d] = src[(size_t)sl * DD + d];
    }
    __syncthreads();
    const int d = tid >> 1, half = tid & 1;
    __nv_bfloat16 hibuf[32], lobuf[32];
#pragma unroll
    for (int j = 0; j < 32; j++) {
        float v = st[half * 32 + j][d];
        __nv_bfloat16 hi = __float2bfloat16(v);
        hibuf[j] = hi;
        lobuf[j] = __float2bfloat16(v - __bfloat162float(hi));
    }
    size_t dst = ((size_t)bh * HD + d) * SS + s0 + half * 32;
    uint4* ph = reinterpret_cast<uint4*>(&g_vthi[dst]);
    uint4* pl = reinterpret_cast<uint4*>(&g_vtlo[dst]);
#pragma unroll
    for (int tch = 0; tch < 4; tch++) {
        ph[tch] = reinterpret_cast<uint4*>(hibuf)[tch];
        pl[tch] = reinterpret_cast<uint4*>(lobuf)[tch];
    }
}

// ---------------------------------------------------------------------------
// HMMA GEMM (unchanged from R6)
// ---------------------------------------------------------------------------
#define TILE_STAGE_BYTES 32768
#define GEMM_SMEM_BYTES (STG * TILE_STAGE_BYTES)

__device__ __forceinline__ void issue_stage(
    uint32_t sb, int s, int tid,
    const __nv_bfloat16* __restrict__ Ag,
    const __nv_bfloat16* __restrict__ Bg)
{
    if (s < ITERS) {
        const int k0 = s * 64;
        const int slot = s & (STG - 1);
        uint32_t abase = sb + slot * TILE_STAGE_BYTES;
        uint32_t bbase = abase + 16384;
#pragma unroll
        for (int i = 0; i < 4; i++) {
            int id = tid + 256 * i;
            int row = id >> 3;
            int c = id & 7;
            uint32_t off = (uint32_t)(row * 128 + ((c ^ (row & 7)) << 4));
            CP_ASYNC16(abase + off, Ag + (size_t)row * KBIG + k0 + c * 8);
            CP_ASYNC16(bbase + off, Bg + (size_t)row * KBIG + k0 + c * 8);
        }
    }
    CP_COMMIT();
}

__global__ __launch_bounds__(256, 1)
void gemm_hmma(const __nv_bfloat16* __restrict__ A,
               const __nv_bfloat16* __restrict__ Bw,
               float* __restrict__ C)
{
    extern __shared__ char smraw[];
    uint32_t sb = smem_u32(smraw);
    const int tid  = threadIdx.x;
    const int lane = tid & 31;
    const int warp = tid >> 5;
    const int wm = warp & 1;
    const int wn = warp >> 1;
    const int m0 = blockIdx.y * 128;
    const int n0 = blockIdx.x * 128;
    const __nv_bfloat16* Ag = A  + (size_t)m0 * KBIG;
    const __nv_bfloat16* Bg = Bw + (size_t)n0 * KBIG;

    float acc[4][4][4];
#pragma unroll
    for (int a = 0; a < 4; a++)
#pragma unroll
        for (int b = 0; b < 4; b++)
#pragma unroll
            for (int c = 0; c < 4; c++) acc[a][b][c] = 0.f;

    issue_stage(sb, 0, tid, Ag, Bg);
    issue_stage(sb, 1, tid, Ag, Bg);
    issue_stage(sb, 2, tid, Ag, Bg);

    for (int s = 0; s < ITERS; s++) {
        asm volatile("cp.async.wait_group 2;" ::: "memory");
        __syncthreads();
        const int slot = s & (STG - 1);
        uint32_t abase = sb + slot * TILE_STAGE_BYTES;
        uint32_t bbase = abase + 16384;

#pragma unroll
        for (int ks = 0; ks < 4; ks++) {
            uint32_t af[4][4];
            uint32_t bf[4][2];
#pragma unroll
            for (int mt = 0; mt < 4; mt++) {
                int row = wm * 64 + mt * 16 + (lane & 15);
                int ch  = ks * 2 + (lane >> 4);
                uint32_t ad = abase + (uint32_t)(row * 128 +
                                  ((ch ^ (row & 7)) << 4));
                LDSM_X4(af[mt][0], af[mt][1], af[mt][2], af[mt][3], ad);
            }
#pragma unroll
            for (int np = 0; np < 2; np++) {
                int row = wn * 32 + np * 16 + ((lane >> 4) << 3) + (lane & 7);
                int ch  = ks * 2 + ((lane >> 3) & 1);
                uint32_t bd = bbase + (uint32_t)(row * 128 +
                                  ((ch ^ (row & 7)) << 4));
                LDSM_X4(bf[2 * np][0], bf[2 * np][1],
                        bf[2 * np + 1][0], bf[2 * np + 1][1], bd);
            }
#pragma unroll
            for (int mt = 0; mt < 4; mt++)
#pragma unroll
                for (int nt = 0; nt < 4; nt++)
                    MMA16816(acc[mt][nt], af[mt], bf[nt][0], bf[nt][1]);
        }
        issue_stage(sb, s + 3, tid, Ag, Bg);
    }

#pragma unroll
    for (int mt = 0; mt < 4; mt++) {
#pragma unroll
        for (int nt = 0; nt < 4; nt++) {
            int row = m0 + wm * 64 + mt * 16 + (lane >> 2);
            int col = n0 + wn * 32 + nt * 8 + (lane & 3) * 2;
            float2 v0 = make_float2(acc[mt][nt][0], acc[mt][nt][1]);
            float2 v1 = make_float2(acc[mt][nt][2], acc[mt][nt][3]);
            *reinterpret_cast<float2*>(&C[(size_t)row * DD + col]) = v0;
            *reinterpret_cast<float2*>(&C[(size_t)(row + 8) * DD + col]) = v1;
        }
    }
}

// ---------------------------------------------------------------------------
// HMMA flash attention, split-precision (error ~2^-18)
// Block: 64 queries x one (b,h); 256 threads = 8 warps (2m x 4n).
// smem byte offsets:
// ---------------------------------------------------------------------------
#define SQHI 0
#define SQLO 16384
#define SKHI 32768
#define SKLO 49152
#define SVHI 65536
#define SVLO 81920
#define SC_   98304           // scores fp32 [64][66]
#define SPHI 115200
#define SPLO 123392
#define SML  131584           // m[64], l[64], alpha[64]
#define FLASH2_SMEM (SML + 768)

// Q/K tile loader: 64 rows x 128 bf16 (256B rows, swizzled), hi+lo parts
__device__ __forceinline__ void issue_qk_tile(
    uint32_t dsthi, uint32_t dstlo,
    const __nv_bfloat16* __restrict__ ghi,
    const __nv_bfloat16* __restrict__ glo, int tid)
{
#pragma unroll
    for (int i = 0; i < 4; i++) {
        int id = tid + 256 * i;
        int row = id >> 4, c = id & 15;
        uint32_t off = (uint32_t)(row * 256 + ((c >> 3) << 7) +
                                  (((c & 7) ^ (row & 7)) << 4));
        CP_ASYNC16(dsthi + off, ghi + (size_t)row * HD + c * 8);
        CP_ASYNC16(dstlo + off, glo + (size_t)row * HD + c * 8);
    }
}
// V^T tile loader: 128 rows(d) x 64 bf16 (128B rows, swizzled); row stride SS
__device__ __forceinline__ void issue_v_tile(
    uint32_t dsthi, uint32_t dstlo,
    const __nv_bfloat16* __restrict__ ghi,
    const __nv_bfloat16* __restrict__ glo, int tid)
{
#pragma unroll
    for (int i = 0; i < 4; i++) {
        int id = tid + 256 * i;
        int row = id >> 3, c = id & 7;
        uint32_t off = (uint32_t)(row * 128 + ((c ^ (row & 7)) << 4));
        CP_ASYNC16(dsthi + off, ghi + (size_t)row * SS + c * 8);
        CP_ASYNC16(dstlo + off, glo + (size_t)row * SS + c * 8);
    }
}

__global__ __launch_bounds__(256, 1) void flash_mma_kernel() {
    extern __shared__ char smr[];
    uint32_t sb = smem_u32(smr);
    const int tid = threadIdx.x, lane = tid & 31, warp = tid >> 5;
    const int wm = warp & 1, wn = warp >> 1;
    const int q0 = blockIdx.x * 64;
    const int bh = blockIdx.y;

    const __nv_bfloat16* qhiG = g_qshi + ((size_t)bh * SS + q0) * HD;
    const __nv_bfloat16* qloG = g_qslo + ((size_t)bh * SS + q0) * HD;
    const __nv_bfloat16* khiB = g_kshi + (size_t)bh * SS * HD;
    const __nv_bfloat16* kloB = g_kslo + (size_t)bh * SS * HD;
    const __nv_bfloat16* vhiB = g_vthi + (size_t)bh * HD * SS;
    const __nv_bfloat16* vloB = g_vtlo + (size_t)bh * HD * SS;

    float* m_s  = reinterpret_cast<float*>(smr + SML);
    float* l_s  = m_s + 64;
    float* al_s = l_s + 64;
    float* SCp  = reinterpret_cast<float*>(smr + SC_);

    issue_qk_tile(sb + SQHI, sb + SQLO, qhiG, qloG, tid);
    CP_COMMIT();
    issue_qk_tile(sb + SKHI, sb + SKLO, khiB, kloB, tid);
    CP_COMMIT();

    if (tid < 64) { m_s[tid] = -1e30f; l_s[tid] = 0.f; }

    float o[2][4][4];
#pragma unroll
    for (int mt = 0; mt < 2; mt++)
#pragma unroll
        for (int nt = 0; nt < 4; nt++)
#pragma unroll
            for (int c = 0; c < 4; c++) o[mt][nt][c] = 0.f;

    for (int t = 0; t < 32; t++) {
        asm volatile("cp.async.wait_group 0;" ::: "memory");
        __syncthreads();
        // Prefetch V(t) while QK computes
        issue_v_tile(sb + SVHI, sb + SVLO, vhiB + t * 64, vloB + t * 64, tid);
        CP_COMMIT();

        // ---- QK^T: 64x64, k' = 384 ([qhi|qlo|qhi] . [khi|khi|klo]) ----
        float sc[2][2][4];
#pragma unroll
        for (int mt = 0; mt < 2; mt++)
#pragma unroll
            for (int nt = 0; nt < 2; nt++)
#pragma unroll
                for (int c = 0; c < 4; c++) sc[mt][nt][c] = 0.f;

#pragma unroll
        for (int ks = 0; ks < 24; ks++) {
            const int term = ks >> 3, pk = ks & 7;
            uint32_t abase = sb + ((term == 1) ? SQLO : SQHI);
            uint32_t bbase = sb + ((term == 2) ? SKLO : SKHI);
            uint32_t af[2][4], bfr[2][2];
#pragma unroll
            for (int mt = 0; mt < 2; mt++) {
                int row = wm * 32 + mt * 16 + (lane & 15);
                int c0 = pk * 2 + (lane >> 4);
                uint32_t ad = abase + (uint32_t)(row * 256 + ((c0 >> 3) << 7) +
                                  (((c0 & 7) ^ (row & 7)) << 4));
                LDSM_X4(af[mt][0], af[mt][1], af[mt][2], af[mt][3], ad);
            }
            {
                int row = wn * 16 + ((lane >> 4) << 3) + (lane & 7);
                int c0 = pk * 2 + ((lane >> 3) & 1);
                uint32_t bd = bbase + (uint32_t)(row * 256 + ((c0 >> 3) << 7) +
                                  (((c0 & 7) ^ (row & 7)) << 4));
                LDSM_X4(bfr[0][0], bfr[0][1], bfr[1][0], bfr[1][1], bd);
            }
#pragma unroll
            for (int mt = 0; mt < 2; mt++)
#pragma unroll
                for (int nt = 0; nt < 2; nt++)
                    MMA16816(sc[mt][nt], af[mt], bfr[nt][0], bfr[nt][1]);
        }
        // write scores (already scaled via Q)
#pragma unroll
        for (int mt = 0; mt < 2; mt++)
#pragma unroll
            for (int nt = 0; nt < 2; nt++) {
                int row = wm * 32 + mt * 16 + (lane >> 2);
                int col = wn * 16 + nt * 8 + (lane & 3) * 2;
                *reinterpret_cast<float2*>(&SCp[row * 66 + col]) =
                    make_float2(sc[mt][nt][0], sc[mt][nt][1]);
                *reinterpret_cast<float2*>(&SCp[(row + 8) * 66 + col]) =
                    make_float2(sc[mt][nt][2], sc[mt][nt][3]);
            }
        __syncthreads();

        // ---- online softmax: 4 threads per row, 16 keys each ----
        {
            const int r = tid >> 2, part = tid & 3;
            float vals[16];
            float mloc = -1e30f;
#pragma unroll
            for (int j = 0; j < 16; j++) {
                vals[j] = SCp[r * 66 + part * 16 + j];
                mloc = fmaxf(mloc, vals[j]);
            }
            mloc = fmaxf(mloc, __shfl_xor_sync(0xffffffff, mloc, 1));
            mloc = fmaxf(mloc, __shfl_xor_sync(0xffffffff, mloc, 2));
            float mprev = 0.f, mnew = 0.f;
            if (part == 0) {
                mprev = m_s[r];
                mnew = fmaxf(mprev, mloc);
            }
            mnew = __shfl_sync(0xffffffff, mnew, lane & ~3);
            float tsum = 0.f;
#pragma unroll
            for (int j = 0; j < 16; j += 2) {
                float p0 = exp2_fast((vals[j] - mnew) * LOG2E);
                float p1 = exp2_fast((vals[j + 1] - mnew) * LOG2E);
                tsum += p0 + p1;
                __nv_bfloat16 h0 = __float2bfloat16(p0);
                __nv_bfloat16 h1 = __float2bfloat16(p1);
                __nv_bfloat16 l0 = __float2bfloat16(p0 - __bfloat162float(h0));
                __nv_bfloat16 l1 = __float2bfloat16(p1 - __bfloat162float(h1));
                int col = part * 16 + j;
                uint32_t off = (uint32_t)(r * 128 +
                                  (((col >> 3) ^ (r & 7)) << 4) + (col & 7) * 2);
                __nv_bfloat162 h2; h2.x = h0; h2.y = h1;
                __nv_bfloat162 l2; l2.x = l0; l2.y = l1;
                *reinterpret_cast<__nv_bfloat162*>(smr + SPHI + off) = h2;
                *reinterpret_cast<__nv_bfloat162*>(smr + SPLO + off) = l2;
            }
            tsum += __shfl_xor_sync(0xffffffff, tsum, 1);
            tsum += __shfl_xor_sync(0xffffffff, tsum, 2);
            if (part == 0) {
                float alpha = exp2_fast((mprev - mnew) * LOG2E);
                l_s[r] = l_s[r] * alpha + tsum;
                m_s[r] = mnew;
                al_s[r] = alpha;
            }
        }
        __syncthreads();

        // Prefetch K(t+1) while PV computes (QK done reading K buffers)
        if (t + 1 < 32)
            issue_qk_tile(sb + SKHI, sb + SKLO,
                          khiB + (size_t)(t + 1) * 64 * HD,
                          kloB + (size_t)(t + 1) * 64 * HD, tid);
        CP_COMMIT();
        asm volatile("cp.async.wait_group 1;" ::: "memory");  // V(t) ready
        __syncthreads();

        // ---- rescale O, then PV: 64x128, j' = 192 ----
#pragma unroll
        for (int mt = 0; mt < 2; mt++) {
            float a0 = al_s[wm * 32 + mt * 16 + (lane >> 2)];
            float a8 = al_s[wm * 32 + mt * 16 + (lane >> 2) + 8];
#pragma unroll
            for (int nt = 0; nt < 4; nt++) {
                o[mt][nt][0] *= a0; o[mt][nt][1] *= a0;
                o[mt][nt][2] *= a8; o[mt][nt][3] *= a8;
            }
        }
#pragma unroll
        for (int ks = 0; ks < 12; ks++) {
            const int term = ks >> 2, pk = ks & 3;
            uint32_t abase = sb + ((term == 1) ? SPLO : SPHI);
            uint32_t bbase = sb + ((term == 2) ? SVLO : SVHI);
            uint32_t af[2][4], bfr[4][2];
#pragma unroll
            for (int mt = 0; mt < 2; mt++) {
                int row = wm * 32 + mt * 16 + (lane & 15);
                int c0 = pk * 2 + (lane >> 4);
                uint32_t ad = abase + (uint32_t)(row * 128 +
                                  ((c0 ^ (row & 7)) << 4));
                LDSM_X4(af[mt][0], af[mt][1], af[mt][2], af[mt][3], ad);
            }
#pragma unroll
            for (int np = 0; np < 2; np++) {
                int row = wn * 32 + np * 16 + ((lane >> 4) << 3) + (lane & 7);
                int c0 = pk * 2 + ((lane >> 3) & 1);
                uint32_t bd = bbase + (uint32_t)(row * 128 +
                                  ((c0 ^ (row & 7)) << 4));
                LDSM_X4(bfr[2 * np][0], bfr[2 * np][1],
                        bfr[2 * np + 1][0], bfr[2 * np + 1][1], bd);
            }
#pragma unroll
            for (int mt = 0; mt < 2; mt++)
#pragma unroll
                for (int nt = 0; nt < 4; nt++)
                    MMA16816(o[mt][nt], af[mt], bfr[nt][0], bfr[nt][1]);
        }
    }

    // Epilogue: normalize by 1/l, write g_ao[b][s][h][d]
    const int b = bh >> 4, h = bh & 15;
#pragma unroll
    for (int mt = 0; mt < 2; mt++) {
        int row = wm * 32 + mt * 16 + (lane >> 2);
        float inv0 = 1.0f / l_s[row];
        float inv8 = 1.0f / l_s[row + 8];
#pragma unroll
        for (int nt = 0; nt < 4; nt++) {
            int col = wn * 32 + nt * 8 + (lane & 3) * 2;
            size_t a0 = (size_t)b * SS * DD + (size_t)(q0 + row) * DD +
                        h * HD + col;
            *reinterpret_cast<float2*>(&g_ao[a0]) =
                make_float2(o[mt][nt][0] * inv0, o[mt][nt][1] * inv0);
            *reinterpret_cast<float2*>(&g_ao[a0 + 8 * DD]) =
                make_float2(o[mt][nt][2] * inv8, o[mt][nt][3] * inv8);
        }
    }
}

// ---------------------------------------------------------------------------
// Launch
// ---------------------------------------------------------------------------
extern "C" void kernel_launch(void* const* d_in, const int* in_sizes, int n_in,
                              void* d_out, int out_size) {
    (void)in_sizes; (void)n_in; (void)out_size;
    const float* x  = (const float*)d_in[0];
    const float* wq = (const float*)d_in[1];
    const float* wk = (const float*)d_in[2];
    const float* wv = (const float*)d_in[3];
    const float* wo = (const float*)d_in[4];
    float* out = (float*)d_out;

    float *q, *k, *v, *ao;
    __nv_bfloat16 *abig, *wbig;
    cudaGetSymbolAddress((void**)&q,    g_q);
    cudaGetSymbolAddress((void**)&k,    g_k);
    cudaGetSymbolAddress((void**)&v,    g_v);
    cudaGetSymbolAddress((void**)&ao,   g_ao);
    cudaGetSymbolAddress((void**)&abig, g_abig);
    cudaGetSymbolAddress((void**)&wbig, g_wbig);

    cudaFuncSetAttribute(gemm_hmma,
                         cudaFuncAttributeMaxDynamicSharedMemorySize,
                         GEMM_SMEM_BYTES);
    cudaFuncSetAttribute(flash_mma_kernel,
                         cudaFuncAttributeMaxDynamicSharedMemorySize,
                         FLASH2_SMEM);

    const int n_act = BS * DD;
    const int n_w   = DD * DD;
    dim3 ggrid(DD / 128, BS / 128);

    rope_table_kernel<<<(SS * NPAIR + 255) / 256, 256>>>();

    split3_kernel<<<(n_act + 255) / 256, 256>>>(x, abig, n_act, 0);

    split3_kernel<<<(n_w + 255) / 256, 256>>>(wq, wbig, n_w, 1);
    gemm_hmma<<<ggrid, 256, GEMM_SMEM_BYTES>>>(abig, wbig, q);
    split3_kernel<<<(n_w + 255) / 256, 256>>>(wk, wbig, n_w, 1);
    gemm_hmma<<<ggrid, 256, GEMM_SMEM_BYTES>>>(abig, wbig, k);
    split3_kernel<<<(n_w + 255) / 256, 256>>>(wv, wbig, n_w, 1);
    gemm_hmma<<<ggrid, 256, GEMM_SMEM_BYTES>>>(abig, wbig, v);

    rope_apply_kernel<<<(BS * (DD / 2) + 255) / 256, 256>>>();

    // Attention pre-splits
    qk_split_kernel<<<(BS * DD + 255) / 256, 256>>>();
    v_split_t_kernel<<<dim3(SS / 64, BB * HH), 256>>>();

    // HMMA flash attention
    flash_mma_kernel<<<dim3(SS / 64, BB * HH), 256, FLASH2_SMEM>>>();

    split3_kernel<<<(n_act + 255) / 256, 256>>>(ao, abig, n_act, 0);
    split3_kernel<<<(n_w + 255) / 256, 256>>>(wo, wbig, n_w, 1);
    gemm_hmma<<<ggrid, 256, GEMM_SMEM_BYTES>>>(abig, wbig, out);
}

// round 8
// speedup vs baseline: 1.6487x; 1.0617x over previous
#include <cuda_runtime.h>
#include <cuda_bf16.h>
#include <math.h>
#include <stdint.h>

// Problem constants
#define BB 2
#define SS 2048
#define DD 2048
#define HH 16
#define HD 128
#define BS (BB * SS)        // 4096 tokens
#define NPAIR (HD / 2)      // 64 rope pairs per head
#define KBIG (3 * DD)       // 6144: bf16x3 split-K
#define ITERS (KBIG / 64)   // 96 K-chunks of 64
#define STG 4               // cp.async pipeline stages
#define LOG2E 1.4426950408889634f
#define QK_SCALE 0.08838834764831845f

// ---------------------------------------------------------------------------
// Scratch (device globals -- no allocation allowed in kernel_launch)
// ---------------------------------------------------------------------------
__device__ float g_qkv[(size_t)BS * KBIG];           // fused QKV output [t][q|k|v]
__device__ float g_cos[SS * NPAIR];
__device__ float g_sin[SS * NPAIR];
__device__ __nv_bfloat16 g_abig[(size_t)BS * KBIG];  // activations [hi | lo | hi]
__device__ __nv_bfloat16 g_wbig[(size_t)KBIG * KBIG]; // weights [hi | hi | lo], up to 6144 rows
// Attention split buffers, [bh][s][d] (q/k) and [bh][d][s] (v transposed)
__device__ __nv_bfloat16 g_qshi[(size_t)BS * DD];
__device__ __nv_bfloat16 g_qslo[(size_t)BS * DD];
__device__ __nv_bfloat16 g_kshi[(size_t)BS * DD];
__device__ __nv_bfloat16 g_kslo[(size_t)BS * DD];
__device__ __nv_bfloat16 g_vthi[(size_t)BS * DD];
__device__ __nv_bfloat16 g_vtlo[(size_t)BS * DD];

// ---------------------------------------------------------------------------
// Helpers
// ---------------------------------------------------------------------------
__device__ __forceinline__ uint32_t smem_u32(const void* p) {
    uint32_t a;
    asm("{ .reg .u64 t; cvta.to.shared.u64 t, %1; cvt.u32.u64 %0, t; }"
        : "=r"(a) : "l"(p));
    return a;
}
#define CP_ASYNC16(smem, gptr) \
    asm volatile("cp.async.cg.shared.global [%0], [%1], 16;" \
                 :: "r"((uint32_t)(smem)), "l"((const void*)(gptr)) : "memory")
#define CP_COMMIT() asm volatile("cp.async.commit_group;" ::: "memory")

#define LDSM_X4(r0, r1, r2, r3, addr) \
    asm volatile("ldmatrix.sync.aligned.m8n8.x4.shared.b16 {%0,%1,%2,%3}, [%4];" \
                 : "=r"(r0), "=r"(r1), "=r"(r2), "=r"(r3) : "r"(addr))

#define MMA16816(d, a, b0, b1) \
    asm volatile("mma.sync.aligned.m16n8k16.row.col.f32.bf16.bf16.f32 " \
                 "{%0,%1,%2,%3}, {%4,%5,%6,%7}, {%8,%9}, {%0,%1,%2,%3};" \
                 : "+f"((d)[0]), "+f"((d)[1]), "+f"((d)[2]), "+f"((d)[3]) \
                 : "r"((a)[0]), "r"((a)[1]), "r"((a)[2]), "r"((a)[3]),   \
                   "r"(b0), "r"(b1))

// Fast exp2 on FMA pipe: t <= 0, clamp at -126; |rel err| ~ 3e-6
__device__ __forceinline__ float exp2_fast(float t) {
    t = fmaxf(t, -126.0f);
    float r = t + 12582912.0f;
    int e = __float_as_int(r) - 0x4B400000;
    float f = t - (r - 12582912.0f);
    float p = 0.0013333558f;
    p = fmaf(p, f, 0.0096181291f);
    p = fmaf(p, f, 0.0555041087f);
    p = fmaf(p, f, 0.2402265070f);
    p = fmaf(p, f, 0.6931471806f);
    p = fmaf(p, f, 1.0f);
    return __int_as_float((e + 127) << 23) * p;
}
__device__ __forceinline__ __nv_bfloat162 split_hi2(float a, float b,
                                                    __nv_bfloat162& lo2) {
    __nv_bfloat16 ha = __float2bfloat16(a);
    __nv_bfloat16 hb = __float2bfloat16(b);
    lo2.x = __float2bfloat16(a - __bfloat162float(ha));
    lo2.y = __float2bfloat16(b - __bfloat162float(hb));
    __nv_bfloat162 hi2; hi2.x = ha; hi2.y = hb;
    return hi2;
}

// ---------------------------------------------------------------------------
// RoPE table (double precision generation)
// ---------------------------------------------------------------------------
__global__ void rope_table_kernel() {
    int idx = blockIdx.x * blockDim.x + threadIdx.x;
    if (idx >= SS * NPAIR) return;
    int s = idx / NPAIR;
    int i = idx - s * NPAIR;
    double freq = (double)s * exp(((double)(-2 * i) / (double)HD) * log(10000.0));
    g_cos[idx] = (float)cos(freq);
    g_sin[idx] = (float)sin(freq);
}

// ---------------------------------------------------------------------------
// bf16x3 split for projection GEMMs
// ---------------------------------------------------------------------------
__global__ void split3_kernel(const float* __restrict__ src,
                              __nv_bfloat16* __restrict__ dst,
                              int n, int mode) {
    int idx = blockIdx.x * blockDim.x + threadIdx.x;
    if (idx >= n) return;
    int r = idx >> 11;
    int c = idx & 2047;
    float v = src[idx];
    __nv_bfloat16 hi = __float2bfloat16(v);
    __nv_bfloat16 lo = __float2bfloat16(v - __bfloat162float(hi));
    size_t base = (size_t)r * KBIG + c;
    if (mode == 0) {
        dst[base] = hi; dst[base + DD] = lo; dst[base + 2 * DD] = hi;
    } else {
        dst[base] = hi; dst[base + DD] = hi; dst[base + 2 * DD] = lo;
    }
}

// ---------------------------------------------------------------------------
// Fused RoPE + scale + bf16 split for q,k straight out of g_qkv.
// One thread per rope pair (BS * 1024 pairs).
// ---------------------------------------------------------------------------
__global__ void qkv_rope_split_kernel() {
    int idx = blockIdx.x * blockDim.x + threadIdx.x;
    if (idx >= BS * 1024) return;
    int t = idx >> 10;          // token
    int p = idx & 1023;
    int h = p >> 6;
    int i = p & 63;
    int s = t & (SS - 1);
    int b = t >> 11;
    float c  = g_cos[(s << 6) + i];
    float sn = g_sin[(s << 6) + i];
    size_t src = (size_t)t * KBIG + h * HD + 2 * i;
    float q0 = g_qkv[src],        q1 = g_qkv[src + 1];
    float k0 = g_qkv[src + DD],   k1 = g_qkv[src + DD + 1];
    float qo0 = (q0 * c - q1 * sn) * QK_SCALE;
    float qo1 = (q0 * sn + q1 * c) * QK_SCALE;
    float ko0 = k0 * c - k1 * sn;
    float ko1 = k0 * sn + k1 * c;
    size_t dst = ((size_t)(b * HH + h) * SS + s) * HD + 2 * i;
    __nv_bfloat162 lo2;
    __nv_bfloat162 hi2 = split_hi2(qo0, qo1, lo2);
    *reinterpret_cast<__nv_bfloat162*>(&g_qshi[dst]) = hi2;
    *reinterpret_cast<__nv_bfloat162*>(&g_qslo[dst]) = lo2;
    hi2 = split_hi2(ko0, ko1, lo2);
    *reinterpret_cast<__nv_bfloat162*>(&g_kshi[dst]) = hi2;
    *reinterpret_cast<__nv_bfloat162*>(&g_kslo[dst]) = lo2;
}

// ---------------------------------------------------------------------------
// V transpose+split: g_qkv[t][4096 + h*128 + d] -> g_vthi/lo [bh][d][s]
// ---------------------------------------------------------------------------
__global__ __launch_bounds__(256) void v_split_t_kernel() {
    __shared__ float st[64][129];
    const int s0 = blockIdx.x * 64;
    const int bh = blockIdx.y;
    const int b = bh >> 4, h = bh & 15;
    const float* src = g_qkv + (size_t)(b * SS + s0) * KBIG + 2 * DD + h * HD;
    const int tid = threadIdx.x;
#pragma unroll
    for (int i = 0; i < 32; i++) {
        int id = tid + 256 * i;
        int sl = id >> 7, d = id & 127;
        st[sl][d] = src[(size_t)sl * KBIG + d];
    }
    __syncthreads();
    const int d = tid >> 1, half = tid & 1;
    __nv_bfloat16 hibuf[32], lobuf[32];
#pragma unroll
    for (int j = 0; j < 32; j++) {
        float v = st[half * 32 + j][d];
        __nv_bfloat16 hi = __float2bfloat16(v);
        hibuf[j] = hi;
        lobuf[j] = __float2bfloat16(v - __bfloat162float(hi));
    }
    size_t dst = ((size_t)bh * HD + d) * SS + s0 + half * 32;
    uint4* ph = reinterpret_cast<uint4*>(&g_vthi[dst]);
    uint4* pl = reinterpret_cast<uint4*>(&g_vtlo[dst]);
#pragma unroll
    for (int tch = 0; tch < 4; tch++) {
        ph[tch] = reinterpret_cast<uint4*>(hibuf)[tch];
        pl[tch] = reinterpret_cast<uint4*>(lobuf)[tch];
    }
}

// ---------------------------------------------------------------------------
// HMMA GEMM: C[4096, N] = A[4096,6144] * B[N,6144]^T, ldc = N (2048 or 6144)
// ---------------------------------------------------------------------------
#define TILE_STAGE_BYTES 32768
#define GEMM_SMEM_BYTES (STG * TILE_STAGE_BYTES)

__device__ __forceinline__ void issue_stage(
    uint32_t sb, int s, int tid,
    const __nv_bfloat16* __restrict__ Ag,
    const __nv_bfloat16* __restrict__ Bg)
{
    if (s < ITERS) {
        const int k0 = s * 64;
        const int slot = s & (STG - 1);
        uint32_t abase = sb + slot * TILE_STAGE_BYTES;
        uint32_t bbase = abase + 16384;
#pragma unroll
        for (int i = 0; i < 4; i++) {
            int id = tid + 256 * i;
            int row = id >> 3;
            int c = id & 7;
            uint32_t off = (uint32_t)(row * 128 + ((c ^ (row & 7)) << 4));
            CP_ASYNC16(abase + off, Ag + (size_t)row * KBIG + k0 + c * 8);
            CP_ASYNC16(bbase + off, Bg + (size_t)row * KBIG + k0 + c * 8);
        }
    }
    CP_COMMIT();
}

__global__ __launch_bounds__(256, 1)
void gemm_hmma(const __nv_bfloat16* __restrict__ A,
               const __nv_bfloat16* __restrict__ Bw,
               float* __restrict__ C, int ldc)
{
    extern __shared__ char smraw[];
    uint32_t sb = smem_u32(smraw);
    const int tid  = threadIdx.x;
    const int lane = tid & 31;
    const int warp = tid >> 5;
    const int wm = warp & 1;
    const int wn = warp >> 1;
    const int m0 = blockIdx.y * 128;
    const int n0 = blockIdx.x * 128;
    const __nv_bfloat16* Ag = A  + (size_t)m0 * KBIG;
    const __nv_bfloat16* Bg = Bw + (size_t)n0 * KBIG;

    float acc[4][4][4];
#pragma unroll
    for (int a = 0; a < 4; a++)
#pragma unroll
        for (int b = 0; b < 4; b++)
#pragma unroll
            for (int c = 0; c < 4; c++) acc[a][b][c] = 0.f;

    issue_stage(sb, 0, tid, Ag, Bg);
    issue_stage(sb, 1, tid, Ag, Bg);
    issue_stage(sb, 2, tid, Ag, Bg);

    for (int s = 0; s < ITERS; s++) {
        asm volatile("cp.async.wait_group 2;" ::: "memory");
        __syncthreads();
        const int slot = s & (STG - 1);
        uint32_t abase = sb + slot * TILE_STAGE_BYTES;
        uint32_t bbase = abase + 16384;

#pragma unroll
        for (int ks = 0; ks < 4; ks++) {
            uint32_t af[4][4];
            uint32_t bf[4][2];
#pragma unroll
            for (int mt = 0; mt < 4; mt++) {
                int row = wm * 64 + mt * 16 + (lane & 15);
                int ch  = ks * 2 + (lane >> 4);
                uint32_t ad = abase + (uint32_t)(row * 128 +
                                  ((ch ^ (row & 7)) << 4));
                LDSM_X4(af[mt][0], af[mt][1], af[mt][2], af[mt][3], ad);
            }
#pragma unroll
            for (int np = 0; np < 2; np++) {
                int row = wn * 32 + np * 16 + ((lane >> 4) << 3) + (lane & 7);
                int ch  = ks * 2 + ((lane >> 3) & 1);
                uint32_t bd = bbase + (uint32_t)(row * 128 +
                                  ((ch ^ (row & 7)) << 4));
                LDSM_X4(bf[2 * np][0], bf[2 * np][1],
                        bf[2 * np + 1][0], bf[2 * np + 1][1], bd);
            }
#pragma unroll
            for (int mt = 0; mt < 4; mt++)
#pragma unroll
                for (int nt = 0; nt < 4; nt++)
                    MMA16816(acc[mt][nt], af[mt], bf[nt][0], bf[nt][1]);
        }
        issue_stage(sb, s + 3, tid, Ag, Bg);
    }

#pragma unroll
    for (int mt = 0; mt < 4; mt++) {
#pragma unroll
        for (int nt = 0; nt < 4; nt++) {
            int row = m0 + wm * 64 + mt * 16 + (lane >> 2);
            int col = n0 + wn * 32 + nt * 8 + (lane & 3) * 2;
            float2 v0 = make_float2(acc[mt][nt][0], acc[mt][nt][1]);
            float2 v1 = make_float2(acc[mt][nt][2], acc[mt][nt][3]);
            *reinterpret_cast<float2*>(&C[(size_t)row * ldc + col]) = v0;
            *reinterpret_cast<float2*>(&C[(size_t)(row + 8) * ldc + col]) = v1;
        }
    }
}

// ---------------------------------------------------------------------------
// HMMA flash attention, split-precision; epilogue writes [hi|lo|hi] to g_abig
// ---------------------------------------------------------------------------
#define SQHI 0
#define SQLO 16384
#define SKHI 32768
#define SKLO 49152
#define SVHI 65536
#define SVLO 81920
#define SC_   98304           // scores fp32 [64][66]
#define SPHI 115200
#define SPLO 123392
#define SML  131584           // m[64], l[64], alpha[64]
#define FLASH2_SMEM (SML + 768)

__device__ __forceinline__ void issue_qk_tile(
    uint32_t dsthi, uint32_t dstlo,
    const __nv_bfloat16* __restrict__ ghi,
    const __nv_bfloat16* __restrict__ glo, int tid)
{
#pragma unroll
    for (int i = 0; i < 4; i++) {
        int id = tid + 256 * i;
        int row = id >> 4, c = id & 15;
        uint32_t off = (uint32_t)(row * 256 + ((c >> 3) << 7) +
                                  (((c & 7) ^ (row & 7)) << 4));
        CP_ASYNC16(dsthi + off, ghi + (size_t)row * HD + c * 8);
        CP_ASYNC16(dstlo + off, glo + (size_t)row * HD + c * 8);
    }
}
__device__ __forceinline__ void issue_v_tile(
    uint32_t dsthi, uint32_t dstlo,
    const __nv_bfloat16* __restrict__ ghi,
    const __nv_bfloat16* __restrict__ glo, int tid)
{
#pragma unroll
    for (int i = 0; i < 4; i++) {
        int id = tid + 256 * i;
        int row = id >> 3, c = id & 7;
        uint32_t off = (uint32_t)(row * 128 + ((c ^ (row & 7)) << 4));
        CP_ASYNC16(dsthi + off, ghi + (size_t)row * SS + c * 8);
        CP_ASYNC16(dstlo + off, glo + (size_t)row * SS + c * 8);
    }
}

__global__ __launch_bounds__(256, 1) void flash_mma_kernel() {
    extern __shared__ char smr[];
    uint32_t sb = smem_u32(smr);
    const int tid = threadIdx.x, lane = tid & 31, warp = tid >> 5;
    const int wm = warp & 1, wn = warp >> 1;
    const int q0 = blockIdx.x * 64;
    const int bh = blockIdx.y;

    const __nv_bfloat16* qhiG = g_qshi + ((size_t)bh * SS + q0) * HD;
    const __nv_bfloat16* qloG = g_qslo + ((size_t)bh * SS + q0) * HD;
    const __nv_bfloat16* khiB = g_kshi + (size_t)bh * SS * HD;
    const __nv_bfloat16* kloB = g_kslo + (size_t)bh * SS * HD;
    const __nv_bfloat16* vhiB = g_vthi + (size_t)bh * HD * SS;
    const __nv_bfloat16* vloB = g_vtlo + (size_t)bh * HD * SS;

    float* m_s  = reinterpret_cast<float*>(smr + SML);
    float* l_s  = m_s + 64;
    float* al_s = l_s + 64;
    float* SCp  = reinterpret_cast<float*>(smr + SC_);

    issue_qk_tile(sb + SQHI, sb + SQLO, qhiG, qloG, tid);
    CP_COMMIT();
    issue_qk_tile(sb + SKHI, sb + SKLO, khiB, kloB, tid);
    CP_COMMIT();

    if (tid < 64) { m_s[tid] = -1e30f; l_s[tid] = 0.f; }

    float o[2][4][4];
#pragma unroll
    for (int mt = 0; mt < 2; mt++)
#pragma unroll
        for (int nt = 0; nt < 4; nt++)
#pragma unroll
            for (int c = 0; c < 4; c++) o[mt][nt][c] = 0.f;

    for (int t = 0; t < 32; t++) {
        asm volatile("cp.async.wait_group 0;" ::: "memory");
        __syncthreads();
        issue_v_tile(sb + SVHI, sb + SVLO, vhiB + t * 64, vloB + t * 64, tid);
        CP_COMMIT();

        // ---- QK^T: 64x64, k' = 384 ----
        float sc[2][2][4];
#pragma unroll
        for (int mt = 0; mt < 2; mt++)
#pragma unroll
            for (int nt = 0; nt < 2; nt++)
#pragma unroll
                for (int c = 0; c < 4; c++) sc[mt][nt][c] = 0.f;

#pragma unroll
        for (int ks = 0; ks < 24; ks++) {
            const int term = ks >> 3, pk = ks & 7;
            uint32_t abase = sb + ((term == 1) ? SQLO : SQHI);
            uint32_t bbase = sb + ((term == 2) ? SKLO : SKHI);
            uint32_t af[2][4], bfr[2][2];
#pragma unroll
            for (int mt = 0; mt < 2; mt++) {
                int row = wm * 32 + mt * 16 + (lane & 15);
                int c0 = pk * 2 + (lane >> 4);
                uint32_t ad = abase + (uint32_t)(row * 256 + ((c0 >> 3) << 7) +
                                  (((c0 & 7) ^ (row & 7)) << 4));
                LDSM_X4(af[mt][0], af[mt][1], af[mt][2], af[mt][3], ad);
            }
            {
                int row = wn * 16 + ((lane >> 4) << 3) + (lane & 7);
                int c0 = pk * 2 + ((lane >> 3) & 1);
                uint32_t bd = bbase + (uint32_t)(row * 256 + ((c0 >> 3) << 7) +
                                  (((c0 & 7) ^ (row & 7)) << 4));
                LDSM_X4(bfr[0][0], bfr[0][1], bfr[1][0], bfr[1][1], bd);
            }
#pragma unroll
            for (int mt = 0; mt < 2; mt++)
#pragma unroll
                for (int nt = 0; nt < 2; nt++)
                    MMA16816(sc[mt][nt], af[mt], bfr[nt][0], bfr[nt][1]);
        }
#pragma unroll
        for (int mt = 0; mt < 2; mt++)
#pragma unroll
            for (int nt = 0; nt < 2; nt++) {
                int row = wm * 32 + mt * 16 + (lane >> 2);
                int col = wn * 16 + nt * 8 + (lane & 3) * 2;
                *reinterpret_cast<float2*>(&SCp[row * 66 + col]) =
                    make_float2(sc[mt][nt][0], sc[mt][nt][1]);
                *reinterpret_cast<float2*>(&SCp[(row + 8) * 66 + col]) =
                    make_float2(sc[mt][nt][2], sc[mt][nt][3]);
            }
        __syncthreads();

        // ---- online softmax: 4 threads per row ----
        {
            const int r = tid >> 2, part = tid & 3;
            float vals[16];
            float mloc = -1e30f;
#pragma unroll
            for (int j = 0; j < 16; j++) {
                vals[j] = SCp[r * 66 + part * 16 + j];
                mloc = fmaxf(mloc, vals[j]);
            }
            mloc = fmaxf(mloc, __shfl_xor_sync(0xffffffff, mloc, 1));
            mloc = fmaxf(mloc, __shfl_xor_sync(0xffffffff, mloc, 2));
            float mprev = 0.f, mnew = 0.f;
            if (part == 0) {
                mprev = m_s[r];
                mnew = fmaxf(mprev, mloc);
            }
            mnew = __shfl_sync(0xffffffff, mnew, lane & ~3);
            float tsum = 0.f;
#pragma unroll
            for (int j = 0; j < 16; j += 2) {
                float p0 = exp2_fast((vals[j] - mnew) * LOG2E);
                float p1 = exp2_fast((vals[j + 1] - mnew) * LOG2E);
                tsum += p0 + p1;
                __nv_bfloat162 l2;
                __nv_bfloat162 h2 = split_hi2(p0, p1, l2);
                int col = part * 16 + j;
                uint32_t off = (uint32_t)(r * 128 +
                                  (((col >> 3) ^ (r & 7)) << 4) + (col & 7) * 2);
                *reinterpret_cast<__nv_bfloat162*>(smr + SPHI + off) = h2;
                *reinterpret_cast<__nv_bfloat162*>(smr + SPLO + off) = l2;
            }
            tsum += __shfl_xor_sync(0xffffffff, tsum, 1);
            tsum += __shfl_xor_sync(0xffffffff, tsum, 2);
            if (part == 0) {
                float alpha = exp2_fast((mprev - mnew) * LOG2E);
                l_s[r] = l_s[r] * alpha + tsum;
                m_s[r] = mnew;
                al_s[r] = alpha;
            }
        }
        __syncthreads();

        if (t + 1 < 32)
            issue_qk_tile(sb + SKHI, sb + SKLO,
                          khiB + (size_t)(t + 1) * 64 * HD,
                          kloB + (size_t)(t + 1) * 64 * HD, tid);
        CP_COMMIT();
        asm volatile("cp.async.wait_group 1;" ::: "memory");
        __syncthreads();

        // ---- rescale O, then PV: 64x128, j' = 192 ----
#pragma unroll
        for (int mt = 0; mt < 2; mt++) {
            float a0 = al_s[wm * 32 + mt * 16 + (lane >> 2)];
            float a8 = al_s[wm * 32 + mt * 16 + (lane >> 2) + 8];
#pragma unroll
            for (int nt = 0; nt < 4; nt++) {
                o[mt][nt][0] *= a0; o[mt][nt][1] *= a0;
                o[mt][nt][2] *= a8; o[mt][nt][3] *= a8;
            }
        }
#pragma unroll
        for (int ks = 0; ks < 12; ks++) {
            const int term = ks >> 2, pk = ks & 3;
            uint32_t abase = sb + ((term == 1) ? SPLO : SPHI);
            uint32_t bbase = sb + ((term == 2) ? SVLO : SVHI);
            uint32_t af[2][4], bfr[4][2];
#pragma unroll
            for (int mt = 0; mt < 2; mt++) {
                int row = wm * 32 + mt * 16 + (lane & 15);
                int c0 = pk * 2 + (lane >> 4);
                uint32_t ad = abase + (uint32_t)(row * 128 +
                                  ((c0 ^ (row & 7)) << 4));
                LDSM_X4(af[mt][0], af[mt][1], af[mt][2], af[mt][3], ad);
            }
#pragma unroll
            for (int np = 0; np < 2; np++) {
                int row = wn * 32 + np * 16 + ((lane >> 4) << 3) + (lane & 7);
                int c0 = pk * 2 + ((lane >> 3) & 1);
                uint32_t bd = bbase + (uint32_t)(row * 128 +
                                  ((c0 ^ (row & 7)) << 4));
                LDSM_X4(bfr[2 * np][0], bfr[2 * np][1],
                        bfr[2 * np + 1][0], bfr[2 * np + 1][1], bd);
            }
#pragma unroll
            for (int mt = 0; mt < 2; mt++)
#pragma unroll
                for (int nt = 0; nt < 4; nt++)
                    MMA16816(o[mt][nt], af[mt], bfr[nt][0], bfr[nt][1]);
        }
    }

    // Epilogue: normalize by 1/l; write [hi|lo|hi] split directly into g_abig
    const int b = bh >> 4, h = bh & 15;
#pragma unroll
    for (int mt = 0; mt < 2; mt++) {
        int row = wm * 32 + mt * 16 + (lane >> 2);
        float inv0 = 1.0f / l_s[row];
        float inv8 = 1.0f / l_s[row + 8];
#pragma unroll
        for (int nt = 0; nt < 4; nt++) {
            int col = wn * 32 + nt * 8 + (lane & 3) * 2;
            size_t a0 = (size_t)(b * SS + q0 + row) * KBIG + h * HD + col;
            {
                __nv_bfloat162 l2;
                __nv_bfloat162 h2 =
                    split_hi2(o[mt][nt][0] * inv0, o[mt][nt][1] * inv0, l2);
                *reinterpret_cast<__nv_bfloat162*>(&g_abig[a0]) = h2;
                *reinterpret_cast<__nv_bfloat162*>(&g_abig[a0 + DD]) = l2;
                *reinterpret_cast<__nv_bfloat162*>(&g_abig[a0 + 2 * DD]) = h2;
            }
            {
                size_t a8 = a0 + (size_t)8 * KBIG;
                __nv_bfloat162 l2;
                __nv_bfloat162 h2 =
                    split_hi2(o[mt][nt][2] * inv8, o[mt][nt][3] * inv8, l2);
                *reinterpret_cast<__nv_bfloat162*>(&g_abig[a8]) = h2;
                *reinterpret_cast<__nv_bfloat162*>(&g_abig[a8 + DD]) = l2;
                *reinterpret_cast<__nv_bfloat162*>(&g_abig[a8 + 2 * DD]) = h2;
            }
        }
    }
}

// ---------------------------------------------------------------------------
// Launch
// ---------------------------------------------------------------------------
extern "C" void kernel_launch(void* const* d_in, const int* in_sizes, int n_in,
                              void* d_out, int out_size) {
    (void)in_sizes; (void)n_in; (void)out_size;
    const float* x  = (const float*)d_in[0];
    const float* wq = (const float*)d_in[1];
    const float* wk = (const float*)d_in[2];
    const float* wv = (const float*)d_in[3];
    const float* wo = (const float*)d_in[4];
    float* out = (float*)d_out;

    float* qkv;
    __nv_bfloat16 *abig, *wbig;
    cudaGetSymbolAddress((void**)&qkv,  g_qkv);
    cudaGetSymbolAddress((void**)&abig, g_abig);
    cudaGetSymbolAddress((void**)&wbig, g_wbig);

    cudaFuncSetAttribute(gemm_hmma,
                         cudaFuncAttributeMaxDynamicSharedMemorySize,
                         GEMM_SMEM_BYTES);
    cudaFuncSetAttribute(flash_mma_kernel,
                         cudaFuncAttributeMaxDynamicSharedMemorySize,
                         FLASH2_SMEM);

    const int n_act = BS * DD;
    const int n_w   = DD * DD;

    rope_table_kernel<<<(SS * NPAIR + 255) / 256, 256>>>();

    // x -> bf16x3 activation; wq/wk/wv -> stacked weight buffer
    split3_kernel<<<(n_act + 255) / 256, 256>>>(x, abig, n_act, 0);
    split3_kernel<<<(n_w + 255) / 256, 256>>>(wq, wbig, n_w, 1);
    split3_kernel<<<(n_w + 255) / 256, 256>>>(wk, wbig + (size_t)DD * KBIG, n_w, 1);
    split3_kernel<<<(n_w + 255) / 256, 256>>>(wv, wbig + (size_t)2 * DD * KBIG, n_w, 1);

    // Fused QKV projection: [4096, 6144]
    dim3 qkv_grid(KBIG / 128, BS / 128);  // (48, 32)
    gemm_hmma<<<qkv_grid, 256, GEMM_SMEM_BYTES>>>(abig, wbig, qkv, KBIG);

    // RoPE + scale + split (q,k) and transpose + split (v)
    qkv_rope_split_kernel<<<(BS * 1024 + 255) / 256, 256>>>();
    v_split_t_kernel<<<dim3(SS / 64, BB * HH), 256>>>();

    // HMMA flash attention (writes split activations directly)
    flash_mma_kernel<<<dim3(SS / 64, BB * HH), 256, FLASH2_SMEM>>>();

    // Output projection
    split3_kernel<<<(n_w + 255) / 256, 256>>>(wo, wbig, n_w, 1);
    dim3 ogrid(DD / 128, BS / 128);  // (16, 32)
    gemm_hmma<<<ogrid, 256, GEMM_SMEM_BYTES>>>(abig, wbig, out, DD);
}

// round 9
// speedup vs baseline: 1.6713x; 1.0137x over previous
#include <cuda_runtime.h>
#include <cuda_bf16.h>
#include <math.h>
#include <stdint.h>

// Problem constants
#define BB 2
#define SS 2048
#define DD 2048
#define HH 16
#define HD 128
#define BS (BB * SS)        // 4096 tokens
#define NPAIR (HD / 2)      // 64 rope pairs per head
#define KBIG (3 * DD)       // 6144: bf16x3 split-K
#define ITERS (KBIG / 64)   // 96 K-chunks of 64
#define STG 4               // cp.async pipeline stages
#define LOG2E 1.4426950408889634f
#define QK_SCALE 0.08838834764831845f

// ---------------------------------------------------------------------------
// Scratch (device globals -- no allocation allowed in kernel_launch)
// ---------------------------------------------------------------------------
__device__ float g_qkv[(size_t)BS * KBIG];           // fused QKV output [t][q|k|v]
__device__ float g_cos[SS * NPAIR];
__device__ float g_sin[SS * NPAIR];
__device__ __nv_bfloat16 g_abig[(size_t)BS * KBIG];  // activations [hi | lo | hi]
__device__ __nv_bfloat16 g_wbig[(size_t)KBIG * KBIG]; // weights [hi | hi | lo]
// Attention split buffers, [bh][s][d] (q/k) and [bh][d][s] (v transposed)
__device__ __nv_bfloat16 g_qshi[(size_t)BS * DD];
__device__ __nv_bfloat16 g_qslo[(size_t)BS * DD];
__device__ __nv_bfloat16 g_kshi[(size_t)BS * DD];
__device__ __nv_bfloat16 g_kslo[(size_t)BS * DD];
__device__ __nv_bfloat16 g_vthi[(size_t)BS * DD];
__device__ __nv_bfloat16 g_vtlo[(size_t)BS * DD];

// ---------------------------------------------------------------------------
// Helpers
// ---------------------------------------------------------------------------
__device__ __forceinline__ uint32_t smem_u32(const void* p) {
    uint32_t a;
    asm("{ .reg .u64 t; cvta.to.shared.u64 t, %1; cvt.u32.u64 %0, t; }"
        : "=r"(a) : "l"(p));
    return a;
}
#define CP_ASYNC16(smem, gptr) \
    asm volatile("cp.async.cg.shared.global [%0], [%1], 16;" \
                 :: "r"((uint32_t)(smem)), "l"((const void*)(gptr)) : "memory")
#define CP_COMMIT() asm volatile("cp.async.commit_group;" ::: "memory")

#define LDSM_X4(r0, r1, r2, r3, addr) \
    asm volatile("ldmatrix.sync.aligned.m8n8.x4.shared.b16 {%0,%1,%2,%3}, [%4];" \
                 : "=r"(r0), "=r"(r1), "=r"(r2), "=r"(r3) : "r"(addr))

#define MMA16816(d, a, b0, b1) \
    asm volatile("mma.sync.aligned.m16n8k16.row.col.f32.bf16.bf16.f32 " \
                 "{%0,%1,%2,%3}, {%4,%5,%6,%7}, {%8,%9}, {%0,%1,%2,%3};" \
                 : "+f"((d)[0]), "+f"((d)[1]), "+f"((d)[2]), "+f"((d)[3]) \
                 : "r"((a)[0]), "r"((a)[1]), "r"((a)[2]), "r"((a)[3]),   \
                   "r"(b0), "r"(b1))

// Fast exp2 on FMA pipe: t <= 0, clamp at -126; |rel err| ~ 3e-6
__device__ __forceinline__ float exp2_fast(float t) {
    t = fmaxf(t, -126.0f);
    float r = t + 12582912.0f;
    int e = __float_as_int(r) - 0x4B400000;
    float f = t - (r - 12582912.0f);
    float p = 0.0013333558f;
    p = fmaf(p, f, 0.0096181291f);
    p = fmaf(p, f, 0.0555041087f);
    p = fmaf(p, f, 0.2402265070f);
    p = fmaf(p, f, 0.6931471806f);
    p = fmaf(p, f, 1.0f);
    return __int_as_float((e + 127) << 23) * p;
}
__device__ __forceinline__ __nv_bfloat162 split_hi2(float a, float b,
                                                    __nv_bfloat162& lo2) {
    __nv_bfloat16 ha = __float2bfloat16(a);
    __nv_bfloat16 hb = __float2bfloat16(b);
    lo2.x = __float2bfloat16(a - __bfloat162float(ha));
    lo2.y = __float2bfloat16(b - __bfloat162float(hb));
    __nv_bfloat162 hi2; hi2.x = ha; hi2.y = hb;
    return hi2;
}

// ---------------------------------------------------------------------------
// RoPE table (double precision generation)
// ---------------------------------------------------------------------------
__global__ void rope_table_kernel() {
    int idx = blockIdx.x * blockDim.x + threadIdx.x;
    if (idx >= SS * NPAIR) return;
    int s = idx / NPAIR;
    int i = idx - s * NPAIR;
    double freq = (double)s * exp(((double)(-2 * i) / (double)HD) * log(10000.0));
    g_cos[idx] = (float)cos(freq);
    g_sin[idx] = (float)sin(freq);
}

// ---------------------------------------------------------------------------
// bf16x3 split for projection GEMMs
// ---------------------------------------------------------------------------
__global__ void split3_kernel(const float* __restrict__ src,
                              __nv_bfloat16* __restrict__ dst,
                              int n, int mode) {
    int idx = blockIdx.x * blockDim.x + threadIdx.x;
    if (idx >= n) return;
    int r = idx >> 11;
    int c = idx & 2047;
    float v = src[idx];
    __nv_bfloat16 hi = __float2bfloat16(v);
    __nv_bfloat16 lo = __float2bfloat16(v - __bfloat162float(hi));
    size_t base = (size_t)r * KBIG + c;
    if (mode == 0) {
        dst[base] = hi; dst[base + DD] = lo; dst[base + 2 * DD] = hi;
    } else {
        dst[base] = hi; dst[base + DD] = hi; dst[base + 2 * DD] = lo;
    }
}

// ---------------------------------------------------------------------------
// Fused RoPE + scale + bf16 split for q,k straight out of g_qkv.
// ---------------------------------------------------------------------------
__global__ void qkv_rope_split_kernel() {
    int idx = blockIdx.x * blockDim.x + threadIdx.x;
    if (idx >= BS * 1024) return;
    int t = idx >> 10;
    int p = idx & 1023;
    int h = p >> 6;
    int i = p & 63;
    int s = t & (SS - 1);
    int b = t >> 11;
    float c  = g_cos[(s << 6) + i];
    float sn = g_sin[(s << 6) + i];
    size_t src = (size_t)t * KBIG + h * HD + 2 * i;
    float q0 = g_qkv[src],        q1 = g_qkv[src + 1];
    float k0 = g_qkv[src + DD],   k1 = g_qkv[src + DD + 1];
    float qo0 = (q0 * c - q1 * sn) * QK_SCALE;
    float qo1 = (q0 * sn + q1 * c) * QK_SCALE;
    float ko0 = k0 * c - k1 * sn;
    float ko1 = k0 * sn + k1 * c;
    size_t dst = ((size_t)(b * HH + h) * SS + s) * HD + 2 * i;
    __nv_bfloat162 lo2;
    __nv_bfloat162 hi2 = split_hi2(qo0, qo1, lo2);
    *reinterpret_cast<__nv_bfloat162*>(&g_qshi[dst]) = hi2;
    *reinterpret_cast<__nv_bfloat162*>(&g_qslo[dst]) = lo2;
    hi2 = split_hi2(ko0, ko1, lo2);
    *reinterpret_cast<__nv_bfloat162*>(&g_kshi[dst]) = hi2;
    *reinterpret_cast<__nv_bfloat162*>(&g_kslo[dst]) = lo2;
}

// ---------------------------------------------------------------------------
// V transpose+split: g_qkv[t][4096 + h*128 + d] -> g_vthi/lo [bh][d][s]
// ---------------------------------------------------------------------------
__global__ __launch_bounds__(256) void v_split_t_kernel() {
    __shared__ float st[64][129];
    const int s0 = blockIdx.x * 64;
    const int bh = blockIdx.y;
    const int b = bh >> 4, h = bh & 15;
    const float* src = g_qkv + (size_t)(b * SS + s0) * KBIG + 2 * DD + h * HD;
    const int tid = threadIdx.x;
#pragma unroll
    for (int i = 0; i < 32; i++) {
        int id = tid + 256 * i;
        int sl = id >> 7, d = id & 127;
        st[sl][d] = src[(size_t)sl * KBIG + d];
    }
    __syncthreads();
    const int d = tid >> 1, half = tid & 1;
    __nv_bfloat16 hibuf[32], lobuf[32];
#pragma unroll
    for (int j = 0; j < 32; j++) {
        float v = st[half * 32 + j][d];
        __nv_bfloat16 hi = __float2bfloat16(v);
        hibuf[j] = hi;
        lobuf[j] = __float2bfloat16(v - __bfloat162float(hi));
    }
    size_t dst = ((size_t)bh * HD + d) * SS + s0 + half * 32;
    uint4* ph = reinterpret_cast<uint4*>(&g_vthi[dst]);
    uint4* pl = reinterpret_cast<uint4*>(&g_vtlo[dst]);
#pragma unroll
    for (int tch = 0; tch < 4; tch++) {
        ph[tch] = reinterpret_cast<uint4*>(hibuf)[tch];
        pl[tch] = reinterpret_cast<uint4*>(lobuf)[tch];
    }
}

// ---------------------------------------------------------------------------
// HMMA GEMM: C[4096, N] = A[4096,6144] * B[N,6144]^T, ldc = N
// 128x64 CTA tile (8 warps, 4m x 2n, warp tile 32x32), BK=64, 4-stage
// cp.async pipeline, 24KB/stage -> 96KB smem -> 2 CTAs/SM.
// ---------------------------------------------------------------------------
#define TILE_STAGE_BYTES 24576   // A 16KB + B 8KB
#define GEMM_SMEM_BYTES (STG * TILE_STAGE_BYTES)  // 98304

__device__ __forceinline__ void issue_stage(
    uint32_t sb, int s, int tid,
    const __nv_bfloat16* __restrict__ Ag,
    const __nv_bfloat16* __restrict__ Bg)
{
    if (s < ITERS) {
        const int k0 = s * 64;
        const int slot = s & (STG - 1);
        uint32_t abase = sb + slot * TILE_STAGE_BYTES;
        uint32_t bbase = abase + 16384;
#pragma unroll
        for (int i = 0; i < 4; i++) {
            int id = tid + 256 * i;          // 1024 chunks: A 128 rows x 8
            int row = id >> 3;
            int c = id & 7;
            uint32_t off = (uint32_t)(row * 128 + ((c ^ (row & 7)) << 4));
            CP_ASYNC16(abase + off, Ag + (size_t)row * KBIG + k0 + c * 8);
        }
#pragma unroll
        for (int i = 0; i < 2; i++) {
            int id = tid + 256 * i;          // 512 chunks: B 64 rows x 8
            int row = id >> 3;
            int c = id & 7;
            uint32_t off = (uint32_t)(row * 128 + ((c ^ (row & 7)) << 4));
            CP_ASYNC16(bbase + off, Bg + (size_t)row * KBIG + k0 + c * 8);
        }
    }
    CP_COMMIT();
}

__global__ __launch_bounds__(256, 2)
void gemm_hmma(const __nv_bfloat16* __restrict__ A,
               const __nv_bfloat16* __restrict__ Bw,
               float* __restrict__ C, int ldc)
{
    extern __shared__ char smraw[];
    uint32_t sb = smem_u32(smraw);
    const int tid  = threadIdx.x;
    const int lane = tid & 31;
    const int warp = tid >> 5;
    const int wm = warp & 3;        // m quarter (32 rows)
    const int wn = warp >> 2;       // n half (32 cols)
    const int m0 = blockIdx.y * 128;
    const int n0 = blockIdx.x * 64;
    const __nv_bfloat16* Ag = A  + (size_t)m0 * KBIG;
    const __nv_bfloat16* Bg = Bw + (size_t)n0 * KBIG;

    float acc[2][4][4];
#pragma unroll
    for (int a = 0; a < 2; a++)
#pragma unroll
        for (int b = 0; b < 4; b++)
#pragma unroll
            for (int c = 0; c < 4; c++) acc[a][b][c] = 0.f;

    issue_stage(sb, 0, tid, Ag, Bg);
    issue_stage(sb, 1, tid, Ag, Bg);
    issue_stage(sb, 2, tid, Ag, Bg);

    for (int s = 0; s < ITERS; s++) {
        asm volatile("cp.async.wait_group 2;" ::: "memory");
        __syncthreads();
        const int slot = s & (STG - 1);
        uint32_t abase = sb + slot * TILE_STAGE_BYTES;
        uint32_t bbase = abase + 16384;

#pragma unroll
        for (int ks = 0; ks < 4; ks++) {
            uint32_t af[2][4];
            uint32_t bf[4][2];
#pragma unroll
            for (int mt = 0; mt < 2; mt++) {
                int row = wm * 32 + mt * 16 + (lane & 15);
                int ch  = ks * 2 + (lane >> 4);
                uint32_t ad = abase + (uint32_t)(row * 128 +
                                  ((ch ^ (row & 7)) << 4));
                LDSM_X4(af[mt][0], af[mt][1], af[mt][2], af[mt][3], ad);
            }
#pragma unroll
            for (int np = 0; np < 2; np++) {
                int row = wn * 32 + np * 16 + ((lane >> 4) << 3) + (lane & 7);
                int ch  = ks * 2 + ((lane >> 3) & 1);
                uint32_t bd = bbase + (uint32_t)(row * 128 +
                                  ((ch ^ (row & 7)) << 4));
                LDSM_X4(bf[2 * np][0], bf[2 * np][1],
                        bf[2 * np + 1][0], bf[2 * np + 1][1], bd);
            }
#pragma unroll
            for (int mt = 0; mt < 2; mt++)
#pragma unroll
                for (int nt = 0; nt < 4; nt++)
                    MMA16816(acc[mt][nt], af[mt], bf[nt][0], bf[nt][1]);
        }
        issue_stage(sb, s + 3, tid, Ag, Bg);
    }

#pragma unroll
    for (int mt = 0; mt < 2; mt++) {
#pragma unroll
        for (int nt = 0; nt < 4; nt++) {
            int row = m0 + wm * 32 + mt * 16 + (lane >> 2);
            int col = n0 + wn * 32 + nt * 8 + (lane & 3) * 2;
            float2 v0 = make_float2(acc[mt][nt][0], acc[mt][nt][1]);
            float2 v1 = make_float2(acc[mt][nt][2], acc[mt][nt][3]);
            *reinterpret_cast<float2*>(&C[(size_t)row * ldc + col]) = v0;
            *reinterpret_cast<float2*>(&C[(size_t)(row + 8) * ldc + col]) = v1;
        }
    }
}

// ---------------------------------------------------------------------------
// HMMA flash attention, split-precision; epilogue writes [hi|lo|hi] to g_abig
// ---------------------------------------------------------------------------
#define SQHI 0
#define SQLO 16384
#define SKHI 32768
#define SKLO 49152
#define SVHI 65536
#define SVLO 81920
#define SC_   98304           // scores fp32 [64][66]
#define SPHI 115200
#define SPLO 123392
#define SML  131584           // m[64], l[64], alpha[64]
#define FLASH2_SMEM (SML + 768)

__device__ __forceinline__ void issue_qk_tile(
    uint32_t dsthi, uint32_t dstlo,
    const __nv_bfloat16* __restrict__ ghi,
    const __nv_bfloat16* __restrict__ glo, int tid)
{
#pragma unroll
    for (int i = 0; i < 4; i++) {
        int id = tid + 256 * i;
        int row = id >> 4, c = id & 15;
        uint32_t off = (uint32_t)(row * 256 + ((c >> 3) << 7) +
                                  (((c & 7) ^ (row & 7)) << 4));
        CP_ASYNC16(dsthi + off, ghi + (size_t)row * HD + c * 8);
        CP_ASYNC16(dstlo + off, glo + (size_t)row * HD + c * 8);
    }
}
__device__ __forceinline__ void issue_v_tile(
    uint32_t dsthi, uint32_t dstlo,
    const __nv_bfloat16* __restrict__ ghi,
    const __nv_bfloat16* __restrict__ glo, int tid)
{
#pragma unroll
    for (int i = 0; i < 4; i++) {
        int id = tid + 256 * i;
        int row = id >> 3, c = id & 7;
        uint32_t off = (uint32_t)(row * 128 + ((c ^ (row & 7)) << 4));
        CP_ASYNC16(dsthi + off, ghi + (size_t)row * SS + c * 8);
        CP_ASYNC16(dstlo + off, glo + (size_t)row * SS + c * 8);
    }
}

__global__ __launch_bounds__(256, 1) void flash_mma_kernel() {
    extern __shared__ char smr[];
    uint32_t sb = smem_u32(smr);
    const int tid = threadIdx.x, lane = tid & 31, warp = tid >> 5;
    const int wm = warp & 1, wn = warp >> 1;
    const int q0 = blockIdx.x * 64;
    const int bh = blockIdx.y;

    const __nv_bfloat16* qhiG = g_qshi + ((size_t)bh * SS + q0) * HD;
    const __nv_bfloat16* qloG = g_qslo + ((size_t)bh * SS + q0) * HD;
    const __nv_bfloat16* khiB = g_kshi + (size_t)bh * SS * HD;
    const __nv_bfloat16* kloB = g_kslo + (size_t)bh * SS * HD;
    const __nv_bfloat16* vhiB = g_vthi + (size_t)bh * HD * SS;
    const __nv_bfloat16* vloB = g_vtlo + (size_t)bh * HD * SS;

    float* m_s  = reinterpret_cast<float*>(smr + SML);
    float* l_s  = m_s + 64;
    float* al_s = l_s + 64;
    float* SCp  = reinterpret_cast<float*>(smr + SC_);

    issue_qk_tile(sb + SQHI, sb + SQLO, qhiG, qloG, tid);
    CP_COMMIT();
    issue_qk_tile(sb + SKHI, sb + SKLO, khiB, kloB, tid);
    CP_COMMIT();

    if (tid < 64) { m_s[tid] = -1e30f; l_s[tid] = 0.f; }

    float o[2][4][4];
#pragma unroll
    for (int mt = 0; mt < 2; mt++)
#pragma unroll
        for (int nt = 0; nt < 4; nt++)
#pragma unroll
            for (int c = 0; c < 4; c++) o[mt][nt][c] = 0.f;

    for (int t = 0; t < 32; t++) {
        asm volatile("cp.async.wait_group 0;" ::: "memory");
        __syncthreads();
        issue_v_tile(sb + SVHI, sb + SVLO, vhiB + t * 64, vloB + t * 64, tid);
        CP_COMMIT();

        // ---- QK^T: 64x64, k' = 384 ----
        float sc[2][2][4];
#pragma unroll
        for (int mt = 0; mt < 2; mt++)
#pragma unroll
            for (int nt = 0; nt < 2; nt++)
#pragma unroll
                for (int c = 0; c < 4; c++) sc[mt][nt][c] = 0.f;

#pragma unroll
        for (int ks = 0; ks < 24; ks++) {
            const int term = ks >> 3, pk = ks & 7;
            uint32_t abase = sb + ((term == 1) ? SQLO : SQHI);
            uint32_t bbase = sb + ((term == 2) ? SKLO : SKHI);
            uint32_t af[2][4], bfr[2][2];
#pragma unroll
            for (int mt = 0; mt < 2; mt++) {
                int row = wm * 32 + mt * 16 + (lane & 15);
                int c0 = pk * 2 + (lane >> 4);
                uint32_t ad = abase + (uint32_t)(row * 256 + ((c0 >> 3) << 7) +
                                  (((c0 & 7) ^ (row & 7)) << 4));
                LDSM_X4(af[mt][0], af[mt][1], af[mt][2], af[mt][3], ad);
            }
            {
                int row = wn * 16 + ((lane >> 4) << 3) + (lane & 7);
                int c0 = pk * 2 + ((lane >> 3) & 1);
                uint32_t bd = bbase + (uint32_t)(row * 256 + ((c0 >> 3) << 7) +
                                  (((c0 & 7) ^ (row & 7)) << 4));
                LDSM_X4(bfr[0][0], bfr[0][1], bfr[1][0], bfr[1][1], bd);
            }
#pragma unroll
            for (int mt = 0; mt < 2; mt++)
#pragma unroll
                for (int nt = 0; nt < 2; nt++)
                    MMA16816(sc[mt][nt], af[mt], bfr[nt][0], bfr[nt][1]);
        }
#pragma unroll
        for (int mt = 0; mt < 2; mt++)
#pragma unroll
            for (int nt = 0; nt < 2; nt++) {
                int row = wm * 32 + mt * 16 + (lane >> 2);
                int col = wn * 16 + nt * 8 + (lane & 3) * 2;
                *reinterpret_cast<float2*>(&SCp[row * 66 + col]) =
                    make_float2(sc[mt][nt][0], sc[mt][nt][1]);
                *reinterpret_cast<float2*>(&SCp[(row + 8) * 66 + col]) =
                    make_float2(sc[mt][nt][2], sc[mt][nt][3]);
            }
        __syncthreads();

        // ---- online softmax: 4 threads per row ----
        {
            const int r = tid >> 2, part = tid & 3;
            float vals[16];
            float mloc = -1e30f;
#pragma unroll
            for (int j = 0; j < 16; j++) {
                vals[j] = SCp[r * 66 + part * 16 + j];
                mloc = fmaxf(mloc, vals[j]);
            }
            mloc = fmaxf(mloc, __shfl_xor_sync(0xffffffff, mloc, 1));
            mloc = fmaxf(mloc, __shfl_xor_sync(0xffffffff, mloc, 2));
            float mprev = 0.f, mnew = 0.f;
            if (part == 0) {
                mprev = m_s[r];
                mnew = fmaxf(mprev, mloc);
            }
            mnew = __shfl_sync(0xffffffff, mnew, lane & ~3);
            float tsum = 0.f;
#pragma unroll
            for (int j = 0; j < 16; j += 2) {
                float p0 = exp2_fast((vals[j] - mnew) * LOG2E);
                float p1 = exp2_fast((vals[j + 1] - mnew) * LOG2E);
                tsum += p0 + p1;
                __nv_bfloat162 l2;
                __nv_bfloat162 h2 = split_hi2(p0, p1, l2);
                int col = part * 16 + j;
                uint32_t off = (uint32_t)(r * 128 +
                                  (((col >> 3) ^ (r & 7)) << 4) + (col & 7) * 2);
                *reinterpret_cast<__nv_bfloat162*>(smr + SPHI + off) = h2;
                *reinterpret_cast<__nv_bfloat162*>(smr + SPLO + off) = l2;
            }
            tsum += __shfl_xor_sync(0xffffffff, tsum, 1);
            tsum += __shfl_xor_sync(0xffffffff, tsum, 2);
            if (part == 0) {
                float alpha = exp2_fast((mprev - mnew) * LOG2E);
                l_s[r] = l_s[r] * alpha + tsum;
                m_s[r] = mnew;
                al_s[r] = alpha;
            }
        }
        __syncthreads();

        if (t + 1 < 32)
            issue_qk_tile(sb + SKHI, sb + SKLO,
                          khiB + (size_t)(t + 1) * 64 * HD,
                          kloB + (size_t)(t + 1) * 64 * HD, tid);
        CP_COMMIT();
        asm volatile("cp.async.wait_group 1;" ::: "memory");
        __syncthreads();

        // ---- rescale O, then PV: 64x128, j' = 192 ----
#pragma unroll
        for (int mt = 0; mt < 2; mt++) {
            float a0 = al_s[wm * 32 + mt * 16 + (lane >> 2)];
            float a8 = al_s[wm * 32 + mt * 16 + (lane >> 2) + 8];
#pragma unroll
            for (int nt = 0; nt < 4; nt++) {
                o[mt][nt][0] *= a0; o[mt][nt][1] *= a0;
                o[mt][nt][2] *= a8; o[mt][nt][3] *= a8;
            }
        }
#pragma unroll
        for (int ks = 0; ks < 12; ks++) {
            const int term = ks >> 2, pk = ks & 3;
            uint32_t abase = sb + ((term == 1) ? SPLO : SPHI);
            uint32_t bbase = sb + ((term == 2) ? SVLO : SVHI);
            uint32_t af[2][4], bfr[4][2];
#pragma unroll
            for (int mt = 0; mt < 2; mt++) {
                int row = wm * 32 + mt * 16 + (lane & 15);
                int c0 = pk * 2 + (lane >> 4);
                uint32_t ad = abase + (uint32_t)(row * 128 +
                                  ((c0 ^ (row & 7)) << 4));
                LDSM_X4(af[mt][0], af[mt][1], af[mt][2], af[mt][3], ad);
            }
#pragma unroll
            for (int np = 0; np < 2; np++) {
                int row = wn * 32 + np * 16 + ((lane >> 4) << 3) + (lane & 7);
                int c0 = pk * 2 + ((lane >> 3) & 1);
                uint32_t bd = bbase + (uint32_t)(row * 128 +
                                  ((c0 ^ (row & 7)) << 4));
                LDSM_X4(bfr[2 * np][0], bfr[2 * np][1],
                        bfr[2 * np + 1][0], bfr[2 * np + 1][1], bd);
            }
#pragma unroll
            for (int mt = 0; mt < 2; mt++)
#pragma unroll
                for (int nt = 0; nt < 4; nt++)
                    MMA16816(o[mt][nt], af[mt], bfr[nt][0], bfr[nt][1]);
        }
    }

    // Epilogue: normalize by 1/l; write [hi|lo|hi] split directly into g_abig
    const int b = bh >> 4, h = bh & 15;
#pragma unroll
    for (int mt = 0; mt < 2; mt++) {
        int row = wm * 32 + mt * 16 + (lane >> 2);
        float inv0 = 1.0f / l_s[row];
        float inv8 = 1.0f / l_s[row + 8];
#pragma unroll
        for (int nt = 0; nt < 4; nt++) {
            int col = wn * 32 + nt * 8 + (lane & 3) * 2;
            size_t a0 = (size_t)(b * SS + q0 + row) * KBIG + h * HD + col;
            {
                __nv_bfloat162 l2;
                __nv_bfloat162 h2 =
                    split_hi2(o[mt][nt][0] * inv0, o[mt][nt][1] * inv0, l2);
                *reinterpret_cast<__nv_bfloat162*>(&g_abig[a0]) = h2;
                *reinterpret_cast<__nv_bfloat162*>(&g_abig[a0 + DD]) = l2;
                *reinterpret_cast<__nv_bfloat162*>(&g_abig[a0 + 2 * DD]) = h2;
            }
            {
                size_t a8 = a0 + (size_t)8 * KBIG;
                __nv_bfloat162 l2;
                __nv_bfloat162 h2 =
                    split_hi2(o[mt][nt][2] * inv8, o[mt][nt][3] * inv8, l2);
                *reinterpret_cast<__nv_bfloat162*>(&g_abig[a8]) = h2;
                *reinterpret_cast<__nv_bfloat162*>(&g_abig[a8 + DD]) = l2;
                *reinterpret_cast<__nv_bfloat162*>(&g_abig[a8 + 2 * DD]) = h2;
            }
        }
    }
}

// ---------------------------------------------------------------------------
// Launch
// ---------------------------------------------------------------------------
extern "C" void kernel_launch(void* const* d_in, const int* in_sizes, int n_in,
                              void* d_out, int out_size) {
    (void)in_sizes; (void)n_in; (void)out_size;
    const float* x  = (const float*)d_in[0];
    const float* wq = (const float*)d_in[1];
    const float* wk = (const float*)d_in[2];
    const float* wv = (const float*)d_in[3];
    const float* wo = (const float*)d_in[4];
    float* out = (float*)d_out;

    float* qkv;
    __nv_bfloat16 *abig, *wbig;
    cudaGetSymbolAddress((void**)&qkv,  g_qkv);
    cudaGetSymbolAddress((void**)&abig, g_abig);
    cudaGetSymbolAddress((void**)&wbig, g_wbig);

    cudaFuncSetAttribute(gemm_hmma,
                         cudaFuncAttributeMaxDynamicSharedMemorySize,
                         GEMM_SMEM_BYTES);
    cudaFuncSetAttribute(flash_mma_kernel,
                         cudaFuncAttributeMaxDynamicSharedMemorySize,
                         FLASH2_SMEM);

    const int n_act = BS * DD;
    const int n_w   = DD * DD;

    rope_table_kernel<<<(SS * NPAIR + 255) / 256, 256>>>();

    // x -> bf16x3 activation; wq/wk/wv -> stacked weight buffer
    split3_kernel<<<(n_act + 255) / 256, 256>>>(x, abig, n_act, 0);
    split3_kernel<<<(n_w + 255) / 256, 256>>>(wq, wbig, n_w, 1);
    split3_kernel<<<(n_w + 255) / 256, 256>>>(wk, wbig + (size_t)DD * KBIG, n_w, 1);
    split3_kernel<<<(n_w + 255) / 256, 256>>>(wv, wbig + (size_t)2 * DD * KBIG, n_w, 1);

    // Fused QKV projection: [4096, 6144]
    dim3 qkv_grid(KBIG / 64, BS / 128);  // (96, 32)
    gemm_hmma<<<qkv_grid, 256, GEMM_SMEM_BYTES>>>(abig, wbig, qkv, KBIG);

    // RoPE + scale + split (q,k) and transpose + split (v)
    qkv_rope_split_kernel<<<(BS * 1024 + 255) / 256, 256>>>();
    v_split_t_kernel<<<dim3(SS / 64, BB * HH), 256>>>();

    // HMMA flash attention (writes split activations directly)
    flash_mma_kernel<<<dim3(SS / 64, BB * HH), 256, FLASH2_SMEM>>>();

    // Output projection
    split3_kernel<<<(n_w + 255) / 256, 256>>>(wo, wbig, n_w, 1);
    dim3 ogrid(DD / 64, BS / 128);  // (32, 32)
    gemm_hmma<<<ogrid, 256, GEMM_SMEM_BYTES>>>(abig, wbig, out, DD);
}

// round 10
// speedup vs baseline: 1.7685x; 1.0581x over previous
#include <cuda_runtime.h>
#include <cuda_bf16.h>
#include <math.h>
#include <stdint.h>

// Problem constants
#define BB 2
#define SS 2048
#define DD 2048
#define HH 16
#define HD 128
#define BS (BB * SS)        // 4096 tokens
#define NPAIR (HD / 2)      // 64 rope pairs per head
#define KBIG (3 * DD)       // 6144: bf16x3 split-K
#define ITERS (KBIG / 64)   // 96 K-chunks of 64
#define STG 4               // cp.async pipeline stages
#define LOG2E 1.4426950408889634f
#define QK_SCALE 0.08838834764831845f

// ---------------------------------------------------------------------------
// Scratch (device globals -- no allocation allowed in kernel_launch)
// ---------------------------------------------------------------------------
__device__ float g_qkv[(size_t)BS * KBIG];           // fused QKV output [t][q|k|v]
__device__ float g_cos[SS * NPAIR];
__device__ float g_sin[SS * NPAIR];
__device__ __nv_bfloat16 g_abig[(size_t)BS * KBIG];  // activations [hi | lo | hi]
__device__ __nv_bfloat16 g_wbig[(size_t)KBIG * KBIG]; // weights [hi | hi | lo]
// Attention split buffers, [bh][s][d] (q/k) and [bh][d][s] (v transposed)
__device__ __nv_bfloat16 g_qshi[(size_t)BS * DD];
__device__ __nv_bfloat16 g_qslo[(size_t)BS * DD];
__device__ __nv_bfloat16 g_kshi[(size_t)BS * DD];
__device__ __nv_bfloat16 g_kslo[(size_t)BS * DD];
__device__ __nv_bfloat16 g_vthi[(size_t)BS * DD];
__device__ __nv_bfloat16 g_vtlo[(size_t)BS * DD];

// ---------------------------------------------------------------------------
// Helpers
// ---------------------------------------------------------------------------
__device__ __forceinline__ uint32_t smem_u32(const void* p) {
    uint32_t a;
    asm("{ .reg .u64 t; cvta.to.shared.u64 t, %1; cvt.u32.u64 %0, t; }"
        : "=r"(a) : "l"(p));
    return a;
}
#define CP_ASYNC16(smem, gptr) \
    asm volatile("cp.async.cg.shared.global [%0], [%1], 16;" \
                 :: "r"((uint32_t)(smem)), "l"((const void*)(gptr)) : "memory")
#define CP_COMMIT() asm volatile("cp.async.commit_group;" ::: "memory")

#define LDSM_X4(r0, r1, r2, r3, addr) \
    asm volatile("ldmatrix.sync.aligned.m8n8.x4.shared.b16 {%0,%1,%2,%3}, [%4];" \
                 : "=r"(r0), "=r"(r1), "=r"(r2), "=r"(r3) : "r"(addr))

#define MMA16816(d, a, b0, b1) \
    asm volatile("mma.sync.aligned.m16n8k16.row.col.f32.bf16.bf16.f32 " \
                 "{%0,%1,%2,%3}, {%4,%5,%6,%7}, {%8,%9}, {%0,%1,%2,%3};" \
                 : "+f"((d)[0]), "+f"((d)[1]), "+f"((d)[2]), "+f"((d)[3]) \
                 : "r"((a)[0]), "r"((a)[1]), "r"((a)[2]), "r"((a)[3]),   \
                   "r"(b0), "r"(b1))

// Fast exp2 on FMA pipe: t <= 0, clamp at -126; |rel err| ~ 3e-6
__device__ __forceinline__ float exp2_fast(float t) {
    t = fmaxf(t, -126.0f);
    float r = t + 12582912.0f;
    int e = __float_as_int(r) - 0x4B400000;
    float f = t - (r - 12582912.0f);
    float p = 0.0013333558f;
    p = fmaf(p, f, 0.0096181291f);
    p = fmaf(p, f, 0.0555041087f);
    p = fmaf(p, f, 0.2402265070f);
    p = fmaf(p, f, 0.6931471806f);
    p = fmaf(p, f, 1.0f);
    return __int_as_float((e + 127) << 23) * p;
}
__device__ __forceinline__ __nv_bfloat162 split_hi2(float a, float b,
                                                    __nv_bfloat162& lo2) {
    __nv_bfloat16 ha = __float2bfloat16(a);
    __nv_bfloat16 hb = __float2bfloat16(b);
    lo2.x = __float2bfloat16(a - __bfloat162float(ha));
    lo2.y = __float2bfloat16(b - __bfloat162float(hb));
    __nv_bfloat162 hi2; hi2.x = ha; hi2.y = hb;
    return hi2;
}
// Split two floats into packed bf16 hi and lo words (low half = first arg)
__device__ __forceinline__ void split_pack(float a, float b,
                                           uint32_t& hi, uint32_t& lo) {
    __nv_bfloat162 l2;
    __nv_bfloat162 h2 = split_hi2(a, b, l2);
    hi = *reinterpret_cast<uint32_t*>(&h2);
    lo = *reinterpret_cast<uint32_t*>(&l2);
}

// ---------------------------------------------------------------------------
// RoPE table (double precision generation)
// ---------------------------------------------------------------------------
__global__ void rope_table_kernel() {
    int idx = blockIdx.x * blockDim.x + threadIdx.x;
    if (idx >= SS * NPAIR) return;
    int s = idx / NPAIR;
    int i = idx - s * NPAIR;
    double freq = (double)s * exp(((double)(-2 * i) / (double)HD) * log(10000.0));
    g_cos[idx] = (float)cos(freq);
    g_sin[idx] = (float)sin(freq);
}

// ---------------------------------------------------------------------------
// bf16x3 split for projection GEMMs
// ---------------------------------------------------------------------------
__global__ void split3_kernel(const float* __restrict__ src,
                              __nv_bfloat16* __restrict__ dst,
                              int n, int mode) {
    int idx = blockIdx.x * blockDim.x + threadIdx.x;
    if (idx >= n) return;
    int r = idx >> 11;
    int c = idx & 2047;
    float v = src[idx];
    __nv_bfloat16 hi = __float2bfloat16(v);
    __nv_bfloat16 lo = __float2bfloat16(v - __bfloat162float(hi));
    size_t base = (size_t)r * KBIG + c;
    if (mode == 0) {
        dst[base] = hi; dst[base + DD] = lo; dst[base + 2 * DD] = hi;
    } else {
        dst[base] = hi; dst[base + DD] = hi; dst[base + 2 * DD] = lo;
    }
}

// ---------------------------------------------------------------------------
// Fused RoPE + scale + bf16 split for q,k straight out of g_qkv.
// ---------------------------------------------------------------------------
__global__ void qkv_rope_split_kernel() {
    int idx = blockIdx.x * blockDim.x + threadIdx.x;
    if (idx >= BS * 1024) return;
    int t = idx >> 10;
    int p = idx & 1023;
    int h = p >> 6;
    int i = p & 63;
    int s = t & (SS - 1);
    int b = t >> 11;
    float c  = g_cos[(s << 6) + i];
    float sn = g_sin[(s << 6) + i];
    size_t src = (size_t)t * KBIG + h * HD + 2 * i;
    float q0 = g_qkv[src],        q1 = g_qkv[src + 1];
    float k0 = g_qkv[src + DD],   k1 = g_qkv[src + DD + 1];
    float qo0 = (q0 * c - q1 * sn) * QK_SCALE;
    float qo1 = (q0 * sn + q1 * c) * QK_SCALE;
    float ko0 = k0 * c - k1 * sn;
    float ko1 = k0 * sn + k1 * c;
    size_t dst = ((size_t)(b * HH + h) * SS + s) * HD + 2 * i;
    __nv_bfloat162 lo2;
    __nv_bfloat162 hi2 = split_hi2(qo0, qo1, lo2);
    *reinterpret_cast<__nv_bfloat162*>(&g_qshi[dst]) = hi2;
    *reinterpret_cast<__nv_bfloat162*>(&g_qslo[dst]) = lo2;
    hi2 = split_hi2(ko0, ko1, lo2);
    *reinterpret_cast<__nv_bfloat162*>(&g_kshi[dst]) = hi2;
    *reinterpret_cast<__nv_bfloat162*>(&g_kslo[dst]) = lo2;
}

// ---------------------------------------------------------------------------
// V transpose+split: g_qkv[t][4096 + h*128 + d] -> g_vthi/lo [bh][d][s]
// ---------------------------------------------------------------------------
__global__ __launch_bounds__(256) void v_split_t_kernel() {
    __shared__ float st[64][129];
    const int s0 = blockIdx.x * 64;
    const int bh = blockIdx.y;
    const int b = bh >> 4, h = bh & 15;
    const float* src = g_qkv + (size_t)(b * SS + s0) * KBIG + 2 * DD + h * HD;
    const int tid = threadIdx.x;
#pragma unroll
    for (int i = 0; i < 32; i++) {
        int id = tid + 256 * i;
        int sl = id >> 7, d = id & 127;
        st[sl][d] = src[(size_t)sl * KBIG + d];
    }
    __syncthreads();
    const int d = tid >> 1, half = tid & 1;
    __nv_bfloat16 hibuf[32], lobuf[32];
#pragma unroll
    for (int j = 0; j < 32; j++) {
        float v = st[half * 32 + j][d];
        __nv_bfloat16 hi = __float2bfloat16(v);
        hibuf[j] = hi;
        lobuf[j] = __float2bfloat16(v - __bfloat162float(hi));
    }
    size_t dst = ((size_t)bh * HD + d) * SS + s0 + half * 32;
    uint4* ph = reinterpret_cast<uint4*>(&g_vthi[dst]);
    uint4* pl = reinterpret_cast<uint4*>(&g_vtlo[dst]);
#pragma unroll
    for (int tch = 0; tch < 4; tch++) {
        ph[tch] = reinterpret_cast<uint4*>(hibuf)[tch];
        pl[tch] = reinterpret_cast<uint4*>(lobuf)[tch];
    }
}

// ---------------------------------------------------------------------------
// HMMA GEMM: C[4096, N] = A[4096,6144] * B[N,6144]^T, ldc = N
// 128x64 CTA tile (8 warps, 4m x 2n), BK=64, 4-stage cp.async pipeline.
// ---------------------------------------------------------------------------
#define TILE_STAGE_BYTES 24576   // A 16KB + B 8KB
#define GEMM_SMEM_BYTES (STG * TILE_STAGE_BYTES)  // 98304

__device__ __forceinline__ void issue_stage(
    uint32_t sb, int s, int tid,
    const __nv_bfloat16* __restrict__ Ag,
    const __nv_bfloat16* __restrict__ Bg)
{
    if (s < ITERS) {
        const int k0 = s * 64;
        const int slot = s & (STG - 1);
        uint32_t abase = sb + slot * TILE_STAGE_BYTES;
        uint32_t bbase = abase + 16384;
#pragma unroll
        for (int i = 0; i < 4; i++) {
            int id = tid + 256 * i;
            int row = id >> 3;
            int c = id & 7;
            uint32_t off = (uint32_t)(row * 128 + ((c ^ (row & 7)) << 4));
            CP_ASYNC16(abase + off, Ag + (size_t)row * KBIG + k0 + c * 8);
        }
#pragma unroll
        for (int i = 0; i < 2; i++) {
            int id = tid + 256 * i;
            int row = id >> 3;
            int c = id & 7;
            uint32_t off = (uint32_t)(row * 128 + ((c ^ (row & 7)) << 4));
            CP_ASYNC16(bbase + off, Bg + (size_t)row * KBIG + k0 + c * 8);
        }
    }
    CP_COMMIT();
}

__global__ __launch_bounds__(256, 2)
void gemm_hmma(const __nv_bfloat16* __restrict__ A,
               const __nv_bfloat16* __restrict__ Bw,
               float* __restrict__ C, int ldc)
{
    extern __shared__ char smraw[];
    uint32_t sb = smem_u32(smraw);
    const int tid  = threadIdx.x;
    const int lane = tid & 31;
    const int warp = tid >> 5;
    const int wm = warp & 3;
    const int wn = warp >> 2;
    const int m0 = blockIdx.y * 128;
    const int n0 = blockIdx.x * 64;
    const __nv_bfloat16* Ag = A  + (size_t)m0 * KBIG;
    const __nv_bfloat16* Bg = Bw + (size_t)n0 * KBIG;

    float acc[2][4][4];
#pragma unroll
    for (int a = 0; a < 2; a++)
#pragma unroll
        for (int b = 0; b < 4; b++)
#pragma unroll
            for (int c = 0; c < 4; c++) acc[a][b][c] = 0.f;

    issue_stage(sb, 0, tid, Ag, Bg);
    issue_stage(sb, 1, tid, Ag, Bg);
    issue_stage(sb, 2, tid, Ag, Bg);

    for (int s = 0; s < ITERS; s++) {
        asm volatile("cp.async.wait_group 2;" ::: "memory");
        __syncthreads();
        const int slot = s & (STG - 1);
        uint32_t abase = sb + slot * TILE_STAGE_BYTES;
        uint32_t bbase = abase + 16384;

#pragma unroll
        for (int ks = 0; ks < 4; ks++) {
            uint32_t af[2][4];
            uint32_t bf[4][2];
#pragma unroll
            for (int mt = 0; mt < 2; mt++) {
                int row = wm * 32 + mt * 16 + (lane & 15);
                int ch  = ks * 2 + (lane >> 4);
                uint32_t ad = abase + (uint32_t)(row * 128 +
                                  ((ch ^ (row & 7)) << 4));
                LDSM_X4(af[mt][0], af[mt][1], af[mt][2], af[mt][3], ad);
            }
#pragma unroll
            for (int np = 0; np < 2; np++) {
                int row = wn * 32 + np * 16 + ((lane >> 4) << 3) + (lane & 7);
                int ch  = ks * 2 + ((lane >> 3) & 1);
                uint32_t bd = bbase + (uint32_t)(row * 128 +
                                  ((ch ^ (row & 7)) << 4));
                LDSM_X4(bf[2 * np][0], bf[2 * np][1],
                        bf[2 * np + 1][0], bf[2 * np + 1][1], bd);
            }
#pragma unroll
            for (int mt = 0; mt < 2; mt++)
#pragma unroll
                for (int nt = 0; nt < 4; nt++)
                    MMA16816(acc[mt][nt], af[mt], bf[nt][0], bf[nt][1]);
        }
        issue_stage(sb, s + 3, tid, Ag, Bg);
    }

#pragma unroll
    for (int mt = 0; mt < 2; mt++) {
#pragma unroll
        for (int nt = 0; nt < 4; nt++) {
            int row = m0 + wm * 32 + mt * 16 + (lane >> 2);
            int col = n0 + wn * 32 + nt * 8 + (lane & 3) * 2;
            float2 v0 = make_float2(acc[mt][nt][0], acc[mt][nt][1]);
            float2 v1 = make_float2(acc[mt][nt][2], acc[mt][nt][3]);
            *reinterpret_cast<float2*>(&C[(size_t)row * ldc + col]) = v0;
            *reinterpret_cast<float2*>(&C[(size_t)(row + 8) * ldc + col]) = v1;
        }
    }
}

// ---------------------------------------------------------------------------
// FA2-style HMMA flash attention: Q-tile 128, 8 warps x 16 rows each.
// Scores/softmax/P entirely in registers; P accum layout == PV A-frag layout.
// smem: Q hi/lo (2x32KB) + K hi/lo (2x16KB) + V hi/lo (2x16KB) = 128KB.
// ---------------------------------------------------------------------------
#define SQHI 0
#define SQLO 32768
#define SKHI 65536
#define SKLO 81920
#define SVHI 98304
#define SVLO 114688
#define FLASH3_SMEM 131072

// Q tile: 128 rows x 128 bf16 (256B rows, swizzled), hi+lo
__device__ __forceinline__ void issue_q_tile(
    uint32_t sb, const __nv_bfloat16* __restrict__ ghi,
    const __nv_bfloat16* __restrict__ glo, int tid)
{
#pragma unroll
    for (int i = 0; i < 8; i++) {
        int id = tid + 256 * i;
        int row = id >> 4, c = id & 15;
        uint32_t off = (uint32_t)(row * 256 + ((c >> 3) << 7) +
                                  (((c & 7) ^ (row & 7)) << 4));
        CP_ASYNC16(sb + SQHI + off, ghi + (size_t)row * HD + c * 8);
        CP_ASYNC16(sb + SQLO + off, glo + (size_t)row * HD + c * 8);
    }
}
// K tile: 64 rows x 128 bf16 (256B rows, swizzled), hi+lo
__device__ __forceinline__ void issue_k_tile(
    uint32_t sb, const __nv_bfloat16* __restrict__ ghi,
    const __nv_bfloat16* __restrict__ glo, int tid)
{
#pragma unroll
    for (int i = 0; i < 4; i++) {
        int id = tid + 256 * i;
        int row = id >> 4, c = id & 15;
        uint32_t off = (uint32_t)(row * 256 + ((c >> 3) << 7) +
                                  (((c & 7) ^ (row & 7)) << 4));
        CP_ASYNC16(sb + SKHI + off, ghi + (size_t)row * HD + c * 8);
        CP_ASYNC16(sb + SKLO + off, glo + (size_t)row * HD + c * 8);
    }
}
// V^T tile: 128 rows(d) x 64 bf16 (128B rows, swizzled); row stride SS
__device__ __forceinline__ void issue_v_tile(
    uint32_t sb, const __nv_bfloat16* __restrict__ ghi,
    const __nv_bfloat16* __restrict__ glo, int tid)
{
#pragma unroll
    for (int i = 0; i < 4; i++) {
        int id = tid + 256 * i;
        int row = id >> 3, c = id & 7;
        uint32_t off = (uint32_t)(row * 128 + ((c ^ (row & 7)) << 4));
        CP_ASYNC16(sb + SVHI + off, ghi + (size_t)row * SS + c * 8);
        CP_ASYNC16(sb + SVLO + off, glo + (size_t)row * SS + c * 8);
    }
}

__global__ __launch_bounds__(256, 1) void flash_mma_kernel() {
    extern __shared__ char smr[];
    uint32_t sb = smem_u32(smr);
    const int tid = threadIdx.x, lane = tid & 31, warp = tid >> 5;
    const int q0 = blockIdx.x * 128;
    const int bh = blockIdx.y;

    const __nv_bfloat16* qhiG = g_qshi + ((size_t)bh * SS + q0) * HD;
    const __nv_bfloat16* qloG = g_qslo + ((size_t)bh * SS + q0) * HD;
    const __nv_bfloat16* khiB = g_kshi + (size_t)bh * SS * HD;
    const __nv_bfloat16* kloB = g_kslo + (size_t)bh * SS * HD;
    const __nv_bfloat16* vhiB = g_vthi + (size_t)bh * HD * SS;
    const __nv_bfloat16* vloB = g_vtlo + (size_t)bh * HD * SS;

    issue_q_tile(sb, qhiG, qloG, tid);
    CP_COMMIT();
    issue_k_tile(sb, khiB, kloB, tid);
    CP_COMMIT();

    // Row state in registers: this thread's rows are (warp*16 + lane/4) and +8
    float m0v = -1e30f, m8v = -1e30f, l0 = 0.f, l8 = 0.f;
    float o[16][4];
#pragma unroll
    for (int nt = 0; nt < 16; nt++)
#pragma unroll
        for (int c = 0; c < 4; c++) o[nt][c] = 0.f;

    for (int t = 0; t < 32; t++) {
        asm volatile("cp.async.wait_group 0;" ::: "memory");
        __syncthreads();
        issue_v_tile(sb, vhiB + t * 64, vloB + t * 64, tid);
        CP_COMMIT();

        // ---- QK^T: warp rows 16 x keys 64, k' = 384 ----
        float sc[8][4];
#pragma unroll
        for (int nt = 0; nt < 8; nt++)
#pragma unroll
            for (int c = 0; c < 4; c++) sc[nt][c] = 0.f;

#pragma unroll
        for (int ks = 0; ks < 24; ks++) {
            const int term = ks >> 3, pk = ks & 7;
            uint32_t abase = sb + ((term == 1) ? SQLO : SQHI);
            uint32_t bbase = sb + ((term == 2) ? SKLO : SKHI);
            uint32_t af[4], bfr[8][2];
            {
                int row = warp * 16 + (lane & 15);
                int c0 = pk * 2 + (lane >> 4);
                uint32_t ad = abase + (uint32_t)(row * 256 + ((c0 >> 3) << 7) +
                                  (((c0 & 7) ^ (row & 7)) << 4));
                LDSM_X4(af[0], af[1], af[2], af[3], ad);
            }
#pragma unroll
            for (int np = 0; np < 4; np++) {
                int row = np * 16 + ((lane >> 4) << 3) + (lane & 7);
                int c0 = pk * 2 + ((lane >> 3) & 1);
                uint32_t bd = bbase + (uint32_t)(row * 256 + ((c0 >> 3) << 7) +
                                  (((c0 & 7) ^ (row & 7)) << 4));
                LDSM_X4(bfr[2 * np][0], bfr[2 * np][1],
                        bfr[2 * np + 1][0], bfr[2 * np + 1][1], bd);
            }
#pragma unroll
            for (int nt = 0; nt < 8; nt++)
                MMA16816(sc[nt], af, bfr[nt][0], bfr[nt][1]);
        }

        // ---- in-register online softmax (quad-only reductions) ----
        float mx0 = -1e30f, mx8 = -1e30f;
#pragma unroll
        for (int nt = 0; nt < 8; nt++) {
            mx0 = fmaxf(mx0, fmaxf(sc[nt][0], sc[nt][1]));
            mx8 = fmaxf(mx8, fmaxf(sc[nt][2], sc[nt][3]));
        }
        mx0 = fmaxf(mx0, __shfl_xor_sync(0xffffffff, mx0, 1));
        mx0 = fmaxf(mx0, __shfl_xor_sync(0xffffffff, mx0, 2));
        mx8 = fmaxf(mx8, __shfl_xor_sync(0xffffffff, mx8, 1));
        mx8 = fmaxf(mx8, __shfl_xor_sync(0xffffffff, mx8, 2));
        float mn0 = fmaxf(m0v, mx0), mn8 = fmaxf(m8v, mx8);
        float al0 = exp2_fast((m0v - mn0) * LOG2E);
        float al8 = exp2_fast((m8v - mn8) * LOG2E);
        float s0 = 0.f, s8 = 0.f;
#pragma unroll
        for (int nt = 0; nt < 8; nt++) {
            float p0 = exp2_fast((sc[nt][0] - mn0) * LOG2E);
            float p1 = exp2_fast((sc[nt][1] - mn0) * LOG2E);
            float p2 = exp2_fast((sc[nt][2] - mn8) * LOG2E);
            float p3 = exp2_fast((sc[nt][3] - mn8) * LOG2E);
            sc[nt][0] = p0; sc[nt][1] = p1; sc[nt][2] = p2; sc[nt][3] = p3;
            s0 += p0 + p1; s8 += p2 + p3;
        }
        s0 += __shfl_xor_sync(0xffffffff, s0, 1);
        s0 += __shfl_xor_sync(0xffffffff, s0, 2);
        s8 += __shfl_xor_sync(0xffffffff, s8, 1);
        s8 += __shfl_xor_sync(0xffffffff, s8, 2);
        l0 = l0 * al0 + s0; m0v = mn0;
        l8 = l8 * al8 + s8; m8v = mn8;

        // Pack P hi/lo into PV A-fragments (accum layout == A-frag layout)
        uint32_t pHI[4][4], pLO[4][4];
#pragma unroll
        for (int kc = 0; kc < 4; kc++) {
            split_pack(sc[2 * kc][0],     sc[2 * kc][1],     pHI[kc][0], pLO[kc][0]);
            split_pack(sc[2 * kc][2],     sc[2 * kc][3],     pHI[kc][1], pLO[kc][1]);
            split_pack(sc[2 * kc + 1][0], sc[2 * kc + 1][1], pHI[kc][2], pLO[kc][2]);
            split_pack(sc[2 * kc + 1][2], sc[2 * kc + 1][3], pHI[kc][3], pLO[kc][3]);
        }

        // Rescale O
#pragma unroll
        for (int nt = 0; nt < 16; nt++) {
            o[nt][0] *= al0; o[nt][1] *= al0;
            o[nt][2] *= al8; o[nt][3] *= al8;
        }

        __syncthreads();  // all warps done reading K smem
        if (t + 1 < 32)
            issue_k_tile(sb, khiB + (size_t)(t + 1) * 64 * HD,
                         kloB + (size_t)(t + 1) * 64 * HD, tid);
        CP_COMMIT();
        asm volatile("cp.async.wait_group 1;" ::: "memory");  // V(t) ready
        __syncthreads();

        // ---- PV: rows 16 x d 128, j' = 192, A from registers ----
#pragma unroll
        for (int ks = 0; ks < 12; ks++) {
            const int term = ks >> 2, kc = ks & 3;
            const uint32_t* afr = (term == 1) ? pLO[kc] : pHI[kc];
            uint32_t bbase = sb + ((term == 2) ? SVLO : SVHI);
            const int ch = kc * 2 + ((lane >> 3) & 1);
#pragma unroll
            for (int half = 0; half < 2; half++) {
                uint32_t bfr[8][2];
#pragma unroll
                for (int np = 0; np < 4; np++) {
                    int row = half * 64 + np * 16 +
                              ((lane >> 4) << 3) + (lane & 7);
                    uint32_t bd = bbase + (uint32_t)(row * 128 +
                                      ((ch ^ (row & 7)) << 4));
                    LDSM_X4(bfr[2 * np][0], bfr[2 * np][1],
                            bfr[2 * np + 1][0], bfr[2 * np + 1][1], bd);
                }
#pragma unroll
                for (int i = 0; i < 8; i++)
                    MMA16816(o[half * 8 + i], afr, bfr[i][0], bfr[i][1]);
            }
        }
    }

    // Epilogue: normalize; write [hi|lo|hi] split directly into g_abig
    const int b = bh >> 4, h = bh & 15;
    const int row = warp * 16 + (lane >> 2);
    float inv0 = 1.0f / l0;
    float inv8 = 1.0f / l8;
#pragma unroll
    for (int nt = 0; nt < 16; nt++) {
        int col = nt * 8 + (lane & 3) * 2;
        size_t a0 = (size_t)(b * SS + q0 + row) * KBIG + h * HD + col;
        {
            __nv_bfloat162 l2;
            __nv_bfloat162 h2 = split_hi2(o[nt][0] * inv0, o[nt][1] * inv0, l2);
            *reinterpret_cast<__nv_bfloat162*>(&g_abig[a0]) = h2;
            *reinterpret_cast<__nv_bfloat162*>(&g_abig[a0 + DD]) = l2;
            *reinterpret_cast<__nv_bfloat162*>(&g_abig[a0 + 2 * DD]) = h2;
        }
        {
            size_t a8 = a0 + (size_t)8 * KBIG;
            __nv_bfloat162 l2;
            __nv_bfloat162 h2 = split_hi2(o[nt][2] * inv8, o[nt][3] * inv8, l2);
            *reinterpret_cast<__nv_bfloat162*>(&g_abig[a8]) = h2;
            *reinterpret_cast<__nv_bfloat162*>(&g_abig[a8 + DD]) = l2;
            *reinterpret_cast<__nv_bfloat162*>(&g_abig[a8 + 2 * DD]) = h2;
        }
    }
}

// ---------------------------------------------------------------------------
// Launch
// ---------------------------------------------------------------------------
extern "C" void kernel_launch(void* const* d_in, const int* in_sizes, int n_in,
                              void* d_out, int out_size) {
    (void)in_sizes; (void)n_in; (void)out_size;
    const float* x  = (const float*)d_in[0];
    const float* wq = (const float*)d_in[1];
    const float* wk = (const float*)d_in[2];
    const float* wv = (const float*)d_in[3];
    const float* wo = (const float*)d_in[4];
    float* out = (float*)d_out;

    float* qkv;
    __nv_bfloat16 *abig, *wbig;
    cudaGetSymbolAddress((void**)&qkv,  g_qkv);
    cudaGetSymbolAddress((void**)&abig, g_abig);
    cudaGetSymbolAddress((void**)&wbig, g_wbig);

    cudaFuncSetAttribute(gemm_hmma,
                         cudaFuncAttributeMaxDynamicSharedMemorySize,
                         GEMM_SMEM_BYTES);
    cudaFuncSetAttribute(flash_mma_kernel,
                         cudaFuncAttributeMaxDynamicSharedMemorySize,
                         FLASH3_SMEM);

    const int n_act = BS * DD;
    const int n_w   = DD * DD;

    rope_table_kernel<<<(SS * NPAIR + 255) / 256, 256>>>();

    // x -> bf16x3 activation; wq/wk/wv -> stacked weight buffer
    split3_kernel<<<(n_act + 255) / 256, 256>>>(x, abig, n_act, 0);
    split3_kernel<<<(n_w + 255) / 256, 256>>>(wq, wbig, n_w, 1);
    split3_kernel<<<(n_w + 255) / 256, 256>>>(wk, wbig + (size_t)DD * KBIG, n_w, 1);
    split3_kernel<<<(n_w + 255) / 256, 256>>>(wv, wbig + (size_t)2 * DD * KBIG, n_w, 1);

    // Fused QKV projection: [4096, 6144]
    dim3 qkv_grid(KBIG / 64, BS / 128);  // (96, 32)
    gemm_hmma<<<qkv_grid, 256, GEMM_SMEM_BYTES>>>(abig, wbig, qkv, KBIG);

    // RoPE + scale + split (q,k) and transpose + split (v)
    qkv_rope_split_kernel<<<(BS * 1024 + 255) / 256, 256>>>();
    v_split_t_kernel<<<dim3(SS / 64, BB * HH), 256>>>();

    // FA2-style HMMA flash attention (writes split activations directly)
    flash_mma_kernel<<<dim3(SS / 128, BB * HH), 256, FLASH3_SMEM>>>();

    // Output projection
    split3_kernel<<<(n_w + 255) / 256, 256>>>(wo, wbig, n_w, 1);
    dim3 ogrid(DD / 64, BS / 128);  // (32, 32)
    gemm_hmma<<<ogrid, 256, GEMM_SMEM_BYTES>>>(abig, wbig, out, DD);
}

// round 11
// speedup vs baseline: 1.9939x; 1.1275x over previous
#include <cuda_runtime.h>
#include <cuda_bf16.h>
#include <cuda_fp16.h>
#include <math.h>
#include <stdint.h>

// Problem constants
#define BB 2
#define SS 2048
#define DD 2048
#define HH 16
#define HD 128
#define BS (BB * SS)        // 4096 tokens
#define NPAIR (HD / 2)      // 64 rope pairs per head
#define KBIG (3 * DD)       // 6144: bf16x3 split-K
#define ITERS (KBIG / 64)   // 96 K-chunks of 64
#define STG 4               // cp.async pipeline stages
#define LOG2E 1.4426950408889634f
#define QK_SCALE 0.08838834764831845f

// ---------------------------------------------------------------------------
// Scratch (device globals -- no allocation allowed in kernel_launch)
// ---------------------------------------------------------------------------
__device__ float g_qkv[(size_t)BS * KBIG];           // fused QKV output [t][q|k|v]
__device__ float g_cos[SS * NPAIR];
__device__ float g_sin[SS * NPAIR];
__device__ __nv_bfloat16 g_abig[(size_t)BS * KBIG];  // activations [hi | lo | hi]
__device__ __nv_bfloat16 g_wbig[(size_t)KBIG * KBIG]; // weights [hi | hi | lo]
// Attention fp16 buffers: q hi/lo, k hi, [bh][s][d]; v hi transposed [bh][d][s]
__device__ __half g_qshi[(size_t)BS * DD];
__device__ __half g_qslo[(size_t)BS * DD];
__device__ __half g_kshi[(size_t)BS * DD];
__device__ __half g_vthi[(size_t)BS * DD];

// ---------------------------------------------------------------------------
// Helpers
// ---------------------------------------------------------------------------
__device__ __forceinline__ uint32_t smem_u32(const void* p) {
    uint32_t a;
    asm("{ .reg .u64 t; cvta.to.shared.u64 t, %1; cvt.u32.u64 %0, t; }"
        : "=r"(a) : "l"(p));
    return a;
}
#define CP_ASYNC16(smem, gptr) \
    asm volatile("cp.async.cg.shared.global [%0], [%1], 16;" \
                 :: "r"((uint32_t)(smem)), "l"((const void*)(gptr)) : "memory")
#define CP_COMMIT() asm volatile("cp.async.commit_group;" ::: "memory")

#define LDSM_X4(r0, r1, r2, r3, addr) \
    asm volatile("ldmatrix.sync.aligned.m8n8.x4.shared.b16 {%0,%1,%2,%3}, [%4];" \
                 : "=r"(r0), "=r"(r1), "=r"(r2), "=r"(r3) : "r"(addr))

#define MMA16816(d, a, b0, b1) \
    asm volatile("mma.sync.aligned.m16n8k16.row.col.f32.bf16.bf16.f32 " \
                 "{%0,%1,%2,%3}, {%4,%5,%6,%7}, {%8,%9}, {%0,%1,%2,%3};" \
                 : "+f"((d)[0]), "+f"((d)[1]), "+f"((d)[2]), "+f"((d)[3]) \
                 : "r"((a)[0]), "r"((a)[1]), "r"((a)[2]), "r"((a)[3]),   \
                   "r"(b0), "r"(b1))

#define MMA16816H(d, a, b0, b1) \
    asm volatile("mma.sync.aligned.m16n8k16.row.col.f32.f16.f16.f32 " \
                 "{%0,%1,%2,%3}, {%4,%5,%6,%7}, {%8,%9}, {%0,%1,%2,%3};" \
                 : "+f"((d)[0]), "+f"((d)[1]), "+f"((d)[2]), "+f"((d)[3]) \
                 : "r"((a)[0]), "r"((a)[1]), "r"((a)[2]), "r"((a)[3]),   \
                   "r"(b0), "r"(b1))

// Fast exp2 on FMA pipe: t <= 0, clamp at -126; |rel err| ~ 3e-6
__device__ __forceinline__ float exp2_fast(float t) {
    t = fmaxf(t, -126.0f);
    float r = t + 12582912.0f;
    int e = __float_as_int(r) - 0x4B400000;
    float f = t - (r - 12582912.0f);
    float p = 0.0013333558f;
    p = fmaf(p, f, 0.0096181291f);
    p = fmaf(p, f, 0.0555041087f);
    p = fmaf(p, f, 0.2402265070f);
    p = fmaf(p, f, 0.6931471806f);
    p = fmaf(p, f, 1.0f);
    return __int_as_float((e + 127) << 23) * p;
}
// bf16 hi/lo split (for projection GEMM path)
__device__ __forceinline__ __nv_bfloat162 split_hi2(float a, float b,
                                                    __nv_bfloat162& lo2) {
    __nv_bfloat16 ha = __float2bfloat16(a);
    __nv_bfloat16 hb = __float2bfloat16(b);
    lo2.x = __float2bfloat16(a - __bfloat162float(ha));
    lo2.y = __float2bfloat16(b - __bfloat162float(hb));
    __nv_bfloat162 hi2; hi2.x = ha; hi2.y = hb;
    return hi2;
}
// fp16 hi/lo split packed into b32 words
__device__ __forceinline__ void split_pack_h(float a, float b,
                                             uint32_t& hi, uint32_t& lo) {
    __half2 h2 = __floats2half2_rn(a, b);
    float2 hf = __half22float2(h2);
    __half2 l2 = __floats2half2_rn(a - hf.x, b - hf.y);
    hi = *reinterpret_cast<uint32_t*>(&h2);
    lo = *reinterpret_cast<uint32_t*>(&l2);
}

// ---------------------------------------------------------------------------
// RoPE table (double precision generation)
// ---------------------------------------------------------------------------
__global__ void rope_table_kernel() {
    int idx = blockIdx.x * blockDim.x + threadIdx.x;
    if (idx >= SS * NPAIR) return;
    int s = idx / NPAIR;
    int i = idx - s * NPAIR;
    double freq = (double)s * exp(((double)(-2 * i) / (double)HD) * log(10000.0));
    g_cos[idx] = (float)cos(freq);
    g_sin[idx] = (float)sin(freq);
}

// ---------------------------------------------------------------------------
// bf16x3 split for projection GEMMs
// ---------------------------------------------------------------------------
__global__ void split3_kernel(const float* __restrict__ src,
                              __nv_bfloat16* __restrict__ dst,
                              int n, int mode) {
    int idx = blockIdx.x * blockDim.x + threadIdx.x;
    if (idx >= n) return;
    int r = idx >> 11;
    int c = idx & 2047;
    float v = src[idx];
    __nv_bfloat16 hi = __float2bfloat16(v);
    __nv_bfloat16 lo = __float2bfloat16(v - __bfloat162float(hi));
    size_t base = (size_t)r * KBIG + c;
    if (mode == 0) {
        dst[base] = hi; dst[base + DD] = lo; dst[base + 2 * DD] = hi;
    } else {
        dst[base] = hi; dst[base + DD] = hi; dst[base + 2 * DD] = lo;
    }
}

// ---------------------------------------------------------------------------
// Fused RoPE + scale + fp16 split (q hi/lo, k hi) straight out of g_qkv.
// ---------------------------------------------------------------------------
__global__ void qkv_rope_split_kernel() {
    int idx = blockIdx.x * blockDim.x + threadIdx.x;
    if (idx >= BS * 1024) return;
    int t = idx >> 10;
    int p = idx & 1023;
    int h = p >> 6;
    int i = p & 63;
    int s = t & (SS - 1);
    int b = t >> 11;
    float c  = g_cos[(s << 6) + i];
    float sn = g_sin[(s << 6) + i];
    size_t src = (size_t)t * KBIG + h * HD + 2 * i;
    float q0 = g_qkv[src],        q1 = g_qkv[src + 1];
    float k0 = g_qkv[src + DD],   k1 = g_qkv[src + DD + 1];
    float qo0 = (q0 * c - q1 * sn) * QK_SCALE;
    float qo1 = (q0 * sn + q1 * c) * QK_SCALE;
    float ko0 = k0 * c - k1 * sn;
    float ko1 = k0 * sn + k1 * c;
    size_t dst = ((size_t)(b * HH + h) * SS + s) * HD + 2 * i;
    __half2 qh = __floats2half2_rn(qo0, qo1);
    float2 qhf = __half22float2(qh);
    __half2 ql = __floats2half2_rn(qo0 - qhf.x, qo1 - qhf.y);
    *reinterpret_cast<__half2*>(&g_qshi[dst]) = qh;
    *reinterpret_cast<__half2*>(&g_qslo[dst]) = ql;
    *reinterpret_cast<__half2*>(&g_kshi[dst]) = __floats2half2_rn(ko0, ko1);
}

// ---------------------------------------------------------------------------
// V transpose: g_qkv[t][4096 + h*128 + d] -> g_vthi fp16 [bh][d][s]
// ---------------------------------------------------------------------------
__global__ __launch_bounds__(256) void v_split_t_kernel() {
    __shared__ float st[64][129];
    const int s0 = blockIdx.x * 64;
    const int bh = blockIdx.y;
    const int b = bh >> 4, h = bh & 15;
    const float* src = g_qkv + (size_t)(b * SS + s0) * KBIG + 2 * DD + h * HD;
    const int tid = threadIdx.x;
#pragma unroll
    for (int i = 0; i < 32; i++) {
        int id = tid + 256 * i;
        int sl = id >> 7, d = id & 127;
        st[sl][d] = src[(size_t)sl * KBIG + d];
    }
    __syncthreads();
    const int d = tid >> 1, half = tid & 1;
    __half hibuf[32];
#pragma unroll
    for (int j = 0; j < 32; j++)
        hibuf[j] = __float2half(st[half * 32 + j][d]);
    size_t dst = ((size_t)bh * HD + d) * SS + s0 + half * 32;
    uint4* ph = reinterpret_cast<uint4*>(&g_vthi[dst]);
#pragma unroll
    for (int tch = 0; tch < 4; tch++)
        ph[tch] = reinterpret_cast<uint4*>(hibuf)[tch];
}

// ---------------------------------------------------------------------------
// HMMA GEMM (unchanged): C[4096, N] = A[4096,6144] * B[N,6144]^T
// ---------------------------------------------------------------------------
#define TILE_STAGE_BYTES 24576
#define GEMM_SMEM_BYTES (STG * TILE_STAGE_BYTES)

__device__ __forceinline__ void issue_stage(
    uint32_t sb, int s, int tid,
    const __nv_bfloat16* __restrict__ Ag,
    const __nv_bfloat16* __restrict__ Bg)
{
    if (s < ITERS) {
        const int k0 = s * 64;
        const int slot = s & (STG - 1);
        uint32_t abase = sb + slot * TILE_STAGE_BYTES;
        uint32_t bbase = abase + 16384;
#pragma unroll
        for (int i = 0; i < 4; i++) {
            int id = tid + 256 * i;
            int row = id >> 3;
            int c = id & 7;
            uint32_t off = (uint32_t)(row * 128 + ((c ^ (row & 7)) << 4));
            CP_ASYNC16(abase + off, Ag + (size_t)row * KBIG + k0 + c * 8);
        }
#pragma unroll
        for (int i = 0; i < 2; i++) {
            int id = tid + 256 * i;
            int row = id >> 3;
            int c = id & 7;
            uint32_t off = (uint32_t)(row * 128 + ((c ^ (row & 7)) << 4));
            CP_ASYNC16(bbase + off, Bg + (size_t)row * KBIG + k0 + c * 8);
        }
    }
    CP_COMMIT();
}

__global__ __launch_bounds__(256, 2)
void gemm_hmma(const __nv_bfloat16* __restrict__ A,
               const __nv_bfloat16* __restrict__ Bw,
               float* __restrict__ C, int ldc)
{
    extern __shared__ char smraw[];
    uint32_t sb = smem_u32(smraw);
    const int tid  = threadIdx.x;
    const int lane = tid & 31;
    const int warp = tid >> 5;
    const int wm = warp & 3;
    const int wn = warp >> 2;
    const int m0 = blockIdx.y * 128;
    const int n0 = blockIdx.x * 64;
    const __nv_bfloat16* Ag = A  + (size_t)m0 * KBIG;
    const __nv_bfloat16* Bg = Bw + (size_t)n0 * KBIG;

    float acc[2][4][4];
#pragma unroll
    for (int a = 0; a < 2; a++)
#pragma unroll
        for (int b = 0; b < 4; b++)
#pragma unroll
            for (int c = 0; c < 4; c++) acc[a][b][c] = 0.f;

    issue_stage(sb, 0, tid, Ag, Bg);
    issue_stage(sb, 1, tid, Ag, Bg);
    issue_stage(sb, 2, tid, Ag, Bg);

    for (int s = 0; s < ITERS; s++) {
        asm volatile("cp.async.wait_group 2;" ::: "memory");
        __syncthreads();
        const int slot = s & (STG - 1);
        uint32_t abase = sb + slot * TILE_STAGE_BYTES;
        uint32_t bbase = abase + 16384;

#pragma unroll
        for (int ks = 0; ks < 4; ks++) {
            uint32_t af[2][4];
            uint32_t bf[4][2];
#pragma unroll
            for (int mt = 0; mt < 2; mt++) {
                int row = wm * 32 + mt * 16 + (lane & 15);
                int ch  = ks * 2 + (lane >> 4);
                uint32_t ad = abase + (uint32_t)(row * 128 +
                                  ((ch ^ (row & 7)) << 4));
                LDSM_X4(af[mt][0], af[mt][1], af[mt][2], af[mt][3], ad);
            }
#pragma unroll
            for (int np = 0; np < 2; np++) {
                int row = wn * 32 + np * 16 + ((lane >> 4) << 3) + (lane & 7);
                int ch  = ks * 2 + ((lane >> 3) & 1);
                uint32_t bd = bbase + (uint32_t)(row * 128 +
                                  ((ch ^ (row & 7)) << 4));
                LDSM_X4(bf[2 * np][0], bf[2 * np][1],
                        bf[2 * np + 1][0], bf[2 * np + 1][1], bd);
            }
#pragma unroll
            for (int mt = 0; mt < 2; mt++)
#pragma unroll
                for (int nt = 0; nt < 4; nt++)
                    MMA16816(acc[mt][nt], af[mt], bf[nt][0], bf[nt][1]);
        }
        issue_stage(sb, s + 3, tid, Ag, Bg);
    }

#pragma unroll
    for (int mt = 0; mt < 2; mt++) {
#pragma unroll
        for (int nt = 0; nt < 4; nt++) {
            int row = m0 + wm * 32 + mt * 16 + (lane >> 2);
            int col = n0 + wn * 32 + nt * 8 + (lane & 3) * 2;
            float2 v0 = make_float2(acc[mt][nt][0], acc[mt][nt][1]);
            float2 v1 = make_float2(acc[mt][nt][2], acc[mt][nt][3]);
            *reinterpret_cast<float2*>(&C[(size_t)row * ldc + col]) = v0;
            *reinterpret_cast<float2*>(&C[(size_t)(row + 8) * ldc + col]) = v1;
        }
    }
}

// ---------------------------------------------------------------------------
// FA2-style flash attention, fp16 two-term splits:
// QK: [q_hi|q_lo] . [k_hi], k' = 256.  PV: [p_hi|p_lo] . [v_hi], j' = 128.
// smem: Q hi/lo (2x32KB) + K hi (16KB) + V hi (16KB) = 96KB.
// ---------------------------------------------------------------------------
#define SQHI 0
#define SQLO 32768
#define SKHI 65536
#define SVHI 81920
#define FLASH3_SMEM 98304

// Q tile: 128 rows x 128 fp16 (256B rows, swizzled), hi+lo
__device__ __forceinline__ void issue_q_tile(
    uint32_t sb, const __half* __restrict__ ghi,
    const __half* __restrict__ glo, int tid)
{
#pragma unroll
    for (int i = 0; i < 8; i++) {
        int id = tid + 256 * i;
        int row = id >> 4, c = id & 15;
        uint32_t off = (uint32_t)(row * 256 + ((c >> 3) << 7) +
                                  (((c & 7) ^ (row & 7)) << 4));
        CP_ASYNC16(sb + SQHI + off, ghi + (size_t)row * HD + c * 8);
        CP_ASYNC16(sb + SQLO + off, glo + (size_t)row * HD + c * 8);
    }
}
// K tile: 64 rows x 128 fp16 (256B rows, swizzled), hi only
__device__ __forceinline__ void issue_k_tile(
    uint32_t sb, const __half* __restrict__ ghi, int tid)
{
#pragma unroll
    for (int i = 0; i < 4; i++) {
        int id = tid + 256 * i;
        int row = id >> 4, c = id & 15;
        uint32_t off = (uint32_t)(row * 256 + ((c >> 3) << 7) +
                                  (((c & 7) ^ (row & 7)) << 4));
        CP_ASYNC16(sb + SKHI + off, ghi + (size_t)row * HD + c * 8);
    }
}
// V^T tile: 128 rows(d) x 64 fp16 (128B rows, swizzled); row stride SS
__device__ __forceinline__ void issue_v_tile(
    uint32_t sb, const __half* __restrict__ ghi, int tid)
{
#pragma unroll
    for (int i = 0; i < 4; i++) {
        int id = tid + 256 * i;
        int row = id >> 3, c = id & 7;
        uint32_t off = (uint32_t)(row * 128 + ((c ^ (row & 7)) << 4));
        CP_ASYNC16(sb + SVHI + off, ghi + (size_t)row * SS + c * 8);
    }
}

__global__ __launch_bounds__(256, 1) void flash_mma_kernel() {
    extern __shared__ char smr[];
    uint32_t sb = smem_u32(smr);
    const int tid = threadIdx.x, lane = tid & 31, warp = tid >> 5;
    const int q0 = blockIdx.x * 128;
    const int bh = blockIdx.y;

    const __half* qhiG = g_qshi + ((size_t)bh * SS + q0) * HD;
    const __half* qloG = g_qslo + ((size_t)bh * SS + q0) * HD;
    const __half* khiB = g_kshi + (size_t)bh * SS * HD;
    const __half* vhiB = g_vthi + (size_t)bh * HD * SS;

    issue_q_tile(sb, qhiG, qloG, tid);
    CP_COMMIT();
    issue_k_tile(sb, khiB, tid);
    CP_COMMIT();

    float m0v = -1e30f, m8v = -1e30f, l0 = 0.f, l8 = 0.f;
    float o[16][4];
#pragma unroll
    for (int nt = 0; nt < 16; nt++)
#pragma unroll
        for (int c = 0; c < 4; c++) o[nt][c] = 0.f;

    for (int t = 0; t < 32; t++) {
        asm volatile("cp.async.wait_group 0;" ::: "memory");
        __syncthreads();
        issue_v_tile(sb, vhiB + t * 64, tid);
        CP_COMMIT();

        // ---- QK^T: warp rows 16 x keys 64, k' = 256 (2 fp16 terms) ----
        float sc[8][4];
#pragma unroll
        for (int nt = 0; nt < 8; nt++)
#pragma unroll
            for (int c = 0; c < 4; c++) sc[nt][c] = 0.f;

#pragma unroll
        for (int ks = 0; ks < 16; ks++) {
            const int term = ks >> 3, pk = ks & 7;
            uint32_t abase = sb + (term ? SQLO : SQHI);
            uint32_t bbase = sb + SKHI;
            uint32_t af[4], bfr[8][2];
            {
                int row = warp * 16 + (lane & 15);
                int c0 = pk * 2 + (lane >> 4);
                uint32_t ad = abase + (uint32_t)(row * 256 + ((c0 >> 3) << 7) +
                                  (((c0 & 7) ^ (row & 7)) << 4));
                LDSM_X4(af[0], af[1], af[2], af[3], ad);
            }
#pragma unroll
            for (int np = 0; np < 4; np++) {
                int row = np * 16 + ((lane >> 4) << 3) + (lane & 7);
                int c0 = pk * 2 + ((lane >> 3) & 1);
                uint32_t bd = bbase + (uint32_t)(row * 256 + ((c0 >> 3) << 7) +
                                  (((c0 & 7) ^ (row & 7)) << 4));
                LDSM_X4(bfr[2 * np][0], bfr[2 * np][1],
                        bfr[2 * np + 1][0], bfr[2 * np + 1][1], bd);
            }
#pragma unroll
            for (int nt = 0; nt < 8; nt++)
                MMA16816H(sc[nt], af, bfr[nt][0], bfr[nt][1]);
        }

        // ---- in-register online softmax (quad-only reductions) ----
        float mx0 = -1e30f, mx8 = -1e30f;
#pragma unroll
        for (int nt = 0; nt < 8; nt++) {
            mx0 = fmaxf(mx0, fmaxf(sc[nt][0], sc[nt][1]));
            mx8 = fmaxf(mx8, fmaxf(sc[nt][2], sc[nt][3]));
        }
        mx0 = fmaxf(mx0, __shfl_xor_sync(0xffffffff, mx0, 1));
        mx0 = fmaxf(mx0, __shfl_xor_sync(0xffffffff, mx0, 2));
        mx8 = fmaxf(mx8, __shfl_xor_sync(0xffffffff, mx8, 1));
        mx8 = fmaxf(mx8, __shfl_xor_sync(0xffffffff, mx8, 2));
        float mn0 = fmaxf(m0v, mx0), mn8 = fmaxf(m8v, mx8);
        float al0 = exp2_fast((m0v - mn0) * LOG2E);
        float al8 = exp2_fast((m8v - mn8) * LOG2E);
        float s0 = 0.f, s8 = 0.f;
#pragma unroll
        for (int nt = 0; nt < 8; nt++) {
            float p0 = exp2_fast((sc[nt][0] - mn0) * LOG2E);
            float p1 = exp2_fast((sc[nt][1] - mn0) * LOG2E);
            float p2 = exp2_fast((sc[nt][2] - mn8) * LOG2E);
            float p3 = exp2_fast((sc[nt][3] - mn8) * LOG2E);
            sc[nt][0] = p0; sc[nt][1] = p1; sc[nt][2] = p2; sc[nt][3] = p3;
            s0 += p0 + p1; s8 += p2 + p3;
        }
        s0 += __shfl_xor_sync(0xffffffff, s0, 1);
        s0 += __shfl_xor_sync(0xffffffff, s0, 2);
        s8 += __shfl_xor_sync(0xffffffff, s8, 1);
        s8 += __shfl_xor_sync(0xffffffff, s8, 2);
        l0 = l0 * al0 + s0; m0v = mn0;
        l8 = l8 * al8 + s8; m8v = mn8;

        // Pack P hi/lo (fp16) into PV A-fragments
        uint32_t pHI[4][4], pLO[4][4];
#pragma unroll
        for (int kc = 0; kc < 4; kc++) {
            split_pack_h(sc[2 * kc][0],     sc[2 * kc][1],     pHI[kc][0], pLO[kc][0]);
            split_pack_h(sc[2 * kc][2],     sc[2 * kc][3],     pHI[kc][1], pLO[kc][1]);
            split_pack_h(sc[2 * kc + 1][0], sc[2 * kc + 1][1], pHI[kc][2], pLO[kc][2]);
            split_pack_h(sc[2 * kc + 1][2], sc[2 * kc + 1][3], pHI[kc][3], pLO[kc][3]);
        }

        // Rescale O
#pragma unroll
        for (int nt = 0; nt < 16; nt++) {
            o[nt][0] *= al0; o[nt][1] *= al0;
            o[nt][2] *= al8; o[nt][3] *= al8;
        }

        __syncthreads();  // all warps done reading K smem
        if (t + 1 < 32)
            issue_k_tile(sb, khiB + (size_t)(t + 1) * 64 * HD, tid);
        CP_COMMIT();
        asm volatile("cp.async.wait_group 1;" ::: "memory");  // V(t) ready
        __syncthreads();

        // ---- PV: rows 16 x d 128, j' = 128 (2 fp16 terms) ----
#pragma unroll
        for (int ks = 0; ks < 8; ks++) {
            const int term = ks >> 2, kc = ks & 3;
            const uint32_t* afr = term ? pLO[kc] : pHI[kc];
            uint32_t bbase = sb + SVHI;
            const int ch = kc * 2 + ((lane >> 3) & 1);
#pragma unroll
            for (int half = 0; half < 2; half++) {
                uint32_t bfr[8][2];
#pragma unroll
                for (int np = 0; np < 4; np++) {
                    int row = half * 64 + np * 16 +
                              ((lane >> 4) << 3) + (lane & 7);
                    uint32_t bd = bbase + (uint32_t)(row * 128 +
                                      ((ch ^ (row & 7)) << 4));
                    LDSM_X4(bfr[2 * np][0], bfr[2 * np][1],
                            bfr[2 * np + 1][0], bfr[2 * np + 1][1], bd);
                }
#pragma unroll
                for (int i = 0; i < 8; i++)
                    MMA16816H(o[half * 8 + i], afr, bfr[i][0], bfr[i][1]);
            }
        }
    }

    // Epilogue: normalize; write bf16 [hi|lo|hi] split directly into g_abig
    const int b = bh >> 4, h = bh & 15;
    const int row = warp * 16 + (lane >> 2);
    float inv0 = 1.0f / l0;
    float inv8 = 1.0f / l8;
#pragma unroll
    for (int nt = 0; nt < 16; nt++) {
        int col = nt * 8 + (lane & 3) * 2;
        size_t a0 = (size_t)(b * SS + q0 + row) * KBIG + h * HD + col;
        {
            __nv_bfloat162 l2;
            __nv_bfloat162 h2 = split_hi2(o[nt][0] * inv0, o[nt][1] * inv0, l2);
            *reinterpret_cast<__nv_bfloat162*>(&g_abig[a0]) = h2;
            *reinterpret_cast<__nv_bfloat162*>(&g_abig[a0 + DD]) = l2;
            *reinterpret_cast<__nv_bfloat162*>(&g_abig[a0 + 2 * DD]) = h2;
        }
        {
            size_t a8 = a0 + (size_t)8 * KBIG;
            __nv_bfloat162 l2;
            __nv_bfloat162 h2 = split_hi2(o[nt][2] * inv8, o[nt][3] * inv8, l2);
            *reinterpret_cast<__nv_bfloat162*>(&g_abig[a8]) = h2;
            *reinterpret_cast<__nv_bfloat162*>(&g_abig[a8 + DD]) = l2;
            *reinterpret_cast<__nv_bfloat162*>(&g_abig[a8 + 2 * DD]) = h2;
        }
    }
}

// ---------------------------------------------------------------------------
// Launch
// ---------------------------------------------------------------------------
extern "C" void kernel_launch(void* const* d_in, const int* in_sizes, int n_in,
                              void* d_out, int out_size) {
    (void)in_sizes; (void)n_in; (void)out_size;
    const float* x  = (const float*)d_in[0];
    const float* wq = (const float*)d_in[1];
    const float* wk = (const float*)d_in[2];
    const float* wv = (const float*)d_in[3];
    const float* wo = (const float*)d_in[4];
    float* out = (float*)d_out;

    float* qkv;
    __nv_bfloat16 *abig, *wbig;
    cudaGetSymbolAddress((void**)&qkv,  g_qkv);
    cudaGetSymbolAddress((void**)&abig, g_abig);
    cudaGetSymbolAddress((void**)&wbig, g_wbig);

    cudaFuncSetAttribute(gemm_hmma,
                         cudaFuncAttributeMaxDynamicSharedMemorySize,
                         GEMM_SMEM_BYTES);
    cudaFuncSetAttribute(flash_mma_kernel,
                         cudaFuncAttributeMaxDynamicSharedMemorySize,
                         FLASH3_SMEM);

    const int n_act = BS * DD;
    const int n_w   = DD * DD;

    rope_table_kernel<<<(SS * NPAIR + 255) / 256, 256>>>();

    // x -> bf16x3 activation; wq/wk/wv -> stacked weight buffer
    split3_kernel<<<(n_act + 255) / 256, 256>>>(x, abig, n_act, 0);
    split3_kernel<<<(n_w + 255) / 256, 256>>>(wq, wbig, n_w, 1);
    split3_kernel<<<(n_w + 255) / 256, 256>>>(wk, wbig + (size_t)DD * KBIG, n_w, 1);
    split3_kernel<<<(n_w + 255) / 256, 256>>>(wv, wbig + (size_t)2 * DD * KBIG, n_w, 1);

    // Fused QKV projection: [4096, 6144]
    dim3 qkv_grid(KBIG / 64, BS / 128);  // (96, 32)
    gemm_hmma<<<qkv_grid, 256, GEMM_SMEM_BYTES>>>(abig, wbig, qkv, KBIG);

    // RoPE + scale + fp16 split (q,k) and transpose fp16 (v)
    qkv_rope_split_kernel<<<(BS * 1024 + 255) / 256, 256>>>();
    v_split_t_kernel<<<dim3(SS / 64, BB * HH), 256>>>();

    // fp16x2 FA2 flash attention (writes bf16x3 activations directly)
    flash_mma_kernel<<<dim3(SS / 128, BB * HH), 256, FLASH3_SMEM>>>();

    // Output projection
    split3_kernel<<<(n_w + 255) / 256, 256>>>(wo, wbig, n_w, 1);
    dim3 ogrid(DD / 64, BS / 128);  // (32, 32)
    gemm_hmma<<<ogrid, 256, GEMM_SMEM_BYTES>>>(abig, wbig, out, DD);
}

// round 12
// speedup vs baseline: 2.5384x; 1.2731x over previous
#include <cuda_runtime.h>
#include <cuda_bf16.h>
#include <cuda_fp16.h>
#include <math.h>
#include <stdint.h>

// Problem constants
#define BB 2
#define SS 2048
#define DD 2048
#define HH 16
#define HD 128
#define BS (BB * SS)        // 4096 tokens
#define NPAIR (HD / 2)      // 64 rope pairs per head
#define KA (2 * DD)         // 4096: fp16x2 split-K for projections
#define ITERSG (KA / 64)    // 64 K-chunks of 64
#define STG 4               // cp.async pipeline stages
#define LOG2E 1.4426950408889634f
#define QK_SCALE 0.08838834764831845f

// ---------------------------------------------------------------------------
// Scratch (device globals -- no allocation allowed in kernel_launch)
// ---------------------------------------------------------------------------
__device__ float g_qkv[(size_t)BS * 3 * DD];         // fused QKV output [t][q|k|v]
__device__ float g_cos[SS * NPAIR];
__device__ float g_sin[SS * NPAIR];
__device__ __half g_abig[(size_t)BS * KA];           // activations [hi | lo]
__device__ __half g_wbig[(size_t)(3 * DD) * KA];     // weights [hi | hi]
// Attention fp16 buffers: q hi/lo, k hi, [bh][s][d]; v hi transposed [bh][d][s]
__device__ __half g_qshi[(size_t)BS * DD];
__device__ __half g_qslo[(size_t)BS * DD];
__device__ __half g_kshi[(size_t)BS * DD];
__device__ __half g_vthi[(size_t)BS * DD];

// ---------------------------------------------------------------------------
// Helpers
// ---------------------------------------------------------------------------
__device__ __forceinline__ uint32_t smem_u32(const void* p) {
    uint32_t a;
    asm("{ .reg .u64 t; cvta.to.shared.u64 t, %1; cvt.u32.u64 %0, t; }"
        : "=r"(a) : "l"(p));
    return a;
}
#define CP_ASYNC16(smem, gptr) \
    asm volatile("cp.async.cg.shared.global [%0], [%1], 16;" \
                 :: "r"((uint32_t)(smem)), "l"((const void*)(gptr)) : "memory")
#define CP_COMMIT() asm volatile("cp.async.commit_group;" ::: "memory")

#define LDSM_X4(r0, r1, r2, r3, addr) \
    asm volatile("ldmatrix.sync.aligned.m8n8.x4.shared.b16 {%0,%1,%2,%3}, [%4];" \
                 : "=r"(r0), "=r"(r1), "=r"(r2), "=r"(r3) : "r"(addr))

#define MMA16816H(d, a, b0, b1) \
    asm volatile("mma.sync.aligned.m16n8k16.row.col.f32.f16.f16.f32 " \
                 "{%0,%1,%2,%3}, {%4,%5,%6,%7}, {%8,%9}, {%0,%1,%2,%3};" \
                 : "+f"((d)[0]), "+f"((d)[1]), "+f"((d)[2]), "+f"((d)[3]) \
                 : "r"((a)[0]), "r"((a)[1]), "r"((a)[2]), "r"((a)[3]),   \
                   "r"(b0), "r"(b1))

// Fast exp2 on FMA pipe: t <= 0, clamp at -126; |rel err| ~ 3e-6
__device__ __forceinline__ float exp2_fast(float t) {
    t = fmaxf(t, -126.0f);
    float r = t + 12582912.0f;
    int e = __float_as_int(r) - 0x4B400000;
    float f = t - (r - 12582912.0f);
    float p = 0.0013333558f;
    p = fmaf(p, f, 0.0096181291f);
    p = fmaf(p, f, 0.0555041087f);
    p = fmaf(p, f, 0.2402265070f);
    p = fmaf(p, f, 0.6931471806f);
    p = fmaf(p, f, 1.0f);
    return __int_as_float((e + 127) << 23) * p;
}
// fp16 hi/lo split packed into b32 words
__device__ __forceinline__ void split_pack_h(float a, float b,
                                             uint32_t& hi, uint32_t& lo) {
    __half2 h2 = __floats2half2_rn(a, b);
    float2 hf = __half22float2(h2);
    __half2 l2 = __floats2half2_rn(a - hf.x, b - hf.y);
    hi = *reinterpret_cast<uint32_t*>(&h2);
    lo = *reinterpret_cast<uint32_t*>(&l2);
}

// ---------------------------------------------------------------------------
// RoPE table (double precision generation)
// ---------------------------------------------------------------------------
__global__ void rope_table_kernel() {
    int idx = blockIdx.x * blockDim.x + threadIdx.x;
    if (idx >= SS * NPAIR) return;
    int s = idx / NPAIR;
    int i = idx - s * NPAIR;
    double freq = (double)s * exp(((double)(-2 * i) / (double)HD) * log(10000.0));
    g_cos[idx] = (float)cos(freq);
    g_sin[idx] = (float)sin(freq);
}

// ---------------------------------------------------------------------------
// fp16x2 split for projection GEMMs
// mode 0 (activation): [hi | lo];  mode 1 (weight): [hi | hi]
// ---------------------------------------------------------------------------
__global__ void split2_kernel(const float* __restrict__ src,
                              __half* __restrict__ dst,
                              int n, int mode) {
    int idx = blockIdx.x * blockDim.x + threadIdx.x;
    if (idx >= n) return;
    int r = idx >> 11;
    int c = idx & 2047;
    float v = src[idx];
    __half hi = __float2half_rn(v);
    size_t base = (size_t)r * KA + c;
    dst[base] = hi;
    if (mode == 0) {
        dst[base + DD] = __float2half_rn(v - __half2float(hi));
    } else {
        dst[base + DD] = hi;
    }
}

// ---------------------------------------------------------------------------
// Fused RoPE + scale + fp16 split (q hi/lo, k hi) straight out of g_qkv.
// ---------------------------------------------------------------------------
__global__ void qkv_rope_split_kernel() {
    int idx = blockIdx.x * blockDim.x + threadIdx.x;
    if (idx >= BS * 1024) return;
    int t = idx >> 10;
    int p = idx & 1023;
    int h = p >> 6;
    int i = p & 63;
    int s = t & (SS - 1);
    int b = t >> 11;
    float c  = g_cos[(s << 6) + i];
    float sn = g_sin[(s << 6) + i];
    size_t src = (size_t)t * (3 * DD) + h * HD + 2 * i;
    float q0 = g_qkv[src],        q1 = g_qkv[src + 1];
    float k0 = g_qkv[src + DD],   k1 = g_qkv[src + DD + 1];
    float qo0 = (q0 * c - q1 * sn) * QK_SCALE;
    float qo1 = (q0 * sn + q1 * c) * QK_SCALE;
    float ko0 = k0 * c - k1 * sn;
    float ko1 = k0 * sn + k1 * c;
    size_t dst = ((size_t)(b * HH + h) * SS + s) * HD + 2 * i;
    __half2 qh = __floats2half2_rn(qo0, qo1);
    float2 qhf = __half22float2(qh);
    __half2 ql = __floats2half2_rn(qo0 - qhf.x, qo1 - qhf.y);
    *reinterpret_cast<__half2*>(&g_qshi[dst]) = qh;
    *reinterpret_cast<__half2*>(&g_qslo[dst]) = ql;
    *reinterpret_cast<__half2*>(&g_kshi[dst]) = __floats2half2_rn(ko0, ko1);
}

// ---------------------------------------------------------------------------
// V transpose: g_qkv[t][4096 + h*128 + d] -> g_vthi fp16 [bh][d][s]
// ---------------------------------------------------------------------------
__global__ __launch_bounds__(256) void v_split_t_kernel() {
    __shared__ float st[64][129];
    const int s0 = blockIdx.x * 64;
    const int bh = blockIdx.y;
    const int b = bh >> 4, h = bh & 15;
    const float* src = g_qkv + (size_t)(b * SS + s0) * (3 * DD) + 2 * DD + h * HD;
    const int tid = threadIdx.x;
#pragma unroll
    for (int i = 0; i < 32; i++) {
        int id = tid + 256 * i;
        int sl = id >> 7, d = id & 127;
        st[sl][d] = src[(size_t)sl * (3 * DD) + d];
    }
    __syncthreads();
    const int d = tid >> 1, half = tid & 1;
    __half hibuf[32];
#pragma unroll
    for (int j = 0; j < 32; j++)
        hibuf[j] = __float2half(st[half * 32 + j][d]);
    size_t dst = ((size_t)bh * HD + d) * SS + s0 + half * 32;
    uint4* ph = reinterpret_cast<uint4*>(&g_vthi[dst]);
#pragma unroll
    for (int tch = 0; tch < 4; tch++)
        ph[tch] = reinterpret_cast<uint4*>(hibuf)[tch];
}

// ---------------------------------------------------------------------------
// HMMA GEMM (fp16x2): C[4096, N] = A[4096,4096] * B[N,4096]^T, ldc = N
// 128x64 CTA tile (8 warps, 4m x 2n), BK=64, 4-stage cp.async pipeline.
// ---------------------------------------------------------------------------
#define TILE_STAGE_BYTES 24576
#define GEMM_SMEM_BYTES (STG * TILE_STAGE_BYTES)

__device__ __forceinline__ void issue_stage(
    uint32_t sb, int s, int tid,
    const __half* __restrict__ Ag,
    const __half* __restrict__ Bg)
{
    if (s < ITERSG) {
        const int k0 = s * 64;
        const int slot = s & (STG - 1);
        uint32_t abase = sb + slot * TILE_STAGE_BYTES;
        uint32_t bbase = abase + 16384;
#pragma unroll
        for (int i = 0; i < 4; i++) {
            int id = tid + 256 * i;
            int row = id >> 3;
            int c = id & 7;
            uint32_t off = (uint32_t)(row * 128 + ((c ^ (row & 7)) << 4));
            CP_ASYNC16(abase + off, Ag + (size_t)row * KA + k0 + c * 8);
        }
#pragma unroll
        for (int i = 0; i < 2; i++) {
            int id = tid + 256 * i;
            int row = id >> 3;
            int c = id & 7;
            uint32_t off = (uint32_t)(row * 128 + ((c ^ (row & 7)) << 4));
            CP_ASYNC16(bbase + off, Bg + (size_t)row * KA + k0 + c * 8);
        }
    }
    CP_COMMIT();
}

__global__ __launch_bounds__(256, 2)
void gemm_hmma(const __half* __restrict__ A,
               const __half* __restrict__ Bw,
               float* __restrict__ C, int ldc)
{
    extern __shared__ char smraw[];
    uint32_t sb = smem_u32(smraw);
    const int tid  = threadIdx.x;
    const int lane = tid & 31;
    const int warp = tid >> 5;
    const int wm = warp & 3;
    const int wn = warp >> 2;
    const int m0 = blockIdx.y * 128;
    const int n0 = blockIdx.x * 64;
    const __half* Ag = A  + (size_t)m0 * KA;
    const __half* Bg = Bw + (size_t)n0 * KA;

    float acc[2][4][4];
#pragma unroll
    for (int a = 0; a < 2; a++)
#pragma unroll
        for (int b = 0; b < 4; b++)
#pragma unroll
            for (int c = 0; c < 4; c++) acc[a][b][c] = 0.f;

    issue_stage(sb, 0, tid, Ag, Bg);
    issue_stage(sb, 1, tid, Ag, Bg);
    issue_stage(sb, 2, tid, Ag, Bg);

    for (int s = 0; s < ITERSG; s++) {
        asm volatile("cp.async.wait_group 2;" ::: "memory");
        __syncthreads();
        const int slot = s & (STG - 1);
        uint32_t abase = sb + slot * TILE_STAGE_BYTES;
        uint32_t bbase = abase + 16384;

#pragma unroll
        for (int ks = 0; ks < 4; ks++) {
            uint32_t af[2][4];
            uint32_t bf[4][2];
#pragma unroll
            for (int mt = 0; mt < 2; mt++) {
                int row = wm * 32 + mt * 16 + (lane & 15);
                int ch  = ks * 2 + (lane >> 4);
                uint32_t ad = abase + (uint32_t)(row * 128 +
                                  ((ch ^ (row & 7)) << 4));
                LDSM_X4(af[mt][0], af[mt][1], af[mt][2], af[mt][3], ad);
            }
#pragma unroll
            for (int np = 0; np < 2; np++) {
                int row = wn * 32 + np * 16 + ((lane >> 4) << 3) + (lane & 7);
                int ch  = ks * 2 + ((lane >> 3) & 1);
                uint32_t bd = bbase + (uint32_t)(row * 128 +
                                  ((ch ^ (row & 7)) << 4));
                LDSM_X4(bf[2 * np][0], bf[2 * np][1],
                        bf[2 * np + 1][0], bf[2 * np + 1][1], bd);
            }
#pragma unroll
            for (int mt = 0; mt < 2; mt++)
#pragma unroll
                for (int nt = 0; nt < 4; nt++)
                    MMA16816H(acc[mt][nt], af[mt], bf[nt][0], bf[nt][1]);
        }
        issue_stage(sb, s + 3, tid, Ag, Bg);
    }

#pragma unroll
    for (int mt = 0; mt < 2; mt++) {
#pragma unroll
        for (int nt = 0; nt < 4; nt++) {
            int row = m0 + wm * 32 + mt * 16 + (lane >> 2);
            int col = n0 + wn * 32 + nt * 8 + (lane & 3) * 2;
            float2 v0 = make_float2(acc[mt][nt][0], acc[mt][nt][1]);
            float2 v1 = make_float2(acc[mt][nt][2], acc[mt][nt][3]);
            *reinterpret_cast<float2*>(&C[(size_t)row * ldc + col]) = v0;
            *reinterpret_cast<float2*>(&C[(size_t)(row + 8) * ldc + col]) = v1;
        }
    }
}

// ---------------------------------------------------------------------------
// FA2-style flash attention, fp16 two-term splits:
// QK: [q_hi|q_lo] . [k_hi], k' = 256.  PV: [p_hi|p_lo] . [v_hi], j' = 128.
// smem: Q hi/lo (2x32KB) + K hi (16KB) + V hi (16KB) = 96KB.
// ---------------------------------------------------------------------------
#define SQHI 0
#define SQLO 32768
#define SKHI 65536
#define SVHI 81920
#define FLASH3_SMEM 98304

__device__ __forceinline__ void issue_q_tile(
    uint32_t sb, const __half* __restrict__ ghi,
    const __half* __restrict__ glo, int tid)
{
#pragma unroll
    for (int i = 0; i < 8; i++) {
        int id = tid + 256 * i;
        int row = id >> 4, c = id & 15;
        uint32_t off = (uint32_t)(row * 256 + ((c >> 3) << 7) +
                                  (((c & 7) ^ (row & 7)) << 4));
        CP_ASYNC16(sb + SQHI + off, ghi + (size_t)row * HD + c * 8);
        CP_ASYNC16(sb + SQLO + off, glo + (size_t)row * HD + c * 8);
    }
}
__device__ __forceinline__ void issue_k_tile(
    uint32_t sb, const __half* __restrict__ ghi, int tid)
{
#pragma unroll
    for (int i = 0; i < 4; i++) {
        int id = tid + 256 * i;
        int row = id >> 4, c = id & 15;
        uint32_t off = (uint32_t)(row * 256 + ((c >> 3) << 7) +
                                  (((c & 7) ^ (row & 7)) << 4));
        CP_ASYNC16(sb + SKHI + off, ghi + (size_t)row * HD + c * 8);
    }
}
__device__ __forceinline__ void issue_v_tile(
    uint32_t sb, const __half* __restrict__ ghi, int tid)
{
#pragma unroll
    for (int i = 0; i < 4; i++) {
        int id = tid + 256 * i;
        int row = id >> 3, c = id & 7;
        uint32_t off = (uint32_t)(row * 128 + ((c ^ (row & 7)) << 4));
        CP_ASYNC16(sb + SVHI + off, ghi + (size_t)row * SS + c * 8);
    }
}

__global__ __launch_bounds__(256, 1) void flash_mma_kernel() {
    extern __shared__ char smr[];
    uint32_t sb = smem_u32(smr);
    const int tid = threadIdx.x, lane = tid & 31, warp = tid >> 5;
    const int q0 = blockIdx.x * 128;
    const int bh = blockIdx.y;

    const __half* qhiG = g_qshi + ((size_t)bh * SS + q0) * HD;
    const __half* qloG = g_qslo + ((size_t)bh * SS + q0) * HD;
    const __half* khiB = g_kshi + (size_t)bh * SS * HD;
    const __half* vhiB = g_vthi + (size_t)bh * HD * SS;

    issue_q_tile(sb, qhiG, qloG, tid);
    CP_COMMIT();
    issue_k_tile(sb, khiB, tid);
    CP_COMMIT();

    float m0v = -1e30f, m8v = -1e30f, l0 = 0.f, l8 = 0.f;
    float o[16][4];
#pragma unroll
    for (int nt = 0; nt < 16; nt++)
#pragma unroll
        for (int c = 0; c < 4; c++) o[nt][c] = 0.f;

    for (int t = 0; t < 32; t++) {
        asm volatile("cp.async.wait_group 0;" ::: "memory");
        __syncthreads();
        issue_v_tile(sb, vhiB + t * 64, tid);
        CP_COMMIT();

        // ---- QK^T: warp rows 16 x keys 64, k' = 256 (2 fp16 terms) ----
        float sc[8][4];
#pragma unroll
        for (int nt = 0; nt < 8; nt++)
#pragma unroll
            for (int c = 0; c < 4; c++) sc[nt][c] = 0.f;

#pragma unroll
        for (int ks = 0; ks < 16; ks++) {
            const int term = ks >> 3, pk = ks & 7;
            uint32_t abase = sb + (term ? SQLO : SQHI);
            uint32_t bbase = sb + SKHI;
            uint32_t af[4], bfr[8][2];
            {
                int row = warp * 16 + (lane & 15);
                int c0 = pk * 2 + (lane >> 4);
                uint32_t ad = abase + (uint32_t)(row * 256 + ((c0 >> 3) << 7) +
                                  (((c0 & 7) ^ (row & 7)) << 4));
                LDSM_X4(af[0], af[1], af[2], af[3], ad);
            }
#pragma unroll
            for (int np = 0; np < 4; np++) {
                int row = np * 16 + ((lane >> 4) << 3) + (lane & 7);
                int c0 = pk * 2 + ((lane >> 3) & 1);
                uint32_t bd = bbase + (uint32_t)(row * 256 + ((c0 >> 3) << 7) +
                                  (((c0 & 7) ^ (row & 7)) << 4));
                LDSM_X4(bfr[2 * np][0], bfr[2 * np][1],
                        bfr[2 * np + 1][0], bfr[2 * np + 1][1], bd);
            }
#pragma unroll
            for (int nt = 0; nt < 8; nt++)
                MMA16816H(sc[nt], af, bfr[nt][0], bfr[nt][1]);
        }

        // ---- in-register online softmax (quad-only reductions) ----
        float mx0 = -1e30f, mx8 = -1e30f;
#pragma unroll
        for (int nt = 0; nt < 8; nt++) {
            mx0 = fmaxf(mx0, fmaxf(sc[nt][0], sc[nt][1]));
            mx8 = fmaxf(mx8, fmaxf(sc[nt][2], sc[nt][3]));
        }
        mx0 = fmaxf(mx0, __shfl_xor_sync(0xffffffff, mx0, 1));
        mx0 = fmaxf(mx0, __shfl_xor_sync(0xffffffff, mx0, 2));
        mx8 = fmaxf(mx8, __shfl_xor_sync(0xffffffff, mx8, 1));
        mx8 = fmaxf(mx8, __shfl_xor_sync(0xffffffff, mx8, 2));
        float mn0 = fmaxf(m0v, mx0), mn8 = fmaxf(m8v, mx8);
        float al0 = exp2_fast((m0v - mn0) * LOG2E);
        float al8 = exp2_fast((m8v - mn8) * LOG2E);
        float s0 = 0.f, s8 = 0.f;
#pragma unroll
        for (int nt = 0; nt < 8; nt++) {
            float p0 = exp2_fast((sc[nt][0] - mn0) * LOG2E);
            float p1 = exp2_fast((sc[nt][1] - mn0) * LOG2E);
            float p2 = exp2_fast((sc[nt][2] - mn8) * LOG2E);
            float p3 = exp2_fast((sc[nt][3] - mn8) * LOG2E);
            sc[nt][0] = p0; sc[nt][1] = p1; sc[nt][2] = p2; sc[nt][3] = p3;
            s0 += p0 + p1; s8 += p2 + p3;
        }
        s0 += __shfl_xor_sync(0xffffffff, s0, 1);
        s0 += __shfl_xor_sync(0xffffffff, s0, 2);
        s8 += __shfl_xor_sync(0xffffffff, s8, 1);
        s8 += __shfl_xor_sync(0xffffffff, s8, 2);
        l0 = l0 * al0 + s0; m0v = mn0;
        l8 = l8 * al8 + s8; m8v = mn8;

        // Pack P hi/lo (fp16) into PV A-fragments
        uint32_t pHI[4][4], pLO[4][4];
#pragma unroll
        for (int kc = 0; kc < 4; kc++) {
            split_pack_h(sc[2 * kc][0],     sc[2 * kc][1],     pHI[kc][0], pLO[kc][0]);
            split_pack_h(sc[2 * kc][2],     sc[2 * kc][3],     pHI[kc][1], pLO[kc][1]);
            split_pack_h(sc[2 * kc + 1][0], sc[2 * kc + 1][1], pHI[kc][2], pLO[kc][2]);
            split_pack_h(sc[2 * kc + 1][2], sc[2 * kc + 1][3], pHI[kc][3], pLO[kc][3]);
        }

        // Rescale O
#pragma unroll
        for (int nt = 0; nt < 16; nt++) {
            o[nt][0] *= al0; o[nt][1] *= al0;
            o[nt][2] *= al8; o[nt][3] *= al8;
        }

        __syncthreads();  // all warps done reading K smem
        if (t + 1 < 32)
            issue_k_tile(sb, khiB + (size_t)(t + 1) * 64 * HD, tid);
        CP_COMMIT();
        asm volatile("cp.async.wait_group 1;" ::: "memory");  // V(t) ready
        __syncthreads();

        // ---- PV: rows 16 x d 128, j' = 128 (2 fp16 terms) ----
#pragma unroll
        for (int ks = 0; ks < 8; ks++) {
            const int term = ks >> 2, kc = ks & 3;
            const uint32_t* afr = term ? pLO[kc] : pHI[kc];
            uint32_t bbase = sb + SVHI;
            const int ch = kc * 2 + ((lane >> 3) & 1);
#pragma unroll
            for (int half = 0; half < 2; half++) {
                uint32_t bfr[8][2];
#pragma unroll
                for (int np = 0; np < 4; np++) {
                    int row = half * 64 + np * 16 +
                              ((lane >> 4) << 3) + (lane & 7);
                    uint32_t bd = bbase + (uint32_t)(row * 128 +
                                      ((ch ^ (row & 7)) << 4));
                    LDSM_X4(bfr[2 * np][0], bfr[2 * np][1],
                            bfr[2 * np + 1][0], bfr[2 * np + 1][1], bd);
                }
#pragma unroll
                for (int i = 0; i < 8; i++)
                    MMA16816H(o[half * 8 + i], afr, bfr[i][0], bfr[i][1]);
            }
        }
    }

    // Epilogue: normalize; write fp16 [hi|lo] split directly into g_abig
    const int b = bh >> 4, h = bh & 15;
    const int row = warp * 16 + (lane >> 2);
    float inv0 = 1.0f / l0;
    float inv8 = 1.0f / l8;
#pragma unroll
    for (int nt = 0; nt < 16; nt++) {
        int col = nt * 8 + (lane & 3) * 2;
        size_t a0 = (size_t)(b * SS + q0 + row) * KA + h * HD + col;
        {
            uint32_t hi, lo;
            split_pack_h(o[nt][0] * inv0, o[nt][1] * inv0, hi, lo);
            *reinterpret_cast<uint32_t*>(&g_abig[a0]) = hi;
            *reinterpret_cast<uint32_t*>(&g_abig[a0 + DD]) = lo;
        }
        {
            size_t a8 = a0 + (size_t)8 * KA;
            uint32_t hi, lo;
            split_pack_h(o[nt][2] * inv8, o[nt][3] * inv8, hi, lo);
            *reinterpret_cast<uint32_t*>(&g_abig[a8]) = hi;
            *reinterpret_cast<uint32_t*>(&g_abig[a8 + DD]) = lo;
        }
    }
}

// ---------------------------------------------------------------------------
// Launch
// ---------------------------------------------------------------------------
extern "C" void kernel_launch(void* const* d_in, const int* in_sizes, int n_in,
                              void* d_out, int out_size) {
    (void)in_sizes; (void)n_in; (void)out_size;
    const float* x  = (const float*)d_in[0];
    const float* wq = (const float*)d_in[1];
    const float* wk = (const float*)d_in[2];
    const float* wv = (const float*)d_in[3];
    const float* wo = (const float*)d_in[4];
    float* out = (float*)d_out;

    float* qkv;
    __half *abig, *wbig;
    cudaGetSymbolAddress((void**)&qkv,  g_qkv);
    cudaGetSymbolAddress((void**)&abig, g_abig);
    cudaGetSymbolAddress((void**)&wbig, g_wbig);

    cudaFuncSetAttribute(gemm_hmma,
                         cudaFuncAttributeMaxDynamicSharedMemorySize,
                         GEMM_SMEM_BYTES);
    cudaFuncSetAttribute(flash_mma_kernel,
                         cudaFuncAttributeMaxDynamicSharedMemorySize,
                         FLASH3_SMEM);

    const int n_act = BS * DD;
    const int n_w   = DD * DD;

    rope_table_kernel<<<(SS * NPAIR + 255) / 256, 256>>>();

    // x -> fp16x2 activation; wq/wk/wv -> stacked weight buffer
    split2_kernel<<<(n_act + 255) / 256, 256>>>(x, abig, n_act, 0);
    split2_kernel<<<(n_w + 255) / 256, 256>>>(wq, wbig, n_w, 1);
    split2_kernel<<<(n_w + 255) / 256, 256>>>(wk, wbig + (size_t)DD * KA, n_w, 1);
    split2_kernel<<<(n_w + 255) / 256, 256>>>(wv, wbig + (size_t)2 * DD * KA, n_w, 1);

    // Fused QKV projection: [4096, 6144]
    dim3 qkv_grid((3 * DD) / 64, BS / 128);  // (96, 32)
    gemm_hmma<<<qkv_grid, 256, GEMM_SMEM_BYTES>>>(abig, wbig, qkv, 3 * DD);

    // RoPE + scale + fp16 split (q,k) and transpose fp16 (v)
    qkv_rope_split_kernel<<<(BS * 1024 + 255) / 256, 256>>>();
    v_split_t_kernel<<<dim3(SS / 64, BB * HH), 256>>>();

    // fp16x2 FA2 flash attention (writes fp16x2 activations directly)
    flash_mma_kernel<<<dim3(SS / 128, BB * HH), 256, FLASH3_SMEM>>>();

    // Output projection
    split2_kernel<<<(n_w + 255) / 256, 256>>>(wo, wbig, n_w, 1);
    dim3 ogrid(DD / 64, BS / 128);  // (32, 32)
    gemm_hmma<<<ogrid, 256, GEMM_SMEM_BYTES>>>(abig, wbig, out, DD);
}

// round 13
// speedup vs baseline: 2.9701x; 1.1701x over previous
#include <cuda_runtime.h>
#include <cuda_bf16.h>
#include <cuda_fp16.h>
#include <math.h>
#include <stdint.h>

// Problem constants
#define BB 2
#define SS 2048
#define DD 2048
#define HH 16
#define HD 128
#define BS (BB * SS)        // 4096 tokens
#define NPAIR (HD / 2)      // 64 rope pairs per head
#define KA (2 * DD)         // 4096: fp16x2 split-K for activations
#define KW DD               // 2048: weights stored hi-only (dedup)
#define ITERSG (KA / 64)    // 64 K-chunks of 64
#define STG 4               // cp.async pipeline stages
#define LOG2E 1.4426950408889634f
#define QK_SCALE 0.08838834764831845f

// ---------------------------------------------------------------------------
// Scratch (device globals -- no allocation allowed in kernel_launch)
// ---------------------------------------------------------------------------
__device__ float g_qkv[(size_t)BS * 3 * DD];         // fused QKV output [t][q|k|v]
__device__ float g_cos[SS * NPAIR];
__device__ float g_sin[SS * NPAIR];
__device__ __half g_abig[(size_t)BS * KA];           // activations [hi | lo]
__device__ __half g_wbig[(size_t)(3 * DD) * KW];     // weights hi only
// Attention fp16 buffers: q hi, k hi [bh][s][d]; v hi transposed [bh][d][s]
__device__ __half g_qshi[(size_t)BS * DD];
__device__ __half g_kshi[(size_t)BS * DD];
__device__ __half g_vthi[(size_t)BS * DD];

// ---------------------------------------------------------------------------
// Helpers
// ---------------------------------------------------------------------------
__device__ __forceinline__ uint32_t smem_u32(const void* p) {
    uint32_t a;
    asm("{ .reg .u64 t; cvta.to.shared.u64 t, %1; cvt.u32.u64 %0, t; }"
        : "=r"(a) : "l"(p));
    return a;
}
#define CP_ASYNC16(smem, gptr) \
    asm volatile("cp.async.cg.shared.global [%0], [%1], 16;" \
                 :: "r"((uint32_t)(smem)), "l"((const void*)(gptr)) : "memory")
#define CP_COMMIT() asm volatile("cp.async.commit_group;" ::: "memory")

#define LDSM_X4(r0, r1, r2, r3, addr) \
    asm volatile("ldmatrix.sync.aligned.m8n8.x4.shared.b16 {%0,%1,%2,%3}, [%4];" \
                 : "=r"(r0), "=r"(r1), "=r"(r2), "=r"(r3) : "r"(addr))

#define MMA16816H(d, a, b0, b1) \
    asm volatile("mma.sync.aligned.m16n8k16.row.col.f32.f16.f16.f32 " \
                 "{%0,%1,%2,%3}, {%4,%5,%6,%7}, {%8,%9}, {%0,%1,%2,%3};" \
                 : "+f"((d)[0]), "+f"((d)[1]), "+f"((d)[2]), "+f"((d)[3]) \
                 : "r"((a)[0]), "r"((a)[1]), "r"((a)[2]), "r"((a)[3]),   \
                   "r"(b0), "r"(b1))

// Fast exp2 on FMA pipe: t <= 0, clamp at -126; |rel err| ~ 3e-6
__device__ __forceinline__ float exp2_fast(float t) {
    t = fmaxf(t, -126.0f);
    float r = t + 12582912.0f;
    int e = __float_as_int(r) - 0x4B400000;
    float f = t - (r - 12582912.0f);
    float p = 0.0013333558f;
    p = fmaf(p, f, 0.0096181291f);
    p = fmaf(p, f, 0.0555041087f);
    p = fmaf(p, f, 0.2402265070f);
    p = fmaf(p, f, 0.6931471806f);
    p = fmaf(p, f, 1.0f);
    return __int_as_float((e + 127) << 23) * p;
}
// fp16 hi/lo split packed into b32 words
__device__ __forceinline__ void split_pack_h(float a, float b,
                                             uint32_t& hi, uint32_t& lo) {
    __half2 h2 = __floats2half2_rn(a, b);
    float2 hf = __half22float2(h2);
    __half2 l2 = __floats2half2_rn(a - hf.x, b - hf.y);
    hi = *reinterpret_cast<uint32_t*>(&h2);
    lo = *reinterpret_cast<uint32_t*>(&l2);
}
__device__ __forceinline__ uint32_t pack_h2(float a, float b) {
    __half2 h2 = __floats2half2_rn(a, b);
    return *reinterpret_cast<uint32_t*>(&h2);
}

// ---------------------------------------------------------------------------
// RoPE table (double precision generation)
// ---------------------------------------------------------------------------
__global__ void rope_table_kernel() {
    int idx = blockIdx.x * blockDim.x + threadIdx.x;
    if (idx >= SS * NPAIR) return;
    int s = idx / NPAIR;
    int i = idx - s * NPAIR;
    double freq = (double)s * exp(((double)(-2 * i) / (double)HD) * log(10000.0));
    g_cos[idx] = (float)cos(freq);
    g_sin[idx] = (float)sin(freq);
}

// ---------------------------------------------------------------------------
// Activation split: fp32 [rows,2048] -> fp16 [rows, 4096] = [hi | lo]
// ---------------------------------------------------------------------------
__global__ void split2_act_kernel(const float* __restrict__ src,
                                  __half* __restrict__ dst, int n) {
    int idx = blockIdx.x * blockDim.x + threadIdx.x;
    if (idx >= n) return;
    int r = idx >> 11;
    int c = idx & 2047;
    float v = src[idx];
    __half hi = __float2half_rn(v);
    size_t base = (size_t)r * KA + c;
    dst[base] = hi;
    dst[base + DD] = __float2half_rn(v - __half2float(hi));
}

// Weight convert: fp32 [rows,2048] -> fp16 hi only [rows, 2048]
__global__ void conv_w_kernel(const float* __restrict__ src,
                              __half* __restrict__ dst, int n) {
    int idx = blockIdx.x * blockDim.x + threadIdx.x;
    if (idx >= n) return;
    dst[idx] = __float2half_rn(src[idx]);
}

// ---------------------------------------------------------------------------
// Fused RoPE + scale + fp16 (q hi, k hi) straight out of g_qkv.
// ---------------------------------------------------------------------------
__global__ void qkv_rope_split_kernel() {
    int idx = blockIdx.x * blockDim.x + threadIdx.x;
    if (idx >= BS * 1024) return;
    int t = idx >> 10;
    int p = idx & 1023;
    int h = p >> 6;
    int i = p & 63;
    int s = t & (SS - 1);
    int b = t >> 11;
    float c  = g_cos[(s << 6) + i];
    float sn = g_sin[(s << 6) + i];
    size_t src = (size_t)t * (3 * DD) + h * HD + 2 * i;
    float q0 = g_qkv[src],        q1 = g_qkv[src + 1];
    float k0 = g_qkv[src + DD],   k1 = g_qkv[src + DD + 1];
    float qo0 = (q0 * c - q1 * sn) * QK_SCALE;
    float qo1 = (q0 * sn + q1 * c) * QK_SCALE;
    float ko0 = k0 * c - k1 * sn;
    float ko1 = k0 * sn + k1 * c;
    size_t dst = ((size_t)(b * HH + h) * SS + s) * HD + 2 * i;
    *reinterpret_cast<__half2*>(&g_qshi[dst]) = __floats2half2_rn(qo0, qo1);
    *reinterpret_cast<__half2*>(&g_kshi[dst]) = __floats2half2_rn(ko0, ko1);
}

// ---------------------------------------------------------------------------
// V transpose: g_qkv[t][4096 + h*128 + d] -> g_vthi fp16 [bh][d][s]
// ---------------------------------------------------------------------------
__global__ __launch_bounds__(256) void v_split_t_kernel() {
    __shared__ float st[64][129];
    const int s0 = blockIdx.x * 64;
    const int bh = blockIdx.y;
    const int b = bh >> 4, h = bh & 15;
    const float* src = g_qkv + (size_t)(b * SS + s0) * (3 * DD) + 2 * DD + h * HD;
    const int tid = threadIdx.x;
#pragma unroll
    for (int i = 0; i < 32; i++) {
        int id = tid + 256 * i;
        int sl = id >> 7, d = id & 127;
        st[sl][d] = src[(size_t)sl * (3 * DD) + d];
    }
    __syncthreads();
    const int d = tid >> 1, half = tid & 1;
    __half hibuf[32];
#pragma unroll
    for (int j = 0; j < 32; j++)
        hibuf[j] = __float2half(st[half * 32 + j][d]);
    size_t dst = ((size_t)bh * HD + d) * SS + s0 + half * 32;
    uint4* ph = reinterpret_cast<uint4*>(&g_vthi[dst]);
#pragma unroll
    for (int tch = 0; tch < 4; tch++)
        ph[tch] = reinterpret_cast<uint4*>(hibuf)[tch];
}

// ---------------------------------------------------------------------------
// HMMA GEMM (fp16x2 activations, hi-only weights):
// C[4096, N] = A[4096,4096] * B[N,2048]^T with B column index = k mod 2048.
// ---------------------------------------------------------------------------
#define TILE_STAGE_BYTES 24576
#define GEMM_SMEM_BYTES (STG * TILE_STAGE_BYTES)

__device__ __forceinline__ void issue_stage(
    uint32_t sb, int s, int tid,
    const __half* __restrict__ Ag,
    const __half* __restrict__ Bg)
{
    if (s < ITERSG) {
        const int k0 = s * 64;
        const int kw = k0 & (KW - 1);   // weight dedup: hi copy only
        const int slot = s & (STG - 1);
        uint32_t abase = sb + slot * TILE_STAGE_BYTES;
        uint32_t bbase = abase + 16384;
#pragma unroll
        for (int i = 0; i < 4; i++) {
            int id = tid + 256 * i;
            int row = id >> 3;
            int c = id & 7;
            uint32_t off = (uint32_t)(row * 128 + ((c ^ (row & 7)) << 4));
            CP_ASYNC16(abase + off, Ag + (size_t)row * KA + k0 + c * 8);
        }
#pragma unroll
        for (int i = 0; i < 2; i++) {
            int id = tid + 256 * i;
            int row = id >> 3;
            int c = id & 7;
            uint32_t off = (uint32_t)(row * 128 + ((c ^ (row & 7)) << 4));
            CP_ASYNC16(bbase + off, Bg + (size_t)row * KW + kw + c * 8);
        }
    }
    CP_COMMIT();
}

__global__ __launch_bounds__(256, 2)
void gemm_hmma(const __half* __restrict__ A,
               const __half* __restrict__ Bw,
               float* __restrict__ C, int ldc)
{
    extern __shared__ char smraw[];
    uint32_t sb = smem_u32(smraw);
    const int tid  = threadIdx.x;
    const int lane = tid & 31;
    const int warp = tid >> 5;
    const int wm = warp & 3;
    const int wn = warp >> 2;
    const int m0 = blockIdx.y * 128;
    const int n0 = blockIdx.x * 64;
    const __half* Ag = A  + (size_t)m0 * KA;
    const __half* Bg = Bw + (size_t)n0 * KW;

    float acc[2][4][4];
#pragma unroll
    for (int a = 0; a < 2; a++)
#pragma unroll
        for (int b = 0; b < 4; b++)
#pragma unroll
            for (int c = 0; c < 4; c++) acc[a][b][c] = 0.f;

    issue_stage(sb, 0, tid, Ag, Bg);
    issue_stage(sb, 1, tid, Ag, Bg);
    issue_stage(sb, 2, tid, Ag, Bg);

    for (int s = 0; s < ITERSG; s++) {
        asm volatile("cp.async.wait_group 2;" ::: "memory");
        __syncthreads();
        const int slot = s & (STG - 1);
        uint32_t abase = sb + slot * TILE_STAGE_BYTES;
        uint32_t bbase = abase + 16384;

#pragma unroll
        for (int ks = 0; ks < 4; ks++) {
            uint32_t af[2][4];
            uint32_t bf[4][2];
#pragma unroll
            for (int mt = 0; mt < 2; mt++) {
                int row = wm * 32 + mt * 16 + (lane & 15);
                int ch  = ks * 2 + (lane >> 4);
                uint32_t ad = abase + (uint32_t)(row * 128 +
                                  ((ch ^ (row & 7)) << 4));
                LDSM_X4(af[mt][0], af[mt][1], af[mt][2], af[mt][3], ad);
            }
#pragma unroll
            for (int np = 0; np < 2; np++) {
                int row = wn * 32 + np * 16 + ((lane >> 4) << 3) + (lane & 7);
                int ch  = ks * 2 + ((lane >> 3) & 1);
                uint32_t bd = bbase + (uint32_t)(row * 128 +
                                  ((ch ^ (row & 7)) << 4));
                LDSM_X4(bf[2 * np][0], bf[2 * np][1],
                        bf[2 * np + 1][0], bf[2 * np + 1][1], bd);
            }
#pragma unroll
            for (int mt = 0; mt < 2; mt++)
#pragma unroll
                for (int nt = 0; nt < 4; nt++)
                    MMA16816H(acc[mt][nt], af[mt], bf[nt][0], bf[nt][1]);
        }
        issue_stage(sb, s + 3, tid, Ag, Bg);
    }

#pragma unroll
    for (int mt = 0; mt < 2; mt++) {
#pragma unroll
        for (int nt = 0; nt < 4; nt++) {
            int row = m0 + wm * 32 + mt * 16 + (lane >> 2);
            int col = n0 + wn * 32 + nt * 8 + (lane & 3) * 2;
            float2 v0 = make_float2(acc[mt][nt][0], acc[mt][nt][1]);
            float2 v1 = make_float2(acc[mt][nt][2], acc[mt][nt][3]);
            *reinterpret_cast<float2*>(&C[(size_t)row * ldc + col]) = v0;
            *reinterpret_cast<float2*>(&C[(size_t)(row + 8) * ldc + col]) = v1;
        }
    }
}

// ---------------------------------------------------------------------------
// FA2-style flash attention, single-term fp16:
// QK: q_hi . k_hi (k' = 128).  PV: p_hi . v_hi.
// smem: Q (32KB) + K (16KB) + V (16KB) = 64KB.
// ---------------------------------------------------------------------------
#define SQHI 0
#define SKHI 32768
#define SVHI 49152
#define FLASH3_SMEM 65536

__device__ __forceinline__ void issue_q_tile(
    uint32_t sb, const __half* __restrict__ ghi, int tid)
{
#pragma unroll
    for (int i = 0; i < 8; i++) {
        int id = tid + 256 * i;
        int row = id >> 4, c = id & 15;
        uint32_t off = (uint32_t)(row * 256 + ((c >> 3) << 7) +
                                  (((c & 7) ^ (row & 7)) << 4));
        CP_ASYNC16(sb + SQHI + off, ghi + (size_t)row * HD + c * 8);
    }
}
__device__ __forceinline__ void issue_k_tile(
    uint32_t sb, const __half* __restrict__ ghi, int tid)
{
#pragma unroll
    for (int i = 0; i < 4; i++) {
        int id = tid + 256 * i;
        int row = id >> 4, c = id & 15;
        uint32_t off = (uint32_t)(row * 256 + ((c >> 3) << 7) +
                                  (((c & 7) ^ (row & 7)) << 4));
        CP_ASYNC16(sb + SKHI + off, ghi + (size_t)row * HD + c * 8);
    }
}
__device__ __forceinline__ void issue_v_tile(
    uint32_t sb, const __half* __restrict__ ghi, int tid)
{
#pragma unroll
    for (int i = 0; i < 4; i++) {
        int id = tid + 256 * i;
        int row = id >> 3, c = id & 7;
        uint32_t off = (uint32_t)(row * 128 + ((c ^ (row & 7)) << 4));
        CP_ASYNC16(sb + SVHI + off, ghi + (size_t)row * SS + c * 8);
    }
}

__global__ __launch_bounds__(256, 1) void flash_mma_kernel() {
    extern __shared__ char smr[];
    uint32_t sb = smem_u32(smr);
    const int tid = threadIdx.x, lane = tid & 31, warp = tid >> 5;
    const int q0 = blockIdx.x * 128;
    const int bh = blockIdx.y;

    const __half* qhiG = g_qshi + ((size_t)bh * SS + q0) * HD;
    const __half* khiB = g_kshi + (size_t)bh * SS * HD;
    const __half* vhiB = g_vthi + (size_t)bh * HD * SS;

    issue_q_tile(sb, qhiG, tid);
    CP_COMMIT();
    issue_k_tile(sb, khiB, tid);
    CP_COMMIT();

    float m0v = -1e30f, m8v = -1e30f, l0 = 0.f, l8 = 0.f;
    float o[16][4];
#pragma unroll
    for (int nt = 0; nt < 16; nt++)
#pragma unroll
        for (int c = 0; c < 4; c++) o[nt][c] = 0.f;

    for (int t = 0; t < 32; t++) {
        asm volatile("cp.async.wait_group 0;" ::: "memory");
        __syncthreads();
        issue_v_tile(sb, vhiB + t * 64, tid);
        CP_COMMIT();

        // ---- QK^T: warp rows 16 x keys 64, k' = 128 ----
        float sc[8][4];
#pragma unroll
        for (int nt = 0; nt < 8; nt++)
#pragma unroll
            for (int c = 0; c < 4; c++) sc[nt][c] = 0.f;

#pragma unroll
        for (int pk = 0; pk < 8; pk++) {
            uint32_t af[4], bfr[8][2];
            {
                int row = warp * 16 + (lane & 15);
                int c0 = pk * 2 + (lane >> 4);
                uint32_t ad = sb + SQHI + (uint32_t)(row * 256 + ((c0 >> 3) << 7) +
                                  (((c0 & 7) ^ (row & 7)) << 4));
                LDSM_X4(af[0], af[1], af[2], af[3], ad);
            }
#pragma unroll
            for (int np = 0; np < 4; np++) {
                int row = np * 16 + ((lane >> 4) << 3) + (lane & 7);
                int c0 = pk * 2 + ((lane >> 3) & 1);
                uint32_t bd = sb + SKHI + (uint32_t)(row * 256 + ((c0 >> 3) << 7) +
                                  (((c0 & 7) ^ (row & 7)) << 4));
                LDSM_X4(bfr[2 * np][0], bfr[2 * np][1],
                        bfr[2 * np + 1][0], bfr[2 * np + 1][1], bd);
            }
#pragma unroll
            for (int nt = 0; nt < 8; nt++)
                MMA16816H(sc[nt], af, bfr[nt][0], bfr[nt][1]);
        }

        // ---- in-register online softmax ----
        float mx0 = -1e30f, mx8 = -1e30f;
#pragma unroll
        for (int nt = 0; nt < 8; nt++) {
            mx0 = fmaxf(mx0, fmaxf(sc[nt][0], sc[nt][1]));
            mx8 = fmaxf(mx8, fmaxf(sc[nt][2], sc[nt][3]));
        }
        mx0 = fmaxf(mx0, __shfl_xor_sync(0xffffffff, mx0, 1));
        mx0 = fmaxf(mx0, __shfl_xor_sync(0xffffffff, mx0, 2));
        mx8 = fmaxf(mx8, __shfl_xor_sync(0xffffffff, mx8, 1));
        mx8 = fmaxf(mx8, __shfl_xor_sync(0xffffffff, mx8, 2));
        float mn0 = fmaxf(m0v, mx0), mn8 = fmaxf(m8v, mx8);
        float al0 = exp2_fast((m0v - mn0) * LOG2E);
        float al8 = exp2_fast((m8v - mn8) * LOG2E);
        float s0 = 0.f, s8 = 0.f;
#pragma unroll
        for (int nt = 0; nt < 8; nt++) {
            float p0 = exp2_fast((sc[nt][0] - mn0) * LOG2E);
            float p1 = exp2_fast((sc[nt][1] - mn0) * LOG2E);
            float p2 = exp2_fast((sc[nt][2] - mn8) * LOG2E);
            float p3 = exp2_fast((sc[nt][3] - mn8) * LOG2E);
            sc[nt][0] = p0; sc[nt][1] = p1; sc[nt][2] = p2; sc[nt][3] = p3;
            s0 += p0 + p1; s8 += p2 + p3;
        }
        s0 += __shfl_xor_sync(0xffffffff, s0, 1);
        s0 += __shfl_xor_sync(0xffffffff, s0, 2);
        s8 += __shfl_xor_sync(0xffffffff, s8, 1);
        s8 += __shfl_xor_sync(0xffffffff, s8, 2);
        l0 = l0 * al0 + s0; m0v = mn0;
        l8 = l8 * al8 + s8; m8v = mn8;

        // Pack P (fp16 hi only) into PV A-fragments
        uint32_t pHI[4][4];
#pragma unroll
        for (int kc = 0; kc < 4; kc++) {
            pHI[kc][0] = pack_h2(sc[2 * kc][0],     sc[2 * kc][1]);
            pHI[kc][1] = pack_h2(sc[2 * kc][2],     sc[2 * kc][3]);
            pHI[kc][2] = pack_h2(sc[2 * kc + 1][0], sc[2 * kc + 1][1]);
            pHI[kc][3] = pack_h2(sc[2 * kc + 1][2], sc[2 * kc + 1][3]);
        }

        // Rescale O
#pragma unroll
        for (int nt = 0; nt < 16; nt++) {
            o[nt][0] *= al0; o[nt][1] *= al0;
            o[nt][2] *= al8; o[nt][3] *= al8;
        }

        __syncthreads();  // all warps done reading K smem
        if (t + 1 < 32)
            issue_k_tile(sb, khiB + (size_t)(t + 1) * 64 * HD, tid);
        CP_COMMIT();
        asm volatile("cp.async.wait_group 1;" ::: "memory");  // V(t) ready
        __syncthreads();

        // ---- PV: rows 16 x d 128, single fp16 term ----
#pragma unroll
        for (int kc = 0; kc < 4; kc++) {
            const uint32_t* afr = pHI[kc];
            const int ch = kc * 2 + ((lane >> 3) & 1);
#pragma unroll
            for (int half = 0; half < 2; half++) {
                uint32_t bfr[8][2];
#pragma unroll
                for (int np = 0; np < 4; np++) {
                    int row = half * 64 + np * 16 +
                              ((lane >> 4) << 3) + (lane & 7);
                    uint32_t bd = sb + SVHI + (uint32_t)(row * 128 +
                                      ((ch ^ (row & 7)) << 4));
                    LDSM_X4(bfr[2 * np][0], bfr[2 * np][1],
                            bfr[2 * np + 1][0], bfr[2 * np + 1][1], bd);
                }
#pragma unroll
                for (int i = 0; i < 8; i++)
                    MMA16816H(o[half * 8 + i], afr, bfr[i][0], bfr[i][1]);
            }
        }
    }

    // Epilogue: normalize; write fp16 [hi|lo] split directly into g_abig
    const int b = bh >> 4, h = bh & 15;
    const int row = warp * 16 + (lane >> 2);
    float inv0 = 1.0f / l0;
    float inv8 = 1.0f / l8;
#pragma unroll
    for (int nt = 0; nt < 16; nt++) {
        int col = nt * 8 + (lane & 3) * 2;
        size_t a0 = (size_t)(b * SS + q0 + row) * KA + h * HD + col;
        {
            uint32_t hi, lo;
            split_pack_h(o[nt][0] * inv0, o[nt][1] * inv0, hi, lo);
            *reinterpret_cast<uint32_t*>(&g_abig[a0]) = hi;
            *reinterpret_cast<uint32_t*>(&g_abig[a0 + DD]) = lo;
        }
        {
            size_t a8 = a0 + (size_t)8 * KA;
            uint32_t hi, lo;
            split_pack_h(o[nt][2] * inv8, o[nt][3] * inv8, hi, lo);
            *reinterpret_cast<uint32_t*>(&g_abig[a8]) = hi;
            *reinterpret_cast<uint32_t*>(&g_abig[a8 + DD]) = lo;
        }
    }
}

// ---------------------------------------------------------------------------
// Launch
// ---------------------------------------------------------------------------
extern "C" void kernel_launch(void* const* d_in, const int* in_sizes, int n_in,
                              void* d_out, int out_size) {
    (void)in_sizes; (void)n_in; (void)out_size;
    const float* x  = (const float*)d_in[0];
    const float* wq = (const float*)d_in[1];
    const float* wk = (const float*)d_in[2];
    const float* wv = (const float*)d_in[3];
    const float* wo = (const float*)d_in[4];
    float* out = (float*)d_out;

    float* qkv;
    __half *abig, *wbig;
    cudaGetSymbolAddress((void**)&qkv,  g_qkv);
    cudaGetSymbolAddress((void**)&abig, g_abig);
    cudaGetSymbolAddress((void**)&wbig, g_wbig);

    cudaFuncSetAttribute(gemm_hmma,
                         cudaFuncAttributeMaxDynamicSharedMemorySize,
                         GEMM_SMEM_BYTES);
    cudaFuncSetAttribute(flash_mma_kernel,
                         cudaFuncAttributeMaxDynamicSharedMemorySize,
                         FLASH3_SMEM);

    const int n_act = BS * DD;
    const int n_w   = DD * DD;

    rope_table_kernel<<<(SS * NPAIR + 255) / 256, 256>>>();

    // x -> fp16 [hi|lo]; wq/wk/wv -> stacked hi-only weight buffer
    split2_act_kernel<<<(n_act + 255) / 256, 256>>>(x, abig, n_act);
    conv_w_kernel<<<(n_w + 255) / 256, 256>>>(wq, wbig, n_w);
    conv_w_kernel<<<(n_w + 255) / 256, 256>>>(wk, wbig + (size_t)DD * KW, n_w);
    conv_w_kernel<<<(n_w + 255) / 256, 256>>>(wv, wbig + (size_t)2 * DD * KW, n_w);

    // Fused QKV projection: [4096, 6144]
    dim3 qkv_grid((3 * DD) / 64, BS / 128);  // (96, 32)
    gemm_hmma<<<qkv_grid, 256, GEMM_SMEM_BYTES>>>(abig, wbig, qkv, 3 * DD);

    // RoPE + scale + fp16 (q,k) and transpose fp16 (v)
    qkv_rope_split_kernel<<<(BS * 1024 + 255) / 256, 256>>>();
    v_split_t_kernel<<<dim3(SS / 64, BB * HH), 256>>>();

    // single-term fp16 FA2 flash attention (writes fp16x2 activations)
    flash_mma_kernel<<<dim3(SS / 128, BB * HH), 256, FLASH3_SMEM>>>();

    // Output projection
    conv_w_kernel<<<(n_w + 255) / 256, 256>>>(wo, wbig, n_w);
    dim3 ogrid(DD / 64, BS / 128);  // (32, 32)
    gemm_hmma<<<ogrid, 256, GEMM_SMEM_BYTES>>>(abig, wbig, out, DD);
}

// round 14
// speedup vs baseline: 4.3289x; 1.4575x over previous
#include <cuda_runtime.h>
#include <cuda_bf16.h>
#include <cuda_fp16.h>
#include <math.h>
#include <stdint.h>

// Problem constants
#define BB 2
#define SS 2048
#define DD 2048
#define HH 16
#define HD 128
#define BS (BB * SS)        // 4096 tokens
#define NPAIR (HD / 2)      // 64 rope pairs per head
#define KA DD               // 2048: pure fp16 activations
#define KW DD               // 2048: weights hi only
#define ITERSG (KA / 64)    // 32 K-chunks of 64
#define STG 4               // cp.async pipeline stages
#define LOG2E 1.4426950408889634f
#define QK_SCALE 0.08838834764831845f

// ---------------------------------------------------------------------------
// Scratch (device globals -- no allocation allowed in kernel_launch)
// ---------------------------------------------------------------------------
__device__ float g_qkv[(size_t)BS * 3 * DD];         // fused QKV output [t][q|k|v]
__device__ float g_cos[SS * NPAIR];
__device__ float g_sin[SS * NPAIR];
__device__ __half g_act[(size_t)BS * KA];            // fp16 activations (x, then attn out)
__device__ __half g_wbig[(size_t)(3 * DD) * KW];     // fp16 weights
// Attention fp16 buffers: q hi, k hi [bh][s][d]; v hi transposed [bh][d][s]
__device__ __half g_qshi[(size_t)BS * DD];
__device__ __half g_kshi[(size_t)BS * DD];
__device__ __half g_vthi[(size_t)BS * DD];

// ---------------------------------------------------------------------------
// Helpers
// ---------------------------------------------------------------------------
__device__ __forceinline__ uint32_t smem_u32(const void* p) {
    uint32_t a;
    asm("{ .reg .u64 t; cvta.to.shared.u64 t, %1; cvt.u32.u64 %0, t; }"
        : "=r"(a) : "l"(p));
    return a;
}
#define CP_ASYNC16(smem, gptr) \
    asm volatile("cp.async.cg.shared.global [%0], [%1], 16;" \
                 :: "r"((uint32_t)(smem)), "l"((const void*)(gptr)) : "memory")
#define CP_COMMIT() asm volatile("cp.async.commit_group;" ::: "memory")

#define LDSM_X4(r0, r1, r2, r3, addr) \
    asm volatile("ldmatrix.sync.aligned.m8n8.x4.shared.b16 {%0,%1,%2,%3}, [%4];" \
                 : "=r"(r0), "=r"(r1), "=r"(r2), "=r"(r3) : "r"(addr))

#define MMA16816H(d, a, b0, b1) \
    asm volatile("mma.sync.aligned.m16n8k16.row.col.f32.f16.f16.f32 " \
                 "{%0,%1,%2,%3}, {%4,%5,%6,%7}, {%8,%9}, {%0,%1,%2,%3};" \
                 : "+f"((d)[0]), "+f"((d)[1]), "+f"((d)[2]), "+f"((d)[3]) \
                 : "r"((a)[0]), "r"((a)[1]), "r"((a)[2]), "r"((a)[3]),   \
                   "r"(b0), "r"(b1))

// Fast exp2 on FMA pipe: t <= 0, clamp at -126; |rel err| ~ 3e-6
__device__ __forceinline__ float exp2_fast(float t) {
    t = fmaxf(t, -126.0f);
    float r = t + 12582912.0f;
    int e = __float_as_int(r) - 0x4B400000;
    float f = t - (r - 12582912.0f);
    float p = 0.0013333558f;
    p = fmaf(p, f, 0.0096181291f);
    p = fmaf(p, f, 0.0555041087f);
    p = fmaf(p, f, 0.2402265070f);
    p = fmaf(p, f, 0.6931471806f);
    p = fmaf(p, f, 1.0f);
    return __int_as_float((e + 127) << 23) * p;
}
__device__ __forceinline__ uint32_t pack_h2(float a, float b) {
    __half2 h2 = __floats2half2_rn(a, b);
    return *reinterpret_cast<uint32_t*>(&h2);
}

// ---------------------------------------------------------------------------
// RoPE table (double precision generation)
// ---------------------------------------------------------------------------
__global__ void rope_table_kernel() {
    int idx = blockIdx.x * blockDim.x + threadIdx.x;
    if (idx >= SS * NPAIR) return;
    int s = idx / NPAIR;
    int i = idx - s * NPAIR;
    double freq = (double)s * exp(((double)(-2 * i) / (double)HD) * log(10000.0));
    g_cos[idx] = (float)cos(freq);
    g_sin[idx] = (float)sin(freq);
}

// ---------------------------------------------------------------------------
// fp32 -> fp16 convert (used for x and all weights)
// ---------------------------------------------------------------------------
__global__ void conv_h_kernel(const float* __restrict__ src,
                              __half* __restrict__ dst, int n) {
    int idx = blockIdx.x * blockDim.x + threadIdx.x;
    if (idx >= n) return;
    dst[idx] = __float2half_rn(src[idx]);
}

// ---------------------------------------------------------------------------
// Fused RoPE + scale + fp16 (q hi, k hi) straight out of g_qkv.
// ---------------------------------------------------------------------------
__global__ void qkv_rope_split_kernel() {
    int idx = blockIdx.x * blockDim.x + threadIdx.x;
    if (idx >= BS * 1024) return;
    int t = idx >> 10;
    int p = idx & 1023;
    int h = p >> 6;
    int i = p & 63;
    int s = t & (SS - 1);
    int b = t >> 11;
    float c  = g_cos[(s << 6) + i];
    float sn = g_sin[(s << 6) + i];
    size_t src = (size_t)t * (3 * DD) + h * HD + 2 * i;
    float q0 = g_qkv[src],        q1 = g_qkv[src + 1];
    float k0 = g_qkv[src + DD],   k1 = g_qkv[src + DD + 1];
    float qo0 = (q0 * c - q1 * sn) * QK_SCALE;
    float qo1 = (q0 * sn + q1 * c) * QK_SCALE;
    float ko0 = k0 * c - k1 * sn;
    float ko1 = k0 * sn + k1 * c;
    size_t dst = ((size_t)(b * HH + h) * SS + s) * HD + 2 * i;
    *reinterpret_cast<__half2*>(&g_qshi[dst]) = __floats2half2_rn(qo0, qo1);
    *reinterpret_cast<__half2*>(&g_kshi[dst]) = __floats2half2_rn(ko0, ko1);
}

// ---------------------------------------------------------------------------
// V transpose: g_qkv[t][4096 + h*128 + d] -> g_vthi fp16 [bh][d][s]
// ---------------------------------------------------------------------------
__global__ __launch_bounds__(256) void v_split_t_kernel() {
    __shared__ float st[64][129];
    const int s0 = blockIdx.x * 64;
    const int bh = blockIdx.y;
    const int b = bh >> 4, h = bh & 15;
    const float* src = g_qkv + (size_t)(b * SS + s0) * (3 * DD) + 2 * DD + h * HD;
    const int tid = threadIdx.x;
#pragma unroll
    for (int i = 0; i < 32; i++) {
        int id = tid + 256 * i;
        int sl = id >> 7, d = id & 127;
        st[sl][d] = src[(size_t)sl * (3 * DD) + d];
    }
    __syncthreads();
    const int d = tid >> 1, half = tid & 1;
    __half hibuf[32];
#pragma unroll
    for (int j = 0; j < 32; j++)
        hibuf[j] = __float2half(st[half * 32 + j][d]);
    size_t dst = ((size_t)bh * HD + d) * SS + s0 + half * 32;
    uint4* ph = reinterpret_cast<uint4*>(&g_vthi[dst]);
#pragma unroll
    for (int tch = 0; tch < 4; tch++)
        ph[tch] = reinterpret_cast<uint4*>(hibuf)[tch];
}

// ---------------------------------------------------------------------------
// HMMA GEMM (pure fp16): C[4096, N] = A[4096,2048] * B[N,2048]^T, ldc = N
// 128x64 CTA tile (8 warps, 4m x 2n), BK=64, 4-stage cp.async pipeline.
// ---------------------------------------------------------------------------
#define TILE_STAGE_BYTES 24576
#define GEMM_SMEM_BYTES (STG * TILE_STAGE_BYTES)

__device__ __forceinline__ void issue_stage(
    uint32_t sb, int s, int tid,
    const __half* __restrict__ Ag,
    const __half* __restrict__ Bg)
{
    if (s < ITERSG) {
        const int k0 = s * 64;
        const int slot = s & (STG - 1);
        uint32_t abase = sb + slot * TILE_STAGE_BYTES;
        uint32_t bbase = abase + 16384;
#pragma unroll
        for (int i = 0; i < 4; i++) {
            int id = tid + 256 * i;
            int row = id >> 3;
            int c = id & 7;
            uint32_t off = (uint32_t)(row * 128 + ((c ^ (row & 7)) << 4));
            CP_ASYNC16(abase + off, Ag + (size_t)row * KA + k0 + c * 8);
        }
#pragma unroll
        for (int i = 0; i < 2; i++) {
            int id = tid + 256 * i;
            int row = id >> 3;
            int c = id & 7;
            uint32_t off = (uint32_t)(row * 128 + ((c ^ (row & 7)) << 4));
            CP_ASYNC16(bbase + off, Bg + (size_t)row * KW + k0 + c * 8);
        }
    }
    CP_COMMIT();
}

__global__ __launch_bounds__(256, 2)
void gemm_hmma(const __half* __restrict__ A,
               const __half* __restrict__ Bw,
               float* __restrict__ C, int ldc)
{
    extern __shared__ char smraw[];
    uint32_t sb = smem_u32(smraw);
    const int tid  = threadIdx.x;
    const int lane = tid & 31;
    const int warp = tid >> 5;
    const int wm = warp & 3;
    const int wn = warp >> 2;
    const int m0 = blockIdx.y * 128;
    const int n0 = blockIdx.x * 64;
    const __half* Ag = A  + (size_t)m0 * KA;
    const __half* Bg = Bw + (size_t)n0 * KW;

    float acc[2][4][4];
#pragma unroll
    for (int a = 0; a < 2; a++)
#pragma unroll
        for (int b = 0; b < 4; b++)
#pragma unroll
            for (int c = 0; c < 4; c++) acc[a][b][c] = 0.f;

    issue_stage(sb, 0, tid, Ag, Bg);
    issue_stage(sb, 1, tid, Ag, Bg);
    issue_stage(sb, 2, tid, Ag, Bg);

    for (int s = 0; s < ITERSG; s++) {
        asm volatile("cp.async.wait_group 2;" ::: "memory");
        __syncthreads();
        const int slot = s & (STG - 1);
        uint32_t abase = sb + slot * TILE_STAGE_BYTES;
        uint32_t bbase = abase + 16384;

#pragma unroll
        for (int ks = 0; ks < 4; ks++) {
            uint32_t af[2][4];
            uint32_t bf[4][2];
#pragma unroll
            for (int mt = 0; mt < 2; mt++) {
                int row = wm * 32 + mt * 16 + (lane & 15);
                int ch  = ks * 2 + (lane >> 4);
                uint32_t ad = abase + (uint32_t)(row * 128 +
                                  ((ch ^ (row & 7)) << 4));
                LDSM_X4(af[mt][0], af[mt][1], af[mt][2], af[mt][3], ad);
            }
#pragma unroll
            for (int np = 0; np < 2; np++) {
                int row = wn * 32 + np * 16 + ((lane >> 4) << 3) + (lane & 7);
                int ch  = ks * 2 + ((lane >> 3) & 1);
                uint32_t bd = bbase + (uint32_t)(row * 128 +
                                  ((ch ^ (row & 7)) << 4));
                LDSM_X4(bf[2 * np][0], bf[2 * np][1],
                        bf[2 * np + 1][0], bf[2 * np + 1][1], bd);
            }
#pragma unroll
            for (int mt = 0; mt < 2; mt++)
#pragma unroll
                for (int nt = 0; nt < 4; nt++)
                    MMA16816H(acc[mt][nt], af[mt], bf[nt][0], bf[nt][1]);
        }
        issue_stage(sb, s + 3, tid, Ag, Bg);
    }

#pragma unroll
    for (int mt = 0; mt < 2; mt++) {
#pragma unroll
        for (int nt = 0; nt < 4; nt++) {
            int row = m0 + wm * 32 + mt * 16 + (lane >> 2);
            int col = n0 + wn * 32 + nt * 8 + (lane & 3) * 2;
            float2 v0 = make_float2(acc[mt][nt][0], acc[mt][nt][1]);
            float2 v1 = make_float2(acc[mt][nt][2], acc[mt][nt][3]);
            *reinterpret_cast<float2*>(&C[(size_t)row * ldc + col]) = v0;
            *reinterpret_cast<float2*>(&C[(size_t)(row + 8) * ldc + col]) = v1;
        }
    }
}

// ---------------------------------------------------------------------------
// FA2-style flash attention, single-term fp16:
// QK: q_hi . k_hi (k' = 128).  PV: p_hi . v_hi.
// smem: Q (32KB) + K (16KB) + V (16KB) = 64KB.
// ---------------------------------------------------------------------------
#define SQHI 0
#define SKHI 32768
#define SVHI 49152
#define FLASH3_SMEM 65536

__device__ __forceinline__ void issue_q_tile(
    uint32_t sb, const __half* __restrict__ ghi, int tid)
{
#pragma unroll
    for (int i = 0; i < 8; i++) {
        int id = tid + 256 * i;
        int row = id >> 4, c = id & 15;
        uint32_t off = (uint32_t)(row * 256 + ((c >> 3) << 7) +
                                  (((c & 7) ^ (row & 7)) << 4));
        CP_ASYNC16(sb + SQHI + off, ghi + (size_t)row * HD + c * 8);
    }
}
__device__ __forceinline__ void issue_k_tile(
    uint32_t sb, const __half* __restrict__ ghi, int tid)
{
#pragma unroll
    for (int i = 0; i < 4; i++) {
        int id = tid + 256 * i;
        int row = id >> 4, c = id & 15;
        uint32_t off = (uint32_t)(row * 256 + ((c >> 3) << 7) +
                                  (((c & 7) ^ (row & 7)) << 4));
        CP_ASYNC16(sb + SKHI + off, ghi + (size_t)row * HD + c * 8);
    }
}
__device__ __forceinline__ void issue_v_tile(
    uint32_t sb, const __half* __restrict__ ghi, int tid)
{
#pragma unroll
    for (int i = 0; i < 4; i++) {
        int id = tid + 256 * i;
        int row = id >> 3, c = id & 7;
        uint32_t off = (uint32_t)(row * 128 + ((c ^ (row & 7)) << 4));
        CP_ASYNC16(sb + SVHI + off, ghi + (size_t)row * SS + c * 8);
    }
}

__global__ __launch_bounds__(256, 1) void flash_mma_kernel() {
    extern __shared__ char smr[];
    uint32_t sb = smem_u32(smr);
    const int tid = threadIdx.x, lane = tid & 31, warp = tid >> 5;
    const int q0 = blockIdx.x * 128;
    const int bh = blockIdx.y;

    const __half* qhiG = g_qshi + ((size_t)bh * SS + q0) * HD;
    const __half* khiB = g_kshi + (size_t)bh * SS * HD;
    const __half* vhiB = g_vthi + (size_t)bh * HD * SS;

    issue_q_tile(sb, qhiG, tid);
    CP_COMMIT();
    issue_k_tile(sb, khiB, tid);
    CP_COMMIT();

    float m0v = -1e30f, m8v = -1e30f, l0 = 0.f, l8 = 0.f;
    float o[16][4];
#pragma unroll
    for (int nt = 0; nt < 16; nt++)
#pragma unroll
        for (int c = 0; c < 4; c++) o[nt][c] = 0.f;

    for (int t = 0; t < 32; t++) {
        asm volatile("cp.async.wait_group 0;" ::: "memory");
        __syncthreads();
        issue_v_tile(sb, vhiB + t * 64, tid);
        CP_COMMIT();

        // ---- QK^T: warp rows 16 x keys 64, k' = 128 ----
        float sc[8][4];
#pragma unroll
        for (int nt = 0; nt < 8; nt++)
#pragma unroll
            for (int c = 0; c < 4; c++) sc[nt][c] = 0.f;

#pragma unroll
        for (int pk = 0; pk < 8; pk++) {
            uint32_t af[4], bfr[8][2];
            {
                int row = warp * 16 + (lane & 15);
                int c0 = pk * 2 + (lane >> 4);
                uint32_t ad = sb + SQHI + (uint32_t)(row * 256 + ((c0 >> 3) << 7) +
                                  (((c0 & 7) ^ (row & 7)) << 4));
                LDSM_X4(af[0], af[1], af[2], af[3], ad);
            }
#pragma unroll
            for (int np = 0; np < 4; np++) {
                int row = np * 16 + ((lane >> 4) << 3) + (lane & 7);
                int c0 = pk * 2 + ((lane >> 3) & 1);
                uint32_t bd = sb + SKHI + (uint32_t)(row * 256 + ((c0 >> 3) << 7) +
                                  (((c0 & 7) ^ (row & 7)) << 4));
                LDSM_X4(bfr[2 * np][0], bfr[2 * np][1],
                        bfr[2 * np + 1][0], bfr[2 * np + 1][1], bd);
            }
#pragma unroll
            for (int nt = 0; nt < 8; nt++)
                MMA16816H(sc[nt], af, bfr[nt][0], bfr[nt][1]);
        }

        // ---- in-register online softmax ----
        float mx0 = -1e30f, mx8 = -1e30f;
#pragma unroll
        for (int nt = 0; nt < 8; nt++) {
            mx0 = fmaxf(mx0, fmaxf(sc[nt][0], sc[nt][1]));
            mx8 = fmaxf(mx8, fmaxf(sc[nt][2], sc[nt][3]));
        }
        mx0 = fmaxf(mx0, __shfl_xor_sync(0xffffffff, mx0, 1));
        mx0 = fmaxf(mx0, __shfl_xor_sync(0xffffffff, mx0, 2));
        mx8 = fmaxf(mx8, __shfl_xor_sync(0xffffffff, mx8, 1));
        mx8 = fmaxf(mx8, __shfl_xor_sync(0xffffffff, mx8, 2));
        float mn0 = fmaxf(m0v, mx0), mn8 = fmaxf(m8v, mx8);
        float al0 = exp2_fast((m0v - mn0) * LOG2E);
        float al8 = exp2_fast((m8v - mn8) * LOG2E);
        float s0 = 0.f, s8 = 0.f;
#pragma unroll
        for (int nt = 0; nt < 8; nt++) {
            float p0 = exp2_fast((sc[nt][0] - mn0) * LOG2E);
            float p1 = exp2_fast((sc[nt][1] - mn0) * LOG2E);
            float p2 = exp2_fast((sc[nt][2] - mn8) * LOG2E);
            float p3 = exp2_fast((sc[nt][3] - mn8) * LOG2E);
            sc[nt][0] = p0; sc[nt][1] = p1; sc[nt][2] = p2; sc[nt][3] = p3;
            s0 += p0 + p1; s8 += p2 + p3;
        }
        s0 += __shfl_xor_sync(0xffffffff, s0, 1);
        s0 += __shfl_xor_sync(0xffffffff, s0, 2);
        s8 += __shfl_xor_sync(0xffffffff, s8, 1);
        s8 += __shfl_xor_sync(0xffffffff, s8, 2);
        l0 = l0 * al0 + s0; m0v = mn0;
        l8 = l8 * al8 + s8; m8v = mn8;

        // Pack P (fp16) into PV A-fragments
        uint32_t pHI[4][4];
#pragma unroll
        for (int kc = 0; kc < 4; kc++) {
            pHI[kc][0] = pack_h2(sc[2 * kc][0],     sc[2 * kc][1]);
            pHI[kc][1] = pack_h2(sc[2 * kc][2],     sc[2 * kc][3]);
            pHI[kc][2] = pack_h2(sc[2 * kc + 1][0], sc[2 * kc + 1][1]);
            pHI[kc][3] = pack_h2(sc[2 * kc + 1][2], sc[2 * kc + 1][3]);
        }

        // Rescale O
#pragma unroll
        for (int nt = 0; nt < 16; nt++) {
            o[nt][0] *= al0; o[nt][1] *= al0;
            o[nt][2] *= al8; o[nt][3] *= al8;
        }

        __syncthreads();  // all warps done reading K smem
        if (t + 1 < 32)
            issue_k_tile(sb, khiB + (size_t)(t + 1) * 64 * HD, tid);
        CP_COMMIT();
        asm volatile("cp.async.wait_group 1;" ::: "memory");  // V(t) ready
        __syncthreads();

        // ---- PV: rows 16 x d 128, single fp16 term ----
#pragma unroll
        for (int kc = 0; kc < 4; kc++) {
            const uint32_t* afr = pHI[kc];
            const int ch = kc * 2 + ((lane >> 3) & 1);
#pragma unroll
            for (int half = 0; half < 2; half++) {
                uint32_t bfr[8][2];
#pragma unroll
                for (int np = 0; np < 4; np++) {
                    int row = half * 64 + np * 16 +
                              ((lane >> 4) << 3) + (lane & 7);
                    uint32_t bd = sb + SVHI + (uint32_t)(row * 128 +
                                      ((ch ^ (row & 7)) << 4));
                    LDSM_X4(bfr[2 * np][0], bfr[2 * np][1],
                            bfr[2 * np + 1][0], bfr[2 * np + 1][1], bd);
                }
#pragma unroll
                for (int i = 0; i < 8; i++)
                    MMA16816H(o[half * 8 + i], afr, bfr[i][0], bfr[i][1]);
            }
        }
    }

    // Epilogue: normalize; write fp16 directly into g_act for out-proj
    const int b = bh >> 4, h = bh & 15;
    const int row = warp * 16 + (lane >> 2);
    float inv0 = 1.0f / l0;
    float inv8 = 1.0f / l8;
#pragma unroll
    for (int nt = 0; nt < 16; nt++) {
        int col = nt * 8 + (lane & 3) * 2;
        size_t a0 = (size_t)(b * SS + q0 + row) * KA + h * HD + col;
        *reinterpret_cast<uint32_t*>(&g_act[a0]) =
            pack_h2(o[nt][0] * inv0, o[nt][1] * inv0);
        *reinterpret_cast<uint32_t*>(&g_act[a0 + (size_t)8 * KA]) =
            pack_h2(o[nt][2] * inv8, o[nt][3] * inv8);
    }
}

// ---------------------------------------------------------------------------
// Launch
// ---------------------------------------------------------------------------
extern "C" void kernel_launch(void* const* d_in, const int* in_sizes, int n_in,
                              void* d_out, int out_size) {
    (void)in_sizes; (void)n_in; (void)out_size;
    const float* x  = (const float*)d_in[0];
    const float* wq = (const float*)d_in[1];
    const float* wk = (const float*)d_in[2];
    const float* wv = (const float*)d_in[3];
    const float* wo = (const float*)d_in[4];
    float* out = (float*)d_out;

    float* qkv;
    __half *act, *wbig;
    cudaGetSymbolAddress((void**)&qkv,  g_qkv);
    cudaGetSymbolAddress((void**)&act,  g_act);
    cudaGetSymbolAddress((void**)&wbig, g_wbig);

    cudaFuncSetAttribute(gemm_hmma,
                         cudaFuncAttributeMaxDynamicSharedMemorySize,
                         GEMM_SMEM_BYTES);
    cudaFuncSetAttribute(flash_mma_kernel,
                         cudaFuncAttributeMaxDynamicSharedMemorySize,
                         FLASH3_SMEM);

    const int n_act = BS * DD;
    const int n_w   = DD * DD;

    rope_table_kernel<<<(SS * NPAIR + 255) / 256, 256>>>();

    // x -> fp16; wq/wk/wv -> stacked fp16 weight buffer
    conv_h_kernel<<<(n_act + 255) / 256, 256>>>(x, act, n_act);
    conv_h_kernel<<<(n_w + 255) / 256, 256>>>(wq, wbig, n_w);
    conv_h_kernel<<<(n_w + 255) / 256, 256>>>(wk, wbig + (size_t)DD * KW, n_w);
    conv_h_kernel<<<(n_w + 255) / 256, 256>>>(wv, wbig + (size_t)2 * DD * KW, n_w);

    // Fused QKV projection: [4096, 6144]
    dim3 qkv_grid((3 * DD) / 64, BS / 128);  // (96, 32)
    gemm_hmma<<<qkv_grid, 256, GEMM_SMEM_BYTES>>>(act, wbig, qkv, 3 * DD);

    // RoPE + scale + fp16 (q,k) and transpose fp16 (v)
    qkv_rope_split_kernel<<<(BS * 1024 + 255) / 256, 256>>>();
    v_split_t_kernel<<<dim3(SS / 64, BB * HH), 256>>>();

    // single-term fp16 FA2 flash attention (overwrites g_act with attn out)
    flash_mma_kernel<<<dim3(SS / 128, BB * HH), 256, FLASH3_SMEM>>>();

    // Output projection
    conv_h_kernel<<<(n_w + 255) / 256, 256>>>(wo, wbig, n_w);
    dim3 ogrid(DD / 64, BS / 128);  // (32, 32)
    gemm_hmma<<<ogrid, 256, GEMM_SMEM_BYTES>>>(act, wbig, out, DD);
}

// round 16
// speedup vs baseline: 4.4252x; 1.0223x over previous
#include <cuda_runtime.h>
#include <cuda_bf16.h>
#include <cuda_fp16.h>
#include <math.h>
#include <stdint.h>

// Problem constants
#define BB 2
#define SS 2048
#define DD 2048
#define HH 16
#define HD 128
#define BS (BB * SS)        // 4096 tokens
#define NPAIR (HD / 2)      // 64 rope pairs per head
#define KA DD               // 2048: pure fp16 K for projections
#define KW DD
#define ITERSG (KA / 64)    // 32 K-chunks of 64
#define STG 4               // cp.async pipeline stages
#define LOG2E 1.4426950408889634f
#define QK_SCALE 0.08838834764831845f

// ---------------------------------------------------------------------------
// Scratch (device globals -- no allocation allowed in kernel_launch)
// ---------------------------------------------------------------------------
__device__ float g_cos[SS * NPAIR];
__device__ float g_sin[SS * NPAIR];
__device__ __half g_act[(size_t)BS * KA];            // fp16 activations (x, then attn out)
__device__ __half g_wbig[(size_t)(4 * DD) * KW];     // fp16 weights [wq|wk|wv|wo]
// Attention fp16 buffers: q, k [bh][s][d]; v staged [bh][s][d]; v^T [bh][d][s]
__device__ __half g_qshi[(size_t)BS * DD];
__device__ __half g_kshi[(size_t)BS * DD];
__device__ __half g_vs[(size_t)BS * DD];
__device__ __half g_vthi[(size_t)BS * DD];

// ---------------------------------------------------------------------------
// Helpers
// ---------------------------------------------------------------------------
__device__ __forceinline__ uint32_t smem_u32(const void* p) {
    uint32_t a;
    asm("{ .reg .u64 t; cvta.to.shared.u64 t, %1; cvt.u32.u64 %0, t; }"
        : "=r"(a) : "l"(p));
    return a;
}
#define CP_ASYNC16(smem, gptr) \
    asm volatile("cp.async.cg.shared.global [%0], [%1], 16;" \
                 :: "r"((uint32_t)(smem)), "l"((const void*)(gptr)) : "memory")
#define CP_COMMIT() asm volatile("cp.async.commit_group;" ::: "memory")

#define LDSM_X4(r0, r1, r2, r3, addr) \
    asm volatile("ldmatrix.sync.aligned.m8n8.x4.shared.b16 {%0,%1,%2,%3}, [%4];" \
                 : "=r"(r0), "=r"(r1), "=r"(r2), "=r"(r3) : "r"(addr))

#define MMA16816H(d, a, b0, b1) \
    asm volatile("mma.sync.aligned.m16n8k16.row.col.f32.f16.f16.f32 " \
                 "{%0,%1,%2,%3}, {%4,%5,%6,%7}, {%8,%9}, {%0,%1,%2,%3};" \
                 : "+f"((d)[0]), "+f"((d)[1]), "+f"((d)[2]), "+f"((d)[3]) \
                 : "r"((a)[0]), "r"((a)[1]), "r"((a)[2]), "r"((a)[3]),   \
                   "r"(b0), "r"(b1))

// Fast exp2 on FMA pipe: t <= 0, clamp at -126; |rel err| ~ 3e-6
__device__ __forceinline__ float exp2_fast(float t) {
    t = fmaxf(t, -126.0f);
    float r = t + 12582912.0f;
    int e = __float_as_int(r) - 0x4B400000;
    float f = t - (r - 12582912.0f);
    float p = 0.0013333558f;
    p = fmaf(p, f, 0.0096181291f);
    p = fmaf(p, f, 0.0555041087f);
    p = fmaf(p, f, 0.2402265070f);
    p = fmaf(p, f, 0.6931471806f);
    p = fmaf(p, f, 1.0f);
    return __int_as_float((e + 127) << 23) * p;
}
__device__ __forceinline__ uint32_t pack_h2(float a, float b) {
    __half2 h2 = __floats2half2_rn(a, b);
    return *reinterpret_cast<uint32_t*>(&h2);
}

// ---------------------------------------------------------------------------
// RoPE table (double precision generation)
// ---------------------------------------------------------------------------
__global__ void rope_table_kernel() {
    int idx = blockIdx.x * blockDim.x + threadIdx.x;
    if (idx >= SS * NPAIR) return;
    int s = idx / NPAIR;
    int i = idx - s * NPAIR;
    double freq = (double)s * exp(((double)(-2 * i) / (double)HD) * log(10000.0));
    g_cos[idx] = (float)cos(freq);
    g_sin[idx] = (float)sin(freq);
}

// ---------------------------------------------------------------------------
// fp32 -> fp16 converts: x (single), and all 4 weights in one launch
// ---------------------------------------------------------------------------
__global__ void conv_h_kernel(const float* __restrict__ src,
                              __half* __restrict__ dst, int n) {
    int idx = blockIdx.x * blockDim.x + threadIdx.x;
    if (idx >= n) return;
    dst[idx] = __float2half_rn(src[idx]);
}
// n_w = 2^22 per weight; 4 weights stacked into g_wbig
__global__ void conv_w4_kernel(const float* __restrict__ w0,
                               const float* __restrict__ w1,
                               const float* __restrict__ w2,
                               const float* __restrict__ w3,
                               __half* __restrict__ dst) {
    int idx = blockIdx.x * blockDim.x + threadIdx.x;
    if (idx >= 4 * DD * DD) return;
    int seg = idx >> 22;
    int off = idx & (DD * DD - 1);
    const float* src = (seg == 0) ? w0 : (seg == 1) ? w1 : (seg == 2) ? w2 : w3;
    dst[idx] = __float2half_rn(src[off]);
}

// ---------------------------------------------------------------------------
// V transpose (fp16 -> fp16): g_vs [bh][s][d] -> g_vthi [bh][d][s]
// Tile 64 rows(s) x 128 cols(d) = 1024 chunks of 16B (16 chunks per row).
// ---------------------------------------------------------------------------
__global__ __launch_bounds__(256) void v_t_kernel() {
    __shared__ __half st[64][136];
    const int s0 = blockIdx.x * 64;
    const int bh = blockIdx.y;
    const __half* src = g_vs + ((size_t)bh * SS + s0) * HD;
    const int tid = threadIdx.x;
#pragma unroll
    for (int i = 0; i < 4; i++) {
        int id = tid + 256 * i;          // 0..1023
        int r = id >> 4;                 // 0..63 (16 chunks per 128-half row)
        int c8 = id & 15;                // chunk within row
        *reinterpret_cast<uint4*>(&st[r][c8 * 8]) =
            *reinterpret_cast<const uint4*>(src + (size_t)r * HD + c8 * 8);
    }
    __syncthreads();
    const int d = tid >> 1, half = tid & 1;
    __half buf[32];
#pragma unroll
    for (int j = 0; j < 32; j++)
        buf[j] = st[half * 32 + j][d];
    size_t dst = ((size_t)bh * HD + d) * SS + s0 + half * 32;
    uint4* ph = reinterpret_cast<uint4*>(&g_vthi[dst]);
#pragma unroll
    for (int tch = 0; tch < 4; tch++)
        ph[tch] = reinterpret_cast<uint4*>(buf)[tch];
}

// ---------------------------------------------------------------------------
// HMMA GEMM (pure fp16): A[4096,2048] * B[N,2048]^T.
// mode 0: C fp32, ldc = N (output projection).
// mode 1: fused QKV epilogue -- RoPE+scale+fp16 write to q/k/v buffers.
// ---------------------------------------------------------------------------
#define TILE_STAGE_BYTES 24576
#define GEMM_SMEM_BYTES (STG * TILE_STAGE_BYTES)

__device__ __forceinline__ void qkv_write(int row, int col, float x0, float x1) {
    const int b = row >> 11, s = row & (SS - 1);
    if (col < 2 * DD) {
        const int which = col >> 11;       // 0 = q, 1 = k
        const int cc = col & (DD - 1);
        const int h = cc >> 7, d = cc & 127;
        const int i = d >> 1;
        const float c  = g_cos[(s << 6) + i];
        const float sn = g_sin[(s << 6) + i];
        float o0 = x0 * c - x1 * sn;
        float o1 = x0 * sn + x1 * c;
        size_t dst = ((size_t)(b * HH + h) * SS + s) * HD + d;
        if (which == 0) {
            *reinterpret_cast<uint32_t*>(&g_qshi[dst]) =
                pack_h2(o0 * QK_SCALE, o1 * QK_SCALE);
        } else {
            *reinterpret_cast<uint32_t*>(&g_kshi[dst]) = pack_h2(o0, o1);
        }
    } else {
        const int cc = col - 2 * DD;
        const int h = cc >> 7, d = cc & 127;
        size_t dst = ((size_t)(b * HH + h) * SS + s) * HD + d;
        *reinterpret_cast<uint32_t*>(&g_vs[dst]) = pack_h2(x0, x1);
    }
}

__device__ __forceinline__ void issue_stage(
    uint32_t sb, int s, int tid,
    const __half* __restrict__ Ag,
    const __half* __restrict__ Bg)
{
    if (s < ITERSG) {
        const int k0 = s * 64;
        const int slot = s & (STG - 1);
        uint32_t abase = sb + slot * TILE_STAGE_BYTES;
        uint32_t bbase = abase + 16384;
#pragma unroll
        for (int i = 0; i < 4; i++) {
            int id = tid + 256 * i;
            int row = id >> 3;
            int c = id & 7;
            uint32_t off = (uint32_t)(row * 128 + ((c ^ (row & 7)) << 4));
            CP_ASYNC16(abase + off, Ag + (size_t)row * KA + k0 + c * 8);
        }
#pragma unroll
        for (int i = 0; i < 2; i++) {
            int id = tid + 256 * i;
            int row = id >> 3;
            int c = id & 7;
            uint32_t off = (uint32_t)(row * 128 + ((c ^ (row & 7)) << 4));
            CP_ASYNC16(bbase + off, Bg + (size_t)row * KW + k0 + c * 8);
        }
    }
    CP_COMMIT();
}

__global__ __launch_bounds__(256, 2)
void gemm_hmma(const __half* __restrict__ A,
               const __half* __restrict__ Bw,
               float* __restrict__ C, int ldc, int mode)
{
    extern __shared__ char smraw[];
    uint32_t sb = smem_u32(smraw);
    const int tid  = threadIdx.x;
    const int lane = tid & 31;
    const int warp = tid >> 5;
    const int wm = warp & 3;
    const int wn = warp >> 2;
    const int m0 = blockIdx.y * 128;
    const int n0 = blockIdx.x * 64;
    const __half* Ag = A  + (size_t)m0 * KA;
    const __half* Bg = Bw + (size_t)n0 * KW;

    float acc[2][4][4];
#pragma unroll
    for (int a = 0; a < 2; a++)
#pragma unroll
        for (int b = 0; b < 4; b++)
#pragma unroll
            for (int c = 0; c < 4; c++) acc[a][b][c] = 0.f;

    issue_stage(sb, 0, tid, Ag, Bg);
    issue_stage(sb, 1, tid, Ag, Bg);
    issue_stage(sb, 2, tid, Ag, Bg);

    for (int s = 0; s < ITERSG; s++) {
        asm volatile("cp.async.wait_group 2;" ::: "memory");
        __syncthreads();
        const int slot = s & (STG - 1);
        uint32_t abase = sb + slot * TILE_STAGE_BYTES;
        uint32_t bbase = abase + 16384;

#pragma unroll
        for (int ks = 0; ks < 4; ks++) {
            uint32_t af[2][4];
            uint32_t bf[4][2];
#pragma unroll
            for (int mt = 0; mt < 2; mt++) {
                int row = wm * 32 + mt * 16 + (lane & 15);
                int ch  = ks * 2 + (lane >> 4);
                uint32_t ad = abase + (uint32_t)(row * 128 +
                                  ((ch ^ (row & 7)) << 4));
                LDSM_X4(af[mt][0], af[mt][1], af[mt][2], af[mt][3], ad);
            }
#pragma unroll
            for (int np = 0; np < 2; np++) {
                int row = wn * 32 + np * 16 + ((lane >> 4) << 3) + (lane & 7);
                int ch  = ks * 2 + ((lane >> 3) & 1);
                uint32_t bd = bbase + (uint32_t)(row * 128 +
                                  ((ch ^ (row & 7)) << 4));
                LDSM_X4(bf[2 * np][0], bf[2 * np][1],
                        bf[2 * np + 1][0], bf[2 * np + 1][1], bd);
            }
#pragma unroll
            for (int mt = 0; mt < 2; mt++)
#pragma unroll
                for (int nt = 0; nt < 4; nt++)
                    MMA16816H(acc[mt][nt], af[mt], bf[nt][0], bf[nt][1]);
        }
        issue_stage(sb, s + 3, tid, Ag, Bg);
    }

    if (mode == 0) {
#pragma unroll
        for (int mt = 0; mt < 2; mt++) {
#pragma unroll
            for (int nt = 0; nt < 4; nt++) {
                int row = m0 + wm * 32 + mt * 16 + (lane >> 2);
                int col = n0 + wn * 32 + nt * 8 + (lane & 3) * 2;
                float2 v0 = make_float2(acc[mt][nt][0], acc[mt][nt][1]);
                float2 v1 = make_float2(acc[mt][nt][2], acc[mt][nt][3]);
                *reinterpret_cast<float2*>(&C[(size_t)row * ldc + col]) = v0;
                *reinterpret_cast<float2*>(&C[(size_t)(row + 8) * ldc + col]) = v1;
            }
        }
    } else {
        // Fused QKV epilogue: RoPE + scale + fp16 write (cols are rope pairs)
#pragma unroll
        for (int mt = 0; mt < 2; mt++) {
#pragma unroll
            for (int nt = 0; nt < 4; nt++) {
                int row = m0 + wm * 32 + mt * 16 + (lane >> 2);
                int col = n0 + wn * 32 + nt * 8 + (lane & 3) * 2;
                qkv_write(row,     col, acc[mt][nt][0], acc[mt][nt][1]);
                qkv_write(row + 8, col, acc[mt][nt][2], acc[mt][nt][3]);
            }
        }
    }
}

// ---------------------------------------------------------------------------
// FA2-style flash attention, fp16 (unchanged from R14):
// QK: q.k (k' = 128).  PV: p.v.
// smem: Q (32KB) + K (16KB) + V (16KB) = 64KB.
// ---------------------------------------------------------------------------
#define SQHI 0
#define SKHI 32768
#define SVHI 49152
#define FLASH3_SMEM 65536

__device__ __forceinline__ void issue_q_tile(
    uint32_t sb, const __half* __restrict__ ghi, int tid)
{
#pragma unroll
    for (int i = 0; i < 8; i++) {
        int id = tid + 256 * i;
        int row = id >> 4, c = id & 15;
        uint32_t off = (uint32_t)(row * 256 + ((c >> 3) << 7) +
                                  (((c & 7) ^ (row & 7)) << 4));
        CP_ASYNC16(sb + SQHI + off, ghi + (size_t)row * HD + c * 8);
    }
}
__device__ __forceinline__ void issue_k_tile(
    uint32_t sb, const __half* __restrict__ ghi, int tid)
{
#pragma unroll
    for (int i = 0; i < 4; i++) {
        int id = tid + 256 * i;
        int row = id >> 4, c = id & 15;
        uint32_t off = (uint32_t)(row * 256 + ((c >> 3) << 7) +
                                  (((c & 7) ^ (row & 7)) << 4));
        CP_ASYNC16(sb + SKHI + off, ghi + (size_t)row * HD + c * 8);
    }
}
__device__ __forceinline__ void issue_v_tile(
    uint32_t sb, const __half* __restrict__ ghi, int tid)
{
#pragma unroll
    for (int i = 0; i < 4; i++) {
        int id = tid + 256 * i;
        int row = id >> 3, c = id & 7;
        uint32_t off = (uint32_t)(row * 128 + ((c ^ (row & 7)) << 4));
        CP_ASYNC16(sb + SVHI + off, ghi + (size_t)row * SS + c * 8);
    }
}

__global__ __launch_bounds__(256, 1) void flash_mma_kernel() {
    extern __shared__ char smr[];
    uint32_t sb = smem_u32(smr);
    const int tid = threadIdx.x, lane = tid & 31, warp = tid >> 5;
    const int q0 = blockIdx.x * 128;
    const int bh = blockIdx.y;

    const __half* qhiG = g_qshi + ((size_t)bh * SS + q0) * HD;
    const __half* khiB = g_kshi + (size_t)bh * SS * HD;
    const __half* vhiB = g_vthi + (size_t)bh * HD * SS;

    issue_q_tile(sb, qhiG, tid);
    CP_COMMIT();
    issue_k_tile(sb, khiB, tid);
    CP_COMMIT();

    float m0v = -1e30f, m8v = -1e30f, l0 = 0.f, l8 = 0.f;
    float o[16][4];
#pragma unroll
    for (int nt = 0; nt < 16; nt++)
#pragma unroll
        for (int c = 0; c < 4; c++) o[nt][c] = 0.f;

    for (int t = 0; t < 32; t++) {
        asm volatile("cp.async.wait_group 0;" ::: "memory");
        __syncthreads();
        issue_v_tile(sb, vhiB + t * 64, tid);
        CP_COMMIT();

        // ---- QK^T: warp rows 16 x keys 64, k' = 128 ----
        float sc[8][4];
#pragma unroll
        for (int nt = 0; nt < 8; nt++)
#pragma unroll
            for (int c = 0; c < 4; c++) sc[nt][c] = 0.f;

#pragma unroll
        for (int pk = 0; pk < 8; pk++) {
            uint32_t af[4], bfr[8][2];
            {
                int row = warp * 16 + (lane & 15);
                int c0 = pk * 2 + (lane >> 4);
                uint32_t ad = sb + SQHI + (uint32_t)(row * 256 + ((c0 >> 3) << 7) +
                                  (((c0 & 7) ^ (row & 7)) << 4));
                LDSM_X4(af[0], af[1], af[2], af[3], ad);
            }
#pragma unroll
            for (int np = 0; np < 4; np++) {
                int row = np * 16 + ((lane >> 4) << 3) + (lane & 7);
                int c0 = pk * 2 + ((lane >> 3) & 1);
                uint32_t bd = sb + SKHI + (uint32_t)(row * 256 + ((c0 >> 3) << 7) +
                                  (((c0 & 7) ^ (row & 7)) << 4));
                LDSM_X4(bfr[2 * np][0], bfr[2 * np][1],
                        bfr[2 * np + 1][0], bfr[2 * np + 1][1], bd);
            }
#pragma unroll
            for (int nt = 0; nt < 8; nt++)
                MMA16816H(sc[nt], af, bfr[nt][0], bfr[nt][1]);
        }

        // ---- in-register online softmax ----
        float mx0 = -1e30f, mx8 = -1e30f;
#pragma unroll
        for (int nt = 0; nt < 8; nt++) {
            mx0 = fmaxf(mx0, fmaxf(sc[nt][0], sc[nt][1]));
            mx8 = fmaxf(mx8, fmaxf(sc[nt][2], sc[nt][3]));
        }
        mx0 = fmaxf(mx0, __shfl_xor_sync(0xffffffff, mx0, 1));
        mx0 = fmaxf(mx0, __shfl_xor_sync(0xffffffff, mx0, 2));
        mx8 = fmaxf(mx8, __shfl_xor_sync(0xffffffff, mx8, 1));
        mx8 = fmaxf(mx8, __shfl_xor_sync(0xffffffff, mx8, 2));
        float mn0 = fmaxf(m0v, mx0), mn8 = fmaxf(m8v, mx8);
        float al0 = exp2_fast((m0v - mn0) * LOG2E);
        float al8 = exp2_fast((m8v - mn8) * LOG2E);
        float s0 = 0.f, s8 = 0.f;
#pragma unroll
        for (int nt = 0; nt < 8; nt++) {
            float p0 = exp2_fast((sc[nt][0] - mn0) * LOG2E);
            float p1 = exp2_fast((sc[nt][1] - mn0) * LOG2E);
            float p2 = exp2_fast((sc[nt][2] - mn8) * LOG2E);
            float p3 = exp2_fast((sc[nt][3] - mn8) * LOG2E);
            sc[nt][0] = p0; sc[nt][1] = p1; sc[nt][2] = p2; sc[nt][3] = p3;
            s0 += p0 + p1; s8 += p2 + p3;
        }
        s0 += __shfl_xor_sync(0xffffffff, s0, 1);
        s0 += __shfl_xor_sync(0xffffffff, s0, 2);
        s8 += __shfl_xor_sync(0xffffffff, s8, 1);
        s8 += __shfl_xor_sync(0xffffffff, s8, 2);
        l0 = l0 * al0 + s0; m0v = mn0;
        l8 = l8 * al8 + s8; m8v = mn8;

        // Pack P (fp16) into PV A-fragments
        uint32_t pHI[4][4];
#pragma unroll
        for (int kc = 0; kc < 4; kc++) {
            pHI[kc][0] = pack_h2(sc[2 * kc][0],     sc[2 * kc][1]);
            pHI[kc][1] = pack_h2(sc[2 * kc][2],     sc[2 * kc][3]);
            pHI[kc][2] = pack_h2(sc[2 * kc + 1][0], sc[2 * kc + 1][1]);
            pHI[kc][3] = pack_h2(sc[2 * kc + 1][2], sc[2 * kc + 1][3]);
        }

        // Rescale O
#pragma unroll
        for (int nt = 0; nt < 16; nt++) {
            o[nt][0] *= al0; o[nt][1] *= al0;
            o[nt][2] *= al8; o[nt][3] *= al8;
        }

        __syncthreads();  // all warps done reading K smem
        if (t + 1 < 32)
            issue_k_tile(sb, khiB + (size_t)(t + 1) * 64 * HD, tid);
        CP_COMMIT();
        asm volatile("cp.async.wait_group 1;" ::: "memory");  // V(t) ready
        __syncthreads();

        // ---- PV: rows 16 x d 128, fp16 ----
#pragma unroll
        for (int kc = 0; kc < 4; kc++) {
            const uint32_t* afr = pHI[kc];
            const int ch = kc * 2 + ((lane >> 3) & 1);
#pragma unroll
            for (int half = 0; half < 2; half++) {
                uint32_t bfr[8][2];
#pragma unroll
                for (int np = 0; np < 4; np++) {
                    int row = half * 64 + np * 16 +
                              ((lane >> 4) << 3) + (lane & 7);
                    uint32_t bd = sb + SVHI + (uint32_t)(row * 128 +
                                      ((ch ^ (row & 7)) << 4));
                    LDSM_X4(bfr[2 * np][0], bfr[2 * np][1],
                            bfr[2 * np + 1][0], bfr[2 * np + 1][1], bd);
                }
#pragma unroll
                for (int i = 0; i < 8; i++)
                    MMA16816H(o[half * 8 + i], afr, bfr[i][0], bfr[i][1]);
            }
        }
    }

    // Epilogue: normalize; write fp16 directly into g_act for out-proj
    const int b = bh >> 4, h = bh & 15;
    const int row = warp * 16 + (lane >> 2);
    float inv0 = 1.0f / l0;
    float inv8 = 1.0f / l8;
#pragma unroll
    for (int nt = 0; nt < 16; nt++) {
        int col = nt * 8 + (lane & 3) * 2;
        size_t a0 = (size_t)(b * SS + q0 + row) * KA + h * HD + col;
        *reinterpret_cast<uint32_t*>(&g_act[a0]) =
            pack_h2(o[nt][0] * inv0, o[nt][1] * inv0);
        *reinterpret_cast<uint32_t*>(&g_act[a0 + (size_t)8 * KA]) =
            pack_h2(o[nt][2] * inv8, o[nt][3] * inv8);
    }
}

// ---------------------------------------------------------------------------
// Launch
// ---------------------------------------------------------------------------
extern "C" void kernel_launch(void* const* d_in, const int* in_sizes, int n_in,
                              void* d_out, int out_size) {
    (void)in_sizes; (void)n_in; (void)out_size;
    const float* x  = (const float*)d_in[0];
    const float* wq = (const float*)d_in[1];
    const float* wk = (const float*)d_in[2];
    const float* wv = (const float*)d_in[3];
    const float* wo = (const float*)d_in[4];
    float* out = (float*)d_out;

    __half *act, *wbig;
    cudaGetSymbolAddress((void**)&act,  g_act);
    cudaGetSymbolAddress((void**)&wbig, g_wbig);

    cudaFuncSetAttribute(gemm_hmma,
                         cudaFuncAttributeMaxDynamicSharedMemorySize,
                         GEMM_SMEM_BYTES);
    cudaFuncSetAttribute(flash_mma_kernel,
                         cudaFuncAttributeMaxDynamicSharedMemorySize,
                         FLASH3_SMEM);

    const int n_act = BS * DD;
    const int n_w   = DD * DD;

    rope_table_kernel<<<(SS * NPAIR + 255) / 256, 256>>>();

    // x -> fp16; all 4 weights -> stacked fp16 buffer in one launch
    conv_h_kernel<<<(n_act + 255) / 256, 256>>>(x, act, n_act);
    conv_w4_kernel<<<(4 * n_w + 255) / 256, 256>>>(wq, wk, wv, wo, wbig);

    // Fused QKV projection + RoPE + scale + fp16 split (epilogue-fused)
    dim3 qkv_grid((3 * DD) / 64, BS / 128);  // (96, 32)
    gemm_hmma<<<qkv_grid, 256, GEMM_SMEM_BYTES>>>(act, wbig, nullptr, 0, 1);

    // V transpose (fp16 -> fp16)
    v_t_kernel<<<dim3(SS / 64, BB * HH), 256>>>();

    // fp16 FA2 flash attention (overwrites g_act with attn out)
    flash_mma_kernel<<<dim3(SS / 128, BB * HH), 256, FLASH3_SMEM>>>();

    // Output projection (wo = 4th weight segment)
    dim3 ogrid(DD / 64, BS / 128);  // (32, 32)
    gemm_hmma<<<ogrid, 256, GEMM_SMEM_BYTES>>>(
        act, wbig + (size_t)3 * DD * KW, out, DD, 0);
}

// round 17
// speedup vs baseline: 4.7026x; 1.0627x over previous
#include <cuda_runtime.h>
#include <cuda_bf16.h>
#include <cuda_fp16.h>
#include <math.h>
#include <stdint.h>

// Problem constants
#define BB 2
#define SS 2048
#define DD 2048
#define HH 16
#define HD 128
#define BS (BB * SS)        // 4096 tokens
#define NPAIR (HD / 2)      // 64 rope pairs per head
#define KA DD               // 2048: pure fp16 K for projections
#define KW DD
#define ITERSG (KA / 64)    // 32 K-chunks of 64
#define STG 4               // cp.async pipeline stages
#define LOG2E 1.4426950408889634f
#define QK_SCALE 0.08838834764831845f

// ---------------------------------------------------------------------------
// Scratch (device globals -- no allocation allowed in kernel_launch)
// ---------------------------------------------------------------------------
__device__ float g_cos[SS * NPAIR];
__device__ float g_sin[SS * NPAIR];
__device__ __half g_act[(size_t)BS * KA];            // fp16 activations (x, then attn out)
__device__ __half g_wbig[(size_t)(4 * DD) * KW];     // fp16 weights [wq|wk|wv|wo]
// Attention fp16 buffers: q, k [bh][s][d]; v staged [bh][s][d]; v^T [bh][d][s]
__device__ __half g_qshi[(size_t)BS * DD];
__device__ __half g_kshi[(size_t)BS * DD];
__device__ __half g_vs[(size_t)BS * DD];
__device__ __half g_vthi[(size_t)BS * DD];

// ---------------------------------------------------------------------------
// Helpers
// ---------------------------------------------------------------------------
__device__ __forceinline__ uint32_t smem_u32(const void* p) {
    uint32_t a;
    asm("{ .reg .u64 t; cvta.to.shared.u64 t, %1; cvt.u32.u64 %0, t; }"
        : "=r"(a) : "l"(p));
    return a;
}
#define CP_ASYNC16(smem, gptr) \
    asm volatile("cp.async.cg.shared.global [%0], [%1], 16;" \
                 :: "r"((uint32_t)(smem)), "l"((const void*)(gptr)) : "memory")
#define CP_COMMIT() asm volatile("cp.async.commit_group;" ::: "memory")

#define LDSM_X4(r0, r1, r2, r3, addr) \
    asm volatile("ldmatrix.sync.aligned.m8n8.x4.shared.b16 {%0,%1,%2,%3}, [%4];" \
                 : "=r"(r0), "=r"(r1), "=r"(r2), "=r"(r3) : "r"(addr))

#define MMA16816H(d, a, b0, b1) \
    asm volatile("mma.sync.aligned.m16n8k16.row.col.f32.f16.f16.f32 " \
                 "{%0,%1,%2,%3}, {%4,%5,%6,%7}, {%8,%9}, {%0,%1,%2,%3};" \
                 : "+f"((d)[0]), "+f"((d)[1]), "+f"((d)[2]), "+f"((d)[3]) \
                 : "r"((a)[0]), "r"((a)[1]), "r"((a)[2]), "r"((a)[3]),   \
                   "r"(b0), "r"(b1))

// Fast exp2 on FMA pipe: t <= 0, clamp at -126; |rel err| ~ 3e-6
__device__ __forceinline__ float exp2_fast(float t) {
    t = fmaxf(t, -126.0f);
    float r = t + 12582912.0f;
    int e = __float_as_int(r) - 0x4B400000;
    float f = t - (r - 12582912.0f);
    float p = 0.0013333558f;
    p = fmaf(p, f, 0.0096181291f);
    p = fmaf(p, f, 0.0555041087f);
    p = fmaf(p, f, 0.2402265070f);
    p = fmaf(p, f, 0.6931471806f);
    p = fmaf(p, f, 1.0f);
    return __int_as_float((e + 127) << 23) * p;
}
__device__ __forceinline__ uint32_t pack_h2(float a, float b) {
    __half2 h2 = __floats2half2_rn(a, b);
    return *reinterpret_cast<uint32_t*>(&h2);
}
// Convert 8 fp32 (2 x float4) -> 8 fp16 packed in uint4
__device__ __forceinline__ uint4 conv8(const float4 v0, const float4 v1) {
    uint4 r;
    r.x = pack_h2(v0.x, v0.y);
    r.y = pack_h2(v0.z, v0.w);
    r.z = pack_h2(v1.x, v1.y);
    r.w = pack_h2(v1.z, v1.w);
    return r;
}

// ---------------------------------------------------------------------------
// RoPE table (double precision generation)
// ---------------------------------------------------------------------------
__global__ void rope_table_kernel() {
    int idx = blockIdx.x * blockDim.x + threadIdx.x;
    if (idx >= SS * NPAIR) return;
    int s = idx / NPAIR;
    int i = idx - s * NPAIR;
    double freq = (double)s * exp(((double)(-2 * i) / (double)HD) * log(10000.0));
    g_cos[idx] = (float)cos(freq);
    g_sin[idx] = (float)sin(freq);
}

// ---------------------------------------------------------------------------
// Vectorized fp32 -> fp16 converts (8 elements per thread)
// ---------------------------------------------------------------------------
__global__ void conv_h_kernel(const float* __restrict__ src,
                              __half* __restrict__ dst, int n8) {
    int idx = blockIdx.x * blockDim.x + threadIdx.x;
    if (idx >= n8) return;
    const float4* s4 = reinterpret_cast<const float4*>(src) + 2 * idx;
    float4 v0 = s4[0], v1 = s4[1];
    reinterpret_cast<uint4*>(dst)[idx] = conv8(v0, v1);
}
// 4 weights (each DD*DD = 2^22 elems) stacked into g_wbig; 8 elems/thread
__global__ void conv_w4_kernel(const float* __restrict__ w0,
                               const float* __restrict__ w1,
                               const float* __restrict__ w2,
                               const float* __restrict__ w3,
                               __half* __restrict__ dst) {
    int idx = blockIdx.x * blockDim.x + threadIdx.x;   // 0 .. 4*2^22/8 - 1
    if (idx >= (4 * DD * DD) / 8) return;
    int seg = idx >> 19;                               // 2^22/8 = 2^19 per seg
    int off = idx & ((1 << 19) - 1);
    const float* src = (seg == 0) ? w0 : (seg == 1) ? w1 : (seg == 2) ? w2 : w3;
    const float4* s4 = reinterpret_cast<const float4*>(src) + 2 * off;
    float4 v0 = s4[0], v1 = s4[1];
    reinterpret_cast<uint4*>(dst)[idx] = conv8(v0, v1);
}

// ---------------------------------------------------------------------------
// V transpose (fp16 -> fp16): g_vs [bh][s][d] -> g_vthi [bh][d][s]
// Tile 64 rows(s) x 128 cols(d) = 1024 chunks of 16B (16 chunks per row).
// ---------------------------------------------------------------------------
__global__ __launch_bounds__(256) void v_t_kernel() {
    __shared__ __half st[64][136];
    const int s0 = blockIdx.x * 64;
    const int bh = blockIdx.y;
    const __half* src = g_vs + ((size_t)bh * SS + s0) * HD;
    const int tid = threadIdx.x;
#pragma unroll
    for (int i = 0; i < 4; i++) {
        int id = tid + 256 * i;          // 0..1023
        int r = id >> 4;                 // 0..63
        int c8 = id & 15;                // 16-byte chunk within 128-half row
        *reinterpret_cast<uint4*>(&st[r][c8 * 8]) =
            *reinterpret_cast<const uint4*>(src + (size_t)r * HD + c8 * 8);
    }
    __syncthreads();
    const int d = tid >> 1, half = tid & 1;
    __half buf[32];
#pragma unroll
    for (int j = 0; j < 32; j++)
        buf[j] = st[half * 32 + j][d];
    size_t dst = ((size_t)bh * HD + d) * SS + s0 + half * 32;
    uint4* ph = reinterpret_cast<uint4*>(&g_vthi[dst]);
#pragma unroll
    for (int tch = 0; tch < 4; tch++)
        ph[tch] = reinterpret_cast<uint4*>(buf)[tch];
}

// ---------------------------------------------------------------------------
// HMMA GEMM (pure fp16): A[4096,2048] * B[N,2048]^T.
// mode 0: C fp32, ldc = N (output projection).
// mode 1: fused QKV epilogue -- RoPE+scale+fp16 write to q/k/v buffers.
// ---------------------------------------------------------------------------
#define TILE_STAGE_BYTES 24576
#define GEMM_SMEM_BYTES (STG * TILE_STAGE_BYTES)

__device__ __forceinline__ void qkv_write(int row, int col, float x0, float x1) {
    const int b = row >> 11, s = row & (SS - 1);
    if (col < 2 * DD) {
        const int which = col >> 11;       // 0 = q, 1 = k
        const int cc = col & (DD - 1);
        const int h = cc >> 7, d = cc & 127;
        const int i = d >> 1;
        const float c  = g_cos[(s << 6) + i];
        const float sn = g_sin[(s << 6) + i];
        float o0 = x0 * c - x1 * sn;
        float o1 = x0 * sn + x1 * c;
        size_t dst = ((size_t)(b * HH + h) * SS + s) * HD + d;
        if (which == 0) {
            *reinterpret_cast<uint32_t*>(&g_qshi[dst]) =
                pack_h2(o0 * QK_SCALE, o1 * QK_SCALE);
        } else {
            *reinterpret_cast<uint32_t*>(&g_kshi[dst]) = pack_h2(o0, o1);
        }
    } else {
        const int cc = col - 2 * DD;
        const int h = cc >> 7, d = cc & 127;
        size_t dst = ((size_t)(b * HH + h) * SS + s) * HD + d;
        *reinterpret_cast<uint32_t*>(&g_vs[dst]) = pack_h2(x0, x1);
    }
}

__device__ __forceinline__ void issue_stage(
    uint32_t sb, int s, int tid,
    const __half* __restrict__ Ag,
    const __half* __restrict__ Bg)
{
    if (s < ITERSG) {
        const int k0 = s * 64;
        const int slot = s & (STG - 1);
        uint32_t abase = sb + slot * TILE_STAGE_BYTES;
        uint32_t bbase = abase + 16384;
#pragma unroll
        for (int i = 0; i < 4; i++) {
            int id = tid + 256 * i;
            int row = id >> 3;
            int c = id & 7;
            uint32_t off = (uint32_t)(row * 128 + ((c ^ (row & 7)) << 4));
            CP_ASYNC16(abase + off, Ag + (size_t)row * KA + k0 + c * 8);
        }
#pragma unroll
        for (int i = 0; i < 2; i++) {
            int id = tid + 256 * i;
            int row = id >> 3;
            int c = id & 7;
            uint32_t off = (uint32_t)(row * 128 + ((c ^ (row & 7)) << 4));
            CP_ASYNC16(bbase + off, Bg + (size_t)row * KW + k0 + c * 8);
        }
    }
    CP_COMMIT();
}

__global__ __launch_bounds__(256, 2)
void gemm_hmma(const __half* __restrict__ A,
               const __half* __restrict__ Bw,
               float* __restrict__ C, int ldc, int mode)
{
    extern __shared__ char smraw[];
    uint32_t sb = smem_u32(smraw);
    const int tid  = threadIdx.x;
    const int lane = tid & 31;
    const int warp = tid >> 5;
    const int wm = warp & 3;
    const int wn = warp >> 2;
    const int m0 = blockIdx.y * 128;
    const int n0 = blockIdx.x * 64;
    const __half* Ag = A  + (size_t)m0 * KA;
    const __half* Bg = Bw + (size_t)n0 * KW;

    float acc[2][4][4];
#pragma unroll
    for (int a = 0; a < 2; a++)
#pragma unroll
        for (int b = 0; b < 4; b++)
#pragma unroll
            for (int c = 0; c < 4; c++) acc[a][b][c] = 0.f;

    issue_stage(sb, 0, tid, Ag, Bg);
    issue_stage(sb, 1, tid, Ag, Bg);
    issue_stage(sb, 2, tid, Ag, Bg);

    for (int s = 0; s < ITERSG; s++) {
        asm volatile("cp.async.wait_group 2;" ::: "memory");
        __syncthreads();
        // Hoisted: issue next stage BEFORE compute so LDGSTS overlaps MMA.
        // Safe: slot(s+3) == slot(s-1); all warps' reads of slot(s-1)
        // completed before this iteration's __syncthreads.
        issue_stage(sb, s + 3, tid, Ag, Bg);

        const int slot = s & (STG - 1);
        uint32_t abase = sb + slot * TILE_STAGE_BYTES;
        uint32_t bbase = abase + 16384;

#pragma unroll
        for (int ks = 0; ks < 4; ks++) {
            uint32_t af[2][4];
            uint32_t bf[4][2];
#pragma unroll
            for (int mt = 0; mt < 2; mt++) {
                int row = wm * 32 + mt * 16 + (lane & 15);
                int ch  = ks * 2 + (lane >> 4);
                uint32_t ad = abase + (uint32_t)(row * 128 +
                                  ((ch ^ (row & 7)) << 4));
                LDSM_X4(af[mt][0], af[mt][1], af[mt][2], af[mt][3], ad);
            }
#pragma unroll
            for (int np = 0; np < 2; np++) {
                int row = wn * 32 + np * 16 + ((lane >> 4) << 3) + (lane & 7);
                int ch  = ks * 2 + ((lane >> 3) & 1);
                uint32_t bd = bbase + (uint32_t)(row * 128 +
                                  ((ch ^ (row & 7)) << 4));
                LDSM_X4(bf[2 * np][0], bf[2 * np][1],
                        bf[2 * np + 1][0], bf[2 * np + 1][1], bd);
            }
#pragma unroll
            for (int mt = 0; mt < 2; mt++)
#pragma unroll
                for (int nt = 0; nt < 4; nt++)
                    MMA16816H(acc[mt][nt], af[mt], bf[nt][0], bf[nt][1]);
        }
    }

    if (mode == 0) {
#pragma unroll
        for (int mt = 0; mt < 2; mt++) {
#pragma unroll
            for (int nt = 0; nt < 4; nt++) {
                int row = m0 + wm * 32 + mt * 16 + (lane >> 2);
                int col = n0 + wn * 32 + nt * 8 + (lane & 3) * 2;
                float2 v0 = make_float2(acc[mt][nt][0], acc[mt][nt][1]);
                float2 v1 = make_float2(acc[mt][nt][2], acc[mt][nt][3]);
                *reinterpret_cast<float2*>(&C[(size_t)row * ldc + col]) = v0;
                *reinterpret_cast<float2*>(&C[(size_t)(row + 8) * ldc + col]) = v1;
            }
        }
    } else {
        // Fused QKV epilogue: RoPE + scale + fp16 write (cols are rope pairs)
#pragma unroll
        for (int mt = 0; mt < 2; mt++) {
#pragma unroll
            for (int nt = 0; nt < 4; nt++) {
                int row = m0 + wm * 32 + mt * 16 + (lane >> 2);
                int col = n0 + wn * 32 + nt * 8 + (lane & 3) * 2;
                qkv_write(row,     col, acc[mt][nt][0], acc[mt][nt][1]);
                qkv_write(row + 8, col, acc[mt][nt][2], acc[mt][nt][3]);
            }
        }
    }
}

// ---------------------------------------------------------------------------
// FA2-style flash attention, fp16 (unchanged):
// QK: q.k (k' = 128).  PV: p.v.
// smem: Q (32KB) + K (16KB) + V (16KB) = 64KB.
// ---------------------------------------------------------------------------
#define SQHI 0
#define SKHI 32768
#define SVHI 49152
#define FLASH3_SMEM 65536

__device__ __forceinline__ void issue_q_tile(
    uint32_t sb, const __half* __restrict__ ghi, int tid)
{
#pragma unroll
    for (int i = 0; i < 8; i++) {
        int id = tid + 256 * i;
        int row = id >> 4, c = id & 15;
        uint32_t off = (uint32_t)(row * 256 + ((c >> 3) << 7) +
                                  (((c & 7) ^ (row & 7)) << 4));
        CP_ASYNC16(sb + SQHI + off, ghi + (size_t)row * HD + c * 8);
    }
}
__device__ __forceinline__ void issue_k_tile(
    uint32_t sb, const __half* __restrict__ ghi, int tid)
{
#pragma unroll
    for (int i = 0; i < 4; i++) {
        int id = tid + 256 * i;
        int row = id >> 4, c = id & 15;
        uint32_t off = (uint32_t)(row * 256 + ((c >> 3) << 7) +
                                  (((c & 7) ^ (row & 7)) << 4));
        CP_ASYNC16(sb + SKHI + off, ghi + (size_t)row * HD + c * 8);
    }
}
__device__ __forceinline__ void issue_v_tile(
    uint32_t sb, const __half* __restrict__ ghi, int tid)
{
#pragma unroll
    for (int i = 0; i < 4; i++) {
        int id = tid + 256 * i;
        int row = id >> 3, c = id & 7;
        uint32_t off = (uint32_t)(row * 128 + ((c ^ (row & 7)) << 4));
        CP_ASYNC16(sb + SVHI + off, ghi + (size_t)row * SS + c * 8);
    }
}

__global__ __launch_bounds__(256, 1) void flash_mma_kernel() {
    extern __shared__ char smr[];
    uint32_t sb = smem_u32(smr);
    const int tid = threadIdx.x, lane = tid & 31, warp = tid >> 5;
    const int q0 = blockIdx.x * 128;
    const int bh = blockIdx.y;

    const __half* qhiG = g_qshi + ((size_t)bh * SS + q0) * HD;
    const __half* khiB = g_kshi + (size_t)bh * SS * HD;
    const __half* vhiB = g_vthi + (size_t)bh * HD * SS;

    issue_q_tile(sb, qhiG, tid);
    CP_COMMIT();
    issue_k_tile(sb, khiB, tid);
    CP_COMMIT();

    float m0v = -1e30f, m8v = -1e30f, l0 = 0.f, l8 = 0.f;
    float o[16][4];
#pragma unroll
    for (int nt = 0; nt < 16; nt++)
#pragma unroll
        for (int c = 0; c < 4; c++) o[nt][c] = 0.f;

    for (int t = 0; t < 32; t++) {
        asm volatile("cp.async.wait_group 0;" ::: "memory");
        __syncthreads();
        issue_v_tile(sb, vhiB + t * 64, tid);
        CP_COMMIT();

        // ---- QK^T: warp rows 16 x keys 64, k' = 128 ----
        float sc[8][4];
#pragma unroll
        for (int nt = 0; nt < 8; nt++)
#pragma unroll
            for (int c = 0; c < 4; c++) sc[nt][c] = 0.f;

#pragma unroll
        for (int pk = 0; pk < 8; pk++) {
            uint32_t af[4], bfr[8][2];
            {
                int row = warp * 16 + (lane & 15);
                int c0 = pk * 2 + (lane >> 4);
                uint32_t ad = sb + SQHI + (uint32_t)(row * 256 + ((c0 >> 3) << 7) +
                                  (((c0 & 7) ^ (row & 7)) << 4));
                LDSM_X4(af[0], af[1], af[2], af[3], ad);
            }
#pragma unroll
            for (int np = 0; np < 4; np++) {
                int row = np * 16 + ((lane >> 4) << 3) + (lane & 7);
                int c0 = pk * 2 + ((lane >> 3) & 1);
                uint32_t bd = sb + SKHI + (uint32_t)(row * 256 + ((c0 >> 3) << 7) +
                                  (((c0 & 7) ^ (row & 7)) << 4));
                LDSM_X4(bfr[2 * np][0], bfr[2 * np][1],
                        bfr[2 * np + 1][0], bfr[2 * np + 1][1], bd);
            }
#pragma unroll
            for (int nt = 0; nt < 8; nt++)
                MMA16816H(sc[nt], af, bfr[nt][0], bfr[nt][1]);
        }

        // ---- in-register online softmax ----
        float mx0 = -1e30f, mx8 = -1e30f;
#pragma unroll
        for (int nt = 0; nt < 8; nt++) {
            mx0 = fmaxf(mx0, fmaxf(sc[nt][0], sc[nt][1]));
            mx8 = fmaxf(mx8, fmaxf(sc[nt][2], sc[nt][3]));
        }
        mx0 = fmaxf(mx0, __shfl_xor_sync(0xffffffff, mx0, 1));
        mx0 = fmaxf(mx0, __shfl_xor_sync(0xffffffff, mx0, 2));
        mx8 = fmaxf(mx8, __shfl_xor_sync(0xffffffff, mx8, 1));
        mx8 = fmaxf(mx8, __shfl_xor_sync(0xffffffff, mx8, 2));
        float mn0 = fmaxf(m0v, mx0), mn8 = fmaxf(m8v, mx8);
        float al0 = exp2_fast((m0v - mn0) * LOG2E);
        float al8 = exp2_fast((m8v - mn8) * LOG2E);
        float s0 = 0.f, s8 = 0.f;
#pragma unroll
        for (int nt = 0; nt < 8; nt++) {
            float p0 = exp2_fast((sc[nt][0] - mn0) * LOG2E);
            float p1 = exp2_fast((sc[nt][1] - mn0) * LOG2E);
            float p2 = exp2_fast((sc[nt][2] - mn8) * LOG2E);
            float p3 = exp2_fast((sc[nt][3] - mn8) * LOG2E);
            sc[nt][0] = p0; sc[nt][1] = p1; sc[nt][2] = p2; sc[nt][3] = p3;
            s0 += p0 + p1; s8 += p2 + p3;
        }
        s0 += __shfl_xor_sync(0xffffffff, s0, 1);
        s0 += __shfl_xor_sync(0xffffffff, s0, 2);
        s8 += __shfl_xor_sync(0xffffffff, s8, 1);
        s8 += __shfl_xor_sync(0xffffffff, s8, 2);
        l0 = l0 * al0 + s0; m0v = mn0;
        l8 = l8 * al8 + s8; m8v = mn8;

        // Pack P (fp16) into PV A-fragments
        uint32_t pHI[4][4];
#pragma unroll
        for (int kc = 0; kc < 4; kc++) {
            pHI[kc][0] = pack_h2(sc[2 * kc][0],     sc[2 * kc][1]);
            pHI[kc][1] = pack_h2(sc[2 * kc][2],     sc[2 * kc][3]);
            pHI[kc][2] = pack_h2(sc[2 * kc + 1][0], sc[2 * kc + 1][1]);
            pHI[kc][3] = pack_h2(sc[2 * kc + 1][2], sc[2 * kc + 1][3]);
        }

        // Rescale O
#pragma unroll
        for (int nt = 0; nt < 16; nt++) {
            o[nt][0] *= al0; o[nt][1] *= al0;
            o[nt][2] *= al8; o[nt][3] *= al8;
        }

        __syncthreads();  // all warps done reading K smem
        if (t + 1 < 32)
            issue_k_tile(sb, khiB + (size_t)(t + 1) * 64 * HD, tid);
        CP_COMMIT();
        asm volatile("cp.async.wait_group 1;" ::: "memory");  // V(t) ready
        __syncthreads();

        // ---- PV: rows 16 x d 128, fp16 ----
#pragma unroll
        for (int kc = 0; kc < 4; kc++) {
            const uint32_t* afr = pHI[kc];
            const int ch = kc * 2 + ((lane >> 3) & 1);
#pragma unroll
            for (int half = 0; half < 2; half++) {
                uint32_t bfr[8][2];
#pragma unroll
                for (int np = 0; np < 4; np++) {
                    int row = half * 64 + np * 16 +
                              ((lane >> 4) << 3) + (lane & 7);
                    uint32_t bd = sb + SVHI + (uint32_t)(row * 128 +
                                      ((ch ^ (row & 7)) << 4));
                    LDSM_X4(bfr[2 * np][0], bfr[2 * np][1],
                            bfr[2 * np + 1][0], bfr[2 * np + 1][1], bd);
                }
#pragma unroll
                for (int i = 0; i < 8; i++)
                    MMA16816H(o[half * 8 + i], afr, bfr[i][0], bfr[i][1]);
            }
        }
    }

    // Epilogue: normalize; write fp16 directly into g_act for out-proj
    const int b = bh >> 4, h = bh & 15;
    const int row = warp * 16 + (lane >> 2);
    float inv0 = 1.0f / l0;
    float inv8 = 1.0f / l8;
#pragma unroll
    for (int nt = 0; nt < 16; nt++) {
        int col = nt * 8 + (lane & 3) * 2;
        size_t a0 = (size_t)(b * SS + q0 + row) * KA + h * HD + col;
        *reinterpret_cast<uint32_t*>(&g_act[a0]) =
            pack_h2(o[nt][0] * inv0, o[nt][1] * inv0);
        *reinterpret_cast<uint32_t*>(&g_act[a0 + (size_t)8 * KA]) =
            pack_h2(o[nt][2] * inv8, o[nt][3] * inv8);
    }
}

// ---------------------------------------------------------------------------
// Launch
// ---------------------------------------------------------------------------
extern "C" void kernel_launch(void* const* d_in, const int* in_sizes, int n_in,
                              void* d_out, int out_size) {
    (void)in_sizes; (void)n_in; (void)out_size;
    const float* x  = (const float*)d_in[0];
    const float* wq = (const float*)d_in[1];
    const float* wk = (const float*)d_in[2];
    const float* wv = (const float*)d_in[3];
    const float* wo = (const float*)d_in[4];
    float* out = (float*)d_out;

    __half *act, *wbig;
    cudaGetSymbolAddress((void**)&act,  g_act);
    cudaGetSymbolAddress((void**)&wbig, g_wbig);

    cudaFuncSetAttribute(gemm_hmma,
                         cudaFuncAttributeMaxDynamicSharedMemorySize,
                         GEMM_SMEM_BYTES);
    cudaFuncSetAttribute(flash_mma_kernel,
                         cudaFuncAttributeMaxDynamicSharedMemorySize,
                         FLASH3_SMEM);

    const int n_act = BS * DD;

    rope_table_kernel<<<(SS * NPAIR + 255) / 256, 256>>>();

    // x -> fp16 (vectorized); all 4 weights -> stacked fp16 buffer (vectorized)
    conv_h_kernel<<<(n_act / 8 + 255) / 256, 256>>>(x, act, n_act / 8);
    conv_w4_kernel<<<((4 * DD * DD) / 8 + 255) / 256, 256>>>(wq, wk, wv, wo, wbig);

    // Fused QKV projection + RoPE + scale + fp16 split (epilogue-fused)
    dim3 qkv_grid((3 * DD) / 64, BS / 128);  // (96, 32)
    gemm_hmma<<<qkv_grid, 256, GEMM_SMEM_BYTES>>>(act, wbig, nullptr, 0, 1);

    // V transpose (fp16 -> fp16)
    v_t_kernel<<<dim3(SS / 64, BB * HH), 256>>>();

    // fp16 FA2 flash attention (overwrites g_act with attn out)
    flash_mma_kernel<<<dim3(SS / 128, BB * HH), 256, FLASH3_SMEM>>>();

    // Output projection (wo = 4th weight segment)
    dim3 ogrid(DD / 64, BS / 128);  // (32, 32)
    gemm_hmma<<<ogrid, 256, GEMM_SMEM_BYTES>>>(
        act, wbig + (size_t)3 * DD * KW, out, DD, 0);
}